// round 5
// baseline (speedup 1.0000x reference)
#include <cuda_runtime.h>
#include <cuda_bf16.h>
#include <math.h>
#include <stdint.h>

// ---------------------------------------------------------------------------
// Shapes: b=2, L=4096, d=1024, h=16, n=p=64, chunk=64 -> tokens 8192, tiles 2048
// Output: y (8388608 f32) then final_state (131072 f32)
// ---------------------------------------------------------------------------
#define NTOK   8192
#define DMOD   1024
#define NHEADS 16
#define NTILE  2048
#define Y_ELEMS 8388608
#define PROJN  4352    // 2048 (xz) + 1024 (B) + 1024 (C) + 16 (dt) + 240 pad

// fp32 scratch
__device__ float gProj[NTOK * PROJN];    // [tok][xz | B | C | dtraw | pad]
__device__ float gYdiag[NTILE * 4096];
__device__ float gStates[NTILE * 4096];
__device__ float gStateIn[NTILE * 4096];
__device__ float gAlast[NTILE];

// bf16 hi/lo operand scratch (zero-initialized; pad rows of gWcat stay 0)
__device__ __nv_bfloat16 gXhi[NTOK * DMOD], gXlo[NTOK * DMOD];
__device__ __nv_bfloat16 gWcatHi[PROJN * DMOD], gWcatLo[PROJN * DMOD];
__device__ __nv_bfloat16 gWoHi[DMOD * DMOD], gWoLo[DMOD * DMOD];
__device__ __nv_bfloat16 gYaHi[NTOK * DMOD], gYaLo[NTOK * DMOD];

// ---------------------------------------------------------------------------
// PTX helpers (sm_80-level only: cp.async, ldmatrix, mma.sync)
// ---------------------------------------------------------------------------
__device__ __forceinline__ uint32_t smem_u32(const void* p) {
    uint32_t a;
    asm("{ .reg .u64 t; cvta.to.shared.u64 t, %1; cvt.u32.u64 %0, t; }" : "=r"(a) : "l"(p));
    return a;
}
__device__ __forceinline__ void cp16(uint32_t dst, const void* src) {
    asm volatile("cp.async.cg.shared.global [%0], [%1], 16;\n" :: "r"(dst), "l"(src));
}
__device__ __forceinline__ void cp_commit() { asm volatile("cp.async.commit_group;\n" ::: "memory"); }
template <int N> __device__ __forceinline__ void cp_wait() {
    asm volatile("cp.async.wait_group %0;\n" :: "n"(N) : "memory");
}
__device__ __forceinline__ void ldsm4(uint32_t* r, uint32_t addr) {
    asm volatile("ldmatrix.sync.aligned.m8n8.x4.shared.b16 {%0,%1,%2,%3}, [%4];"
                 : "=r"(r[0]), "=r"(r[1]), "=r"(r[2]), "=r"(r[3]) : "r"(addr));
}
__device__ __forceinline__ void mma16816(float* d, const uint32_t* a, const uint32_t* b) {
    asm volatile("mma.sync.aligned.m16n8k16.row.col.f32.bf16.bf16.f32 "
                 "{%0,%1,%2,%3}, {%4,%5,%6,%7}, {%8,%9}, {%0,%1,%2,%3};"
                 : "+f"(d[0]), "+f"(d[1]), "+f"(d[2]), "+f"(d[3])
                 : "r"(a[0]), "r"(a[1]), "r"(a[2]), "r"(a[3]), "r"(b[0]), "r"(b[1]));
}

// ---------------------------------------------------------------------------
// Tensor-core GEMM: C[M,N] = A[M,K] @ B[N,K]^T, fp32 via bf16 hi/lo 3-term.
// CTA tile 128x128, 512 threads (16 warps, 4x4; warp tile 32x32),
// K chunk 32, 4-stage cp.async pipeline. SMEM rows 64B, XOR swizzle.
// ---------------------------------------------------------------------------
#define TM 128
#define TN 128
#define OF_AH 0
#define OF_AL 8192
#define OF_BH 16384
#define OF_BL 24576
#define STG   32768
#define GEMM_SMEM (4 * STG)   // 131072

__device__ __forceinline__ void load_stage(uint32_t st,
                                           const __nv_bfloat16* Ah, const __nv_bfloat16* Al,
                                           const __nv_bfloat16* Bh, const __nv_bfloat16* Bl,
                                           int bm, int bn, int K, int k0, int t) {
    int r = t >> 2, c = t & 3;               // 512 threads: one 16B transfer per tensor
    uint32_t off = (uint32_t)(r * 64) + (uint32_t)((c ^ ((r >> 1) & 3)) << 4);
    size_t ga = (size_t)(bm + r) * K + k0 + c * 8;
    size_t gb = (size_t)(bn + r) * K + k0 + c * 8;
    cp16(st + OF_AH + off, Ah + ga);
    cp16(st + OF_AL + off, Al + ga);
    cp16(st + OF_BH + off, Bh + gb);
    cp16(st + OF_BL + off, Bl + gb);
}

__global__ __launch_bounds__(512, 1)
void gemm_mma(const __nv_bfloat16* __restrict__ Ah, const __nv_bfloat16* __restrict__ Al,
              const __nv_bfloat16* __restrict__ Bh, const __nv_bfloat16* __restrict__ Bl,
              float* __restrict__ C, int M, int N, int K) {
    extern __shared__ char smem[];
    const uint32_t sb = smem_u32(smem);
    const int t = threadIdx.x;
    const int wid = t >> 5, lane = t & 31;
    const int bm = blockIdx.y * TM;
    const int bn = blockIdx.x * TN;
    const int wm = (wid >> 2) * 32;
    const int wn = (wid & 3) * 32;
    const int nch = K >> 5;

    float acc[2][4][4];
#pragma unroll
    for (int i = 0; i < 2; i++)
#pragma unroll
        for (int j = 0; j < 4; j++)
#pragma unroll
            for (int k = 0; k < 4; k++) acc[i][j][k] = 0.f;

    // prologue: chunks 0,1,2 -> stages 0,1,2
#pragma unroll
    for (int pc = 0; pc < 3; pc++) {
        load_stage(sb + pc * STG, Ah, Al, Bh, Bl, bm, bn, K, pc * 32, t);
        cp_commit();
    }

    const int ra = (lane & 15);
    const uint32_t ca = (uint32_t)((lane >> 4) << 4);
    const int rb = (lane & 7) + (((lane >> 4) & 1) << 3);
    const uint32_t cb = (uint32_t)(((lane >> 3) & 1) << 4);

    for (int i = 0; i < nch; i++) {
        __syncthreads();   // all warps done with the stage about to be overwritten
        if (i + 3 < nch) {
            load_stage(sb + ((i + 3) & 3) * STG, Ah, Al, Bh, Bl, bm, bn, K, (i + 3) * 32, t);
            cp_commit();
            cp_wait<3>();
        } else if (i + 2 < nch) cp_wait<2>();
        else if (i + 1 < nch) cp_wait<1>();
        else cp_wait<0>();
        __syncthreads();   // chunk i visible to all warps

        const uint32_t st = sb + (i & 3) * STG;
#pragma unroll
        for (int w = 0; w < 2; w++) {
            uint32_t ah[2][4], al[2][4], bh[2][4], bl[2][4];
#pragma unroll
            for (int mi = 0; mi < 2; mi++) {
                int r = wm + mi * 16 + ra;
                uint32_t col = (uint32_t)(w * 32) + ca;
                uint32_t off = (uint32_t)(r * 64) + (col ^ (uint32_t)(((r >> 1) & 3) << 4));
                ldsm4(ah[mi], st + OF_AH + off);
                ldsm4(al[mi], st + OF_AL + off);
            }
#pragma unroll
            for (int nb = 0; nb < 2; nb++) {
                int r = wn + nb * 16 + rb;
                uint32_t col = (uint32_t)(w * 32) + cb;
                uint32_t off = (uint32_t)(r * 64) + (col ^ (uint32_t)(((r >> 1) & 3) << 4));
                ldsm4(bh[nb], st + OF_BH + off);
                ldsm4(bl[nb], st + OF_BL + off);
            }
#pragma unroll
            for (int mi = 0; mi < 2; mi++)
#pragma unroll
                for (int ni = 0; ni < 4; ni++) {
                    const uint32_t* h2 = &bh[ni >> 1][(ni & 1) * 2];
                    const uint32_t* l2 = &bl[ni >> 1][(ni & 1) * 2];
                    mma16816(acc[mi][ni], ah[mi], h2);
                    mma16816(acc[mi][ni], ah[mi], l2);
                    mma16816(acc[mi][ni], al[mi], h2);
                }
        }
    }

    // epilogue
#pragma unroll
    for (int mi = 0; mi < 2; mi++) {
        int r0 = bm + wm + mi * 16 + (lane >> 2);
#pragma unroll
        for (int ni = 0; ni < 4; ni++) {
            int c0 = bn + wn + ni * 8 + ((lane & 3) << 1);
            *(float2*)&C[(size_t)r0 * N + c0] = make_float2(acc[mi][ni][0], acc[mi][ni][1]);
            *(float2*)&C[(size_t)(r0 + 8) * N + c0] = make_float2(acc[mi][ni][2], acc[mi][ni][3]);
        }
    }
}

// ---------------------------------------------------------------------------
// One-shot fp32 -> bf16 hi/lo split for all six tensors (single launch)
// ---------------------------------------------------------------------------
__device__ __forceinline__ void cvt1(const float* __restrict__ src,
                                     __nv_bfloat16* __restrict__ hi,
                                     __nv_bfloat16* __restrict__ lo, int i) {
    float4 v = ((const float4*)src)[i];
    __nv_bfloat16 h0 = __float2bfloat16(v.x), h1 = __float2bfloat16(v.y);
    __nv_bfloat16 h2 = __float2bfloat16(v.z), h3 = __float2bfloat16(v.w);
    __nv_bfloat162* hp = (__nv_bfloat162*)hi;
    __nv_bfloat162* lp = (__nv_bfloat162*)lo;
    hp[2 * i]     = __nv_bfloat162(h0, h1);
    hp[2 * i + 1] = __nv_bfloat162(h2, h3);
    lp[2 * i]     = __nv_bfloat162(__float2bfloat16(v.x - __bfloat162float(h0)),
                                   __float2bfloat16(v.y - __bfloat162float(h1)));
    lp[2 * i + 1] = __nv_bfloat162(__float2bfloat16(v.z - __bfloat162float(h2)),
                                   __float2bfloat16(v.w - __bfloat162float(h3)));
}

#define S_X   2097152   // 8192*1024/4
#define S_WIN 524288    // 2048*1024/4
#define S_WB  262144
#define S_WC  262144
#define S_WDT 4096
#define S_WO  262144
#define S_TOT (S_X + S_WIN + S_WB + S_WC + S_WDT + S_WO)   // 3411968

__global__ __launch_bounds__(256)
void cvt_all(const float* __restrict__ x, const float* __restrict__ Win,
             const float* __restrict__ WB, const float* __restrict__ WC,
             const float* __restrict__ Wdt, const float* __restrict__ Wout) {
    int i = blockIdx.x * 256 + threadIdx.x;
    if (i < S_X) { cvt1(x, gXhi, gXlo, i); return; }
    i -= S_X;
    if (i < S_WIN) { cvt1(Win, gWcatHi, gWcatLo, i); return; }
    i -= S_WIN;
    if (i < S_WB) { cvt1(WB, gWcatHi + 2048 * DMOD, gWcatLo + 2048 * DMOD, i); return; }
    i -= S_WB;
    if (i < S_WC) { cvt1(WC, gWcatHi + 3072 * DMOD, gWcatLo + 3072 * DMOD, i); return; }
    i -= S_WC;
    if (i < S_WDT) { cvt1(Wdt, gWcatHi + 4096 * DMOD, gWcatLo + 4096 * DMOD, i); return; }
    i -= S_WDT;
    if (i < S_WO) { cvt1(Wout, gWoHi, gWoLo, i); return; }
}

// ---------------------------------------------------------------------------
// SSD pass 1: per (b, chunk, head) tile -> Y_diag, chunk-end states, A_last
// ---------------------------------------------------------------------------
__global__ __launch_bounds__(256)
void ssd_pass1(const float* __restrict__ Alog, const float* __restrict__ bdt) {
    extern __shared__ float sm[];
    float* sB = sm;
    float* sC = sm + 64 * 65;
    float* sX = sm + 2 * 64 * 65;
    __shared__ float sdt[64];
    __shared__ float sacum[64];
    __shared__ float sdec[64];

    const int tile = blockIdx.x;
    const int h = tile & 15;
    const int c = (tile >> 4) & 63;
    const int b = tile >> 10;
    const int t = threadIdx.x;
    const int tokb = b * 4096 + c * 64;

    if (t < 64) {
        float v = gProj[(size_t)(tokb + t) * PROJN + 4096 + h] + bdt[h];
        sdt[t] = (v > 20.f) ? v : log1pf(expf(v));
    }
    __syncthreads();
    if (t == 0) {
        float expA = expf(Alog[h]);
        float run = 0.f;
        for (int l = 0; l < 64; l++) { run -= expA * sdt[l]; sacum[l] = run; }
    }
#pragma unroll
    for (int k = 0; k < 16; k++) {
        int idx = t + k * 256;
        int l = idx >> 6, n = idx & 63;
        size_t tok = (size_t)(tokb + l);
        sB[l * 65 + n] = gProj[tok * PROJN + 2048 + h * 64 + n];
        sC[l * 65 + n] = gProj[tok * PROJN + 3072 + h * 64 + n];
        sX[l * 65 + n] = gProj[tok * PROJN + h * 64 + n] * sdt[l];
    }
    __syncthreads();
    if (t < 64) sdec[t] = expf(sacum[63] - sacum[t]);

    const int ty = t >> 4, tx = t & 15;
    const int r0 = ty * 4, c0 = tx * 4;

    float g[4][4] = {};
#pragma unroll 4
    for (int n = 0; n < 64; n++) {
        float a[4], bb[4];
#pragma unroll
        for (int i = 0; i < 4; i++) a[i]  = sC[(r0 + i) * 65 + n];
#pragma unroll
        for (int j = 0; j < 4; j++) bb[j] = sB[(c0 + j) * 65 + n];
#pragma unroll
        for (int i = 0; i < 4; i++)
#pragma unroll
            for (int j = 0; j < 4; j++) g[i][j] += a[i] * bb[j];
    }
#pragma unroll
    for (int i = 0; i < 4; i++)
#pragma unroll
        for (int j = 0; j < 4; j++) {
            int l = r0 + i, s = c0 + j;
            g[i][j] = (s <= l) ? g[i][j] * expf(sacum[l] - sacum[s]) : 0.f;
        }
    __syncthreads();
#pragma unroll
    for (int i = 0; i < 4; i++)
#pragma unroll
        for (int j = 0; j < 4; j++) sC[(r0 + i) * 65 + c0 + j] = g[i][j];
    __syncthreads();

    float yd[4][4] = {};
#pragma unroll 4
    for (int s = 0; s < 64; s++) {
        float a[4], bb[4];
#pragma unroll
        for (int i = 0; i < 4; i++) a[i]  = sC[(r0 + i) * 65 + s];
#pragma unroll
        for (int j = 0; j < 4; j++) bb[j] = sX[s * 65 + c0 + j];
#pragma unroll
        for (int i = 0; i < 4; i++)
#pragma unroll
            for (int j = 0; j < 4; j++) yd[i][j] += a[i] * bb[j];
    }
    float st[4][4] = {};
#pragma unroll 4
    for (int l = 0; l < 64; l++) {
        float d = sdec[l];
        float a[4], bb[4];
#pragma unroll
        for (int i = 0; i < 4; i++) a[i]  = sX[l * 65 + r0 + i] * d;
#pragma unroll
        for (int j = 0; j < 4; j++) bb[j] = sB[l * 65 + c0 + j];
#pragma unroll
        for (int i = 0; i < 4; i++)
#pragma unroll
            for (int j = 0; j < 4; j++) st[i][j] += a[i] * bb[j];
    }
    size_t obase = (size_t)tile * 4096;
#pragma unroll
    for (int i = 0; i < 4; i++)
#pragma unroll
        for (int j = 0; j < 4; j++) {
            gYdiag[obase + (r0 + i) * 64 + c0 + j]  = yd[i][j];
            gStates[obase + (r0 + i) * 64 + c0 + j] = st[i][j];
        }
    if (t == 0) gAlast[tile] = sacum[63];
}

// ---------------------------------------------------------------------------
// Chunk-level scan, one element per thread
// ---------------------------------------------------------------------------
__global__ __launch_bounds__(256)
void scan_kernel(float* __restrict__ out_final) {
    const int bh = blockIdx.x >> 4;
    const int b = bh >> 4, h = bh & 15;
    const int e = ((blockIdx.x & 15) << 8) | threadIdx.x;
    float S = 0.f;
#pragma unroll 4
    for (int c = 0; c < 64; c++) {
        int tile = (b * 64 + c) * 16 + h;
        float d = expf(gAlast[tile]);
        size_t base = (size_t)tile * 4096 + e;
        gStateIn[base] = S;
        S = S * d + gStates[base];
    }
    out_final[(size_t)Y_ELEMS + (size_t)(b * 16 + h) * 4096 + e] = S;
}

// ---------------------------------------------------------------------------
// SSD pass 2: Y_off + silu gating; writes bf16 hi/lo for the final GEMM
// ---------------------------------------------------------------------------
__global__ __launch_bounds__(256)
void ssd_pass2(const float* __restrict__ Alog, const float* __restrict__ bdt) {
    __shared__ float sC[64 * 65];
    __shared__ float sS[64 * 65];
    __shared__ float sdt[64];
    __shared__ float sacum[64];

    const int tile = blockIdx.x;
    const int h = tile & 15;
    const int c = (tile >> 4) & 63;
    const int b = tile >> 10;
    const int t = threadIdx.x;
    const int tokb = b * 4096 + c * 64;

    if (t < 64) {
        float v = gProj[(size_t)(tokb + t) * PROJN + 4096 + h] + bdt[h];
        sdt[t] = (v > 20.f) ? v : log1pf(expf(v));
    }
    __syncthreads();
    if (t == 0) {
        float expA = expf(Alog[h]);
        float run = 0.f;
        for (int l = 0; l < 64; l++) { run -= expA * sdt[l]; sacum[l] = run; }
    }
    size_t sbase = (size_t)tile * 4096;
#pragma unroll
    for (int k = 0; k < 16; k++) {
        int idx = t + k * 256;
        int l = idx >> 6, n = idx & 63;
        sC[l * 65 + n] = gProj[(size_t)(tokb + l) * PROJN + 3072 + h * 64 + n];
        sS[l * 65 + n] = gStateIn[sbase + idx];
    }
    __syncthreads();

    const int ty = t >> 4, tx = t & 15;
    const int r0 = ty * 4, c0 = tx * 4;
    float o[4][4] = {};
#pragma unroll 4
    for (int n = 0; n < 64; n++) {
        float a[4], bb[4];
#pragma unroll
        for (int i = 0; i < 4; i++) a[i]  = sC[(r0 + i) * 65 + n];
#pragma unroll
        for (int j = 0; j < 4; j++) bb[j] = sS[(c0 + j) * 65 + n];
#pragma unroll
        for (int i = 0; i < 4; i++)
#pragma unroll
            for (int j = 0; j < 4; j++) o[i][j] += a[i] * bb[j];
    }
#pragma unroll
    for (int i = 0; i < 4; i++) {
        int l = r0 + i;
        size_t tok = (size_t)(tokb + l);
        float eA = expf(sacum[l]);
#pragma unroll
        for (int j = 0; j < 4; j++) {
            int p = c0 + j;
            int dcol = h * 64 + p;
            float yv = gYdiag[sbase + l * 64 + p] + o[i][j] * eA;
            float zv = gProj[tok * PROJN + 1024 + dcol];
            float sig = 1.f / (1.f + expf(-zv));
            float y = yv * (zv * sig);
            __nv_bfloat16 hh = __float2bfloat16(y);
            gYaHi[tok * DMOD + dcol] = hh;
            gYaLo[tok * DMOD + dcol] = __float2bfloat16(y - __bfloat162float(hh));
        }
    }
}

// ---------------------------------------------------------------------------
extern "C" void kernel_launch(void* const* d_in, const int* in_sizes, int n_in,
                              void* d_out, int out_size) {
    const float* x     = (const float*)d_in[0];
    const float* W_in  = (const float*)d_in[1];
    const float* W_dt  = (const float*)d_in[2];
    const float* b_dt  = (const float*)d_in[3];
    const float* W_B   = (const float*)d_in[4];
    const float* W_C   = (const float*)d_in[5];
    const float* W_out = (const float*)d_in[6];
    const float* A_log = (const float*)d_in[7];
    float* out = (float*)d_out;

    void *pProj;
    cudaGetSymbolAddress(&pProj, gProj);
    void *pXhi, *pXlo, *pWcH, *pWcL, *pWoH, *pWoL, *pYaH, *pYaL;
    cudaGetSymbolAddress(&pXhi, gXhi);   cudaGetSymbolAddress(&pXlo, gXlo);
    cudaGetSymbolAddress(&pWcH, gWcatHi); cudaGetSymbolAddress(&pWcL, gWcatLo);
    cudaGetSymbolAddress(&pWoH, gWoHi);  cudaGetSymbolAddress(&pWoL, gWoLo);
    cudaGetSymbolAddress(&pYaH, gYaHi);  cudaGetSymbolAddress(&pYaL, gYaLo);

    cudaFuncSetAttribute(gemm_mma, cudaFuncAttributeMaxDynamicSharedMemorySize, GEMM_SMEM);
    const int P1_SHMEM = 3 * 64 * 65 * (int)sizeof(float);
    cudaFuncSetAttribute(ssd_pass1, cudaFuncAttributeMaxDynamicSharedMemorySize, P1_SHMEM);

    // launch #0: all fp32->bf16 hi/lo conversions
    cvt_all<<<S_TOT / 256, 256>>>(x, W_in, W_B, W_C, W_dt, W_out);

    // launch #1: combined projection GEMM [8192 x 4352 x 1024] -> gProj
    gemm_mma<<<dim3(PROJN / TN, NTOK / TM), 512, GEMM_SMEM>>>(
        (const __nv_bfloat16*)pXhi, (const __nv_bfloat16*)pXlo,
        (const __nv_bfloat16*)pWcH, (const __nv_bfloat16*)pWcL,
        (float*)pProj, NTOK, PROJN, DMOD);

    // launches #2-#4
    ssd_pass1<<<NTILE, 256, P1_SHMEM>>>(A_log, b_dt);
    scan_kernel<<<512, 256>>>(out);
    ssd_pass2<<<NTILE, 256>>>(A_log, b_dt);

    // launch #5 (ncu -s 5 profiles this): y = Yact @ W_out^T -> d_out
    gemm_mma<<<dim3(DMOD / TN, NTOK / TM), 512, GEMM_SMEM>>>(
        (const __nv_bfloat16*)pYaH, (const __nv_bfloat16*)pYaL,
        (const __nv_bfloat16*)pWoH, (const __nv_bfloat16*)pWoL,
        out, NTOK, DMOD, DMOD);
}

// round 6
// speedup vs baseline: 1.4214x; 1.4214x over previous
#include <cuda_runtime.h>
#include <cuda_fp16.h>
#include <math.h>
#include <stdint.h>

// ---------------------------------------------------------------------------
// Shapes: b=2, L=4096, d=1024, h=16, n=p=64, chunk=64 -> tokens 8192, tiles 2048
// Output: y (8388608 f32) then final_state (131072 f32)
// ---------------------------------------------------------------------------
#define NTOK   8192
#define DMOD   1024
#define NHEADS 16
#define NTILE  2048
#define Y_ELEMS 8388608
#define PROJN  4352    // 2048 (xz) + 1024 (B) + 1024 (C) + 16 (dt) + 240 pad

// fp32 scratch
__device__ float gProj[NTOK * PROJN];    // [tok][xz | B | C | dtraw | pad]
__device__ float gYdiag[NTILE * 4096];
__device__ float gStates[NTILE * 4096];
__device__ float gStateIn[NTILE * 4096];
__device__ float gAlast[NTILE];

// fp16 operand scratch (zero-initialized; pad rows of gWcat stay 0)
__device__ __half gXhi[NTOK * DMOD], gXlo[NTOK * DMOD];
__device__ __half gWcat[PROJN * DMOD];
__device__ __half gWo[DMOD * DMOD];
__device__ __half gYaHi[NTOK * DMOD], gYaLo[NTOK * DMOD];

// ---------------------------------------------------------------------------
// PTX helpers (sm_80-level only: cp.async, ldmatrix, mma.sync)
// ---------------------------------------------------------------------------
__device__ __forceinline__ uint32_t smem_u32(const void* p) {
    uint32_t a;
    asm("{ .reg .u64 t; cvta.to.shared.u64 t, %1; cvt.u32.u64 %0, t; }" : "=r"(a) : "l"(p));
    return a;
}
#define SW128(o) ((o) ^ (((o) >> 3) & 0x70))

__device__ __forceinline__ void cp16(uint32_t dst, const void* src) {
    asm volatile("cp.async.cg.shared.global [%0], [%1], 16;\n" :: "r"(dst), "l"(src));
}
__device__ __forceinline__ void cp_commit() { asm volatile("cp.async.commit_group;\n" ::: "memory"); }
template <int N> __device__ __forceinline__ void cp_wait() {
    asm volatile("cp.async.wait_group %0;\n" :: "n"(N) : "memory");
}
__device__ __forceinline__ void ldsm4(uint32_t* r, uint32_t addr) {
    asm volatile("ldmatrix.sync.aligned.m8n8.x4.shared.b16 {%0,%1,%2,%3}, [%4];"
                 : "=r"(r[0]), "=r"(r[1]), "=r"(r[2]), "=r"(r[3]) : "r"(addr));
}
__device__ __forceinline__ void mma16816(float* d, const uint32_t* a, const uint32_t* b) {
    asm volatile("mma.sync.aligned.m16n8k16.row.col.f32.f16.f16.f32 "
                 "{%0,%1,%2,%3}, {%4,%5,%6,%7}, {%8,%9}, {%0,%1,%2,%3};"
                 : "+f"(d[0]), "+f"(d[1]), "+f"(d[2]), "+f"(d[3])
                 : "r"(a[0]), "r"(a[1]), "r"(a[2]), "r"(a[3]), "r"(b[0]), "r"(b[1]));
}

// ---------------------------------------------------------------------------
// Tensor-core GEMM: C[M,N] = (Ahi+Alo)[M,K] @ B[N,K]^T, fp16 2-term.
// CTA tile 128x128, 256 threads (8 warps 2m x 4n; warp tile 64x32),
// K chunk 64, double buffered cp.async, SW128 swizzle. (Round-3 proven shape.)
// ---------------------------------------------------------------------------
#define OF_AH 0
#define OF_AL 16384
#define OF_B  32768
#define STG   49152
#define GEMM_SMEM (2 * STG)   // 98304

__device__ __forceinline__ void load_rows(uint32_t smem_dst, const __half* g,
                                          int row0, int K, int k0, int t) {
#pragma unroll
    for (int it = 0; it < 4; it++) {
        int p = t + it * 256;               // 1024 16B transfers for 128x64 fp16
        int r = p >> 3, cc = p & 7;
        uint32_t off = (uint32_t)(r * 128 + cc * 16);
        cp16(smem_dst + SW128(off), g + (size_t)(row0 + r) * K + k0 + cc * 8);
    }
}

__global__ __launch_bounds__(256)
void gemm_mma(const __half* __restrict__ Ah, const __half* __restrict__ Al,
              const __half* __restrict__ B, float* __restrict__ C,
              int M, int N, int K) {
    extern __shared__ char smem[];
    const uint32_t sb = smem_u32(smem);
    const int t = threadIdx.x;
    const int wid = t >> 5, lane = t & 31;
    const int bm = blockIdx.y * 128;
    const int bn = blockIdx.x * 128;
    const int wm = (wid >> 2) * 64;
    const int wn = (wid & 3) * 32;
    const int nch = K >> 6;

    float acc[4][4][4];
#pragma unroll
    for (int i = 0; i < 4; i++)
#pragma unroll
        for (int j = 0; j < 4; j++)
#pragma unroll
            for (int k = 0; k < 4; k++) acc[i][j][k] = 0.f;

    // prologue: chunk 0 -> stage 0
    load_rows(sb + OF_AH, Ah, bm, K, 0, t);
    load_rows(sb + OF_AL, Al, bm, K, 0, t);
    load_rows(sb + OF_B,  B,  bn, K, 0, t);
    cp_commit();

    for (int i = 0; i < nch; i++) {
        if (i + 1 < nch) {
            uint32_t st2 = sb + ((i + 1) & 1) * STG;
            int k0 = (i + 1) * 64;
            load_rows(st2 + OF_AH, Ah, bm, K, k0, t);
            load_rows(st2 + OF_AL, Al, bm, K, k0, t);
            load_rows(st2 + OF_B,  B,  bn, K, k0, t);
            cp_commit();
            cp_wait<1>();
        } else {
            cp_wait<0>();
        }
        __syncthreads();
        const uint32_t st = sb + (i & 1) * STG;

#pragma unroll
        for (int kk = 0; kk < 4; kk++) {
            uint32_t ah[4][4], al[4][4], bn2[2][4];
#pragma unroll
            for (int mi = 0; mi < 4; mi++) {
                int row = wm + mi * 16 + (lane & 15);
                uint32_t off = (uint32_t)(row * 128 + kk * 32 + ((lane >> 4) << 4));
                ldsm4(ah[mi], st + OF_AH + SW128(off));
                ldsm4(al[mi], st + OF_AL + SW128(off));
            }
#pragma unroll
            for (int nb = 0; nb < 2; nb++) {
                int rown = wn + nb * 16 + (lane & 7) + (((lane >> 4) & 1) << 3);
                uint32_t off = (uint32_t)(rown * 128 + kk * 32 + (((lane >> 3) & 1) << 4));
                ldsm4(bn2[nb], st + OF_B + SW128(off));
            }
#pragma unroll
            for (int mi = 0; mi < 4; mi++)
#pragma unroll
                for (int ni = 0; ni < 4; ni++) {
                    const uint32_t* b2 = &bn2[ni >> 1][(ni & 1) * 2];
                    mma16816(acc[mi][ni], ah[mi], b2);
                    mma16816(acc[mi][ni], al[mi], b2);
                }
        }
        __syncthreads();
    }

    // epilogue
#pragma unroll
    for (int mi = 0; mi < 4; mi++) {
        int r0 = bm + wm + mi * 16 + (lane >> 2);
#pragma unroll
        for (int ni = 0; ni < 4; ni++) {
            int c0 = bn + wn + ni * 8 + ((lane & 3) << 1);
            *(float2*)&C[(size_t)r0 * N + c0] = make_float2(acc[mi][ni][0], acc[mi][ni][1]);
            *(float2*)&C[(size_t)(r0 + 8) * N + c0] = make_float2(acc[mi][ni][2], acc[mi][ni][3]);
        }
    }
}

// ---------------------------------------------------------------------------
// One-shot conversions: x -> fp16 hi/lo, weights -> fp16 (single launch)
// ---------------------------------------------------------------------------
__device__ __forceinline__ void cvt_hl(const float* __restrict__ src,
                                       __half* __restrict__ hi,
                                       __half* __restrict__ lo, int i) {
    float4 v = ((const float4*)src)[i];
    __half h0 = __float2half(v.x), h1 = __float2half(v.y);
    __half h2 = __float2half(v.z), h3 = __float2half(v.w);
    __half2* hp = (__half2*)hi;
    __half2* lp = (__half2*)lo;
    hp[2 * i]     = __half2(h0, h1);
    hp[2 * i + 1] = __half2(h2, h3);
    lp[2 * i]     = __half2(__float2half(v.x - __half2float(h0)),
                            __float2half(v.y - __half2float(h1)));
    lp[2 * i + 1] = __half2(__float2half(v.z - __half2float(h2)),
                            __float2half(v.w - __half2float(h3)));
}
__device__ __forceinline__ void cvt_s(const float* __restrict__ src,
                                      __half* __restrict__ dst, int i) {
    float4 v = ((const float4*)src)[i];
    __half2* dp = (__half2*)dst;
    dp[2 * i]     = __half2(__float2half(v.x), __float2half(v.y));
    dp[2 * i + 1] = __half2(__float2half(v.z), __float2half(v.w));
}

#define S_X   2097152   // 8192*1024/4
#define S_WIN 524288    // 2048*1024/4
#define S_WB  262144
#define S_WC  262144
#define S_WDT 4096
#define S_WO  262144
#define S_TOT (S_X + S_WIN + S_WB + S_WC + S_WDT + S_WO)

__global__ __launch_bounds__(256)
void cvt_all(const float* __restrict__ x, const float* __restrict__ Win,
             const float* __restrict__ WB, const float* __restrict__ WC,
             const float* __restrict__ Wdt, const float* __restrict__ Wout) {
    int i = blockIdx.x * 256 + threadIdx.x;
    if (i < S_X) { cvt_hl(x, gXhi, gXlo, i); return; }
    i -= S_X;
    if (i < S_WIN) { cvt_s(Win, gWcat, i); return; }
    i -= S_WIN;
    if (i < S_WB) { cvt_s(WB, gWcat + 2048 * DMOD, i); return; }
    i -= S_WB;
    if (i < S_WC) { cvt_s(WC, gWcat + 3072 * DMOD, i); return; }
    i -= S_WC;
    if (i < S_WDT) { cvt_s(Wdt, gWcat + 4096 * DMOD, i); return; }
    i -= S_WDT;
    if (i < S_WO) { cvt_s(Wout, gWo, i); return; }
}

// ---------------------------------------------------------------------------
// SSD pass 1: per (b, chunk, head) tile -> Y_diag, chunk-end states, A_last
// ---------------------------------------------------------------------------
__global__ __launch_bounds__(256)
void ssd_pass1(const float* __restrict__ Alog, const float* __restrict__ bdt) {
    extern __shared__ float sm[];
    float* sB = sm;
    float* sC = sm + 64 * 65;
    float* sX = sm + 2 * 64 * 65;
    __shared__ float sdt[64];
    __shared__ float sacum[64];
    __shared__ float sdec[64];

    const int tile = blockIdx.x;
    const int h = tile & 15;
    const int c = (tile >> 4) & 63;
    const int b = tile >> 10;
    const int t = threadIdx.x;
    const int tokb = b * 4096 + c * 64;

    if (t < 64) {
        float v = gProj[(size_t)(tokb + t) * PROJN + 4096 + h] + bdt[h];
        sdt[t] = (v > 20.f) ? v : log1pf(expf(v));
    }
    __syncthreads();
    if (t == 0) {
        float expA = expf(Alog[h]);
        float run = 0.f;
        for (int l = 0; l < 64; l++) { run -= expA * sdt[l]; sacum[l] = run; }
    }
#pragma unroll
    for (int k = 0; k < 16; k++) {
        int idx = t + k * 256;
        int l = idx >> 6, n = idx & 63;
        size_t tok = (size_t)(tokb + l);
        sB[l * 65 + n] = gProj[tok * PROJN + 2048 + h * 64 + n];
        sC[l * 65 + n] = gProj[tok * PROJN + 3072 + h * 64 + n];
        sX[l * 65 + n] = gProj[tok * PROJN + h * 64 + n] * sdt[l];
    }
    __syncthreads();
    if (t < 64) sdec[t] = expf(sacum[63] - sacum[t]);

    const int ty = t >> 4, tx = t & 15;
    const int r0 = ty * 4, c0 = tx * 4;

    float g[4][4] = {};
#pragma unroll 4
    for (int n = 0; n < 64; n++) {
        float a[4], bb[4];
#pragma unroll
        for (int i = 0; i < 4; i++) a[i]  = sC[(r0 + i) * 65 + n];
#pragma unroll
        for (int j = 0; j < 4; j++) bb[j] = sB[(c0 + j) * 65 + n];
#pragma unroll
        for (int i = 0; i < 4; i++)
#pragma unroll
            for (int j = 0; j < 4; j++) g[i][j] += a[i] * bb[j];
    }
#pragma unroll
    for (int i = 0; i < 4; i++)
#pragma unroll
        for (int j = 0; j < 4; j++) {
            int l = r0 + i, s = c0 + j;
            g[i][j] = (s <= l) ? g[i][j] * expf(sacum[l] - sacum[s]) : 0.f;
        }
    __syncthreads();
#pragma unroll
    for (int i = 0; i < 4; i++)
#pragma unroll
        for (int j = 0; j < 4; j++) sC[(r0 + i) * 65 + c0 + j] = g[i][j];
    __syncthreads();

    float yd[4][4] = {};
#pragma unroll 4
    for (int s = 0; s < 64; s++) {
        float a[4], bb[4];
#pragma unroll
        for (int i = 0; i < 4; i++) a[i]  = sC[(r0 + i) * 65 + s];
#pragma unroll
        for (int j = 0; j < 4; j++) bb[j] = sX[s * 65 + c0 + j];
#pragma unroll
        for (int i = 0; i < 4; i++)
#pragma unroll
            for (int j = 0; j < 4; j++) yd[i][j] += a[i] * bb[j];
    }
    float st[4][4] = {};
#pragma unroll 4
    for (int l = 0; l < 64; l++) {
        float d = sdec[l];
        float a[4], bb[4];
#pragma unroll
        for (int i = 0; i < 4; i++) a[i]  = sX[l * 65 + r0 + i] * d;
#pragma unroll
        for (int j = 0; j < 4; j++) bb[j] = sB[l * 65 + c0 + j];
#pragma unroll
        for (int i = 0; i < 4; i++)
#pragma unroll
            for (int j = 0; j < 4; j++) st[i][j] += a[i] * bb[j];
    }
    size_t obase = (size_t)tile * 4096;
#pragma unroll
    for (int i = 0; i < 4; i++)
#pragma unroll
        for (int j = 0; j < 4; j++) {
            gYdiag[obase + (r0 + i) * 64 + c0 + j]  = yd[i][j];
            gStates[obase + (r0 + i) * 64 + c0 + j] = st[i][j];
        }
    if (t == 0) gAlast[tile] = sacum[63];
}

// ---------------------------------------------------------------------------
// Chunk-level scan, one element per thread
// ---------------------------------------------------------------------------
__global__ __launch_bounds__(256)
void scan_kernel(float* __restrict__ out_final) {
    const int bh = blockIdx.x >> 4;
    const int b = bh >> 4, h = bh & 15;
    const int e = ((blockIdx.x & 15) << 8) | threadIdx.x;
    float S = 0.f;
#pragma unroll 4
    for (int c = 0; c < 64; c++) {
        int tile = (b * 64 + c) * 16 + h;
        float d = expf(gAlast[tile]);
        size_t base = (size_t)tile * 4096 + e;
        gStateIn[base] = S;
        S = S * d + gStates[base];
    }
    out_final[(size_t)Y_ELEMS + (size_t)(b * 16 + h) * 4096 + e] = S;
}

// ---------------------------------------------------------------------------
// SSD pass 2: Y_off + silu gating; writes fp16 hi/lo for the final GEMM
// ---------------------------------------------------------------------------
__global__ __launch_bounds__(256)
void ssd_pass2(const float* __restrict__ Alog, const float* __restrict__ bdt) {
    __shared__ float sC[64 * 65];
    __shared__ float sS[64 * 65];
    __shared__ float sdt[64];
    __shared__ float sacum[64];

    const int tile = blockIdx.x;
    const int h = tile & 15;
    const int c = (tile >> 4) & 63;
    const int b = tile >> 10;
    const int t = threadIdx.x;
    const int tokb = b * 4096 + c * 64;

    if (t < 64) {
        float v = gProj[(size_t)(tokb + t) * PROJN + 4096 + h] + bdt[h];
        sdt[t] = (v > 20.f) ? v : log1pf(expf(v));
    }
    __syncthreads();
    if (t == 0) {
        float expA = expf(Alog[h]);
        float run = 0.f;
        for (int l = 0; l < 64; l++) { run -= expA * sdt[l]; sacum[l] = run; }
    }
    size_t sbase = (size_t)tile * 4096;
#pragma unroll
    for (int k = 0; k < 16; k++) {
        int idx = t + k * 256;
        int l = idx >> 6, n = idx & 63;
        sC[l * 65 + n] = gProj[(size_t)(tokb + l) * PROJN + 3072 + h * 64 + n];
        sS[l * 65 + n] = gStateIn[sbase + idx];
    }
    __syncthreads();

    const int ty = t >> 4, tx = t & 15;
    const int r0 = ty * 4, c0 = tx * 4;
    float o[4][4] = {};
#pragma unroll 4
    for (int n = 0; n < 64; n++) {
        float a[4], bb[4];
#pragma unroll
        for (int i = 0; i < 4; i++) a[i]  = sC[(r0 + i) * 65 + n];
#pragma unroll
        for (int j = 0; j < 4; j++) bb[j] = sS[(c0 + j) * 65 + n];
#pragma unroll
        for (int i = 0; i < 4; i++)
#pragma unroll
            for (int j = 0; j < 4; j++) o[i][j] += a[i] * bb[j];
    }
#pragma unroll
    for (int i = 0; i < 4; i++) {
        int l = r0 + i;
        size_t tok = (size_t)(tokb + l);
        float eA = expf(sacum[l]);
#pragma unroll
        for (int j = 0; j < 4; j++) {
            int p = c0 + j;
            int dcol = h * 64 + p;
            float yv = gYdiag[sbase + l * 64 + p] + o[i][j] * eA;
            float zv = gProj[tok * PROJN + 1024 + dcol];
            float sig = 1.f / (1.f + expf(-zv));
            float y = yv * (zv * sig);
            __half hh = __float2half(y);
            gYaHi[tok * DMOD + dcol] = hh;
            gYaLo[tok * DMOD + dcol] = __float2half(y - __half2float(hh));
        }
    }
}

// ---------------------------------------------------------------------------
extern "C" void kernel_launch(void* const* d_in, const int* in_sizes, int n_in,
                              void* d_out, int out_size) {
    const float* x     = (const float*)d_in[0];
    const float* W_in  = (const float*)d_in[1];
    const float* W_dt  = (const float*)d_in[2];
    const float* b_dt  = (const float*)d_in[3];
    const float* W_B   = (const float*)d_in[4];
    const float* W_C   = (const float*)d_in[5];
    const float* W_out = (const float*)d_in[6];
    const float* A_log = (const float*)d_in[7];
    float* out = (float*)d_out;

    void *pProj;
    cudaGetSymbolAddress(&pProj, gProj);
    void *pXhi, *pXlo, *pWc, *pWo, *pYaH, *pYaL;
    cudaGetSymbolAddress(&pXhi, gXhi); cudaGetSymbolAddress(&pXlo, gXlo);
    cudaGetSymbolAddress(&pWc, gWcat); cudaGetSymbolAddress(&pWo, gWo);
    cudaGetSymbolAddress(&pYaH, gYaHi); cudaGetSymbolAddress(&pYaL, gYaLo);

    cudaFuncSetAttribute(gemm_mma, cudaFuncAttributeMaxDynamicSharedMemorySize, GEMM_SMEM);
    const int P1_SHMEM = 3 * 64 * 65 * (int)sizeof(float);
    cudaFuncSetAttribute(ssd_pass1, cudaFuncAttributeMaxDynamicSharedMemorySize, P1_SHMEM);

    // #0: conversions
    cvt_all<<<S_TOT / 256, 256>>>(x, W_in, W_B, W_C, W_dt, W_out);

    // #1: combined projection GEMM [8192 x 4352 x 1024] -> gProj
    gemm_mma<<<dim3(PROJN / 128, NTOK / 128), 256, GEMM_SMEM>>>(
        (const __half*)pXhi, (const __half*)pXlo, (const __half*)pWc,
        (float*)pProj, NTOK, PROJN, DMOD);

    // #2-#4
    ssd_pass1<<<NTILE, 256, P1_SHMEM>>>(A_log, b_dt);
    scan_kernel<<<512, 256>>>(out);
    ssd_pass2<<<NTILE, 256>>>(A_log, b_dt);

    // #5: y = Yact @ W_out^T -> d_out
    gemm_mma<<<dim3(DMOD / 128, NTOK / 128), 256, GEMM_SMEM>>>(
        (const __half*)pYaH, (const __half*)pYaL, (const __half*)pWo,
        out, NTOK, DMOD, DMOD);
}

// round 7
// speedup vs baseline: 1.4639x; 1.0300x over previous
#include <cuda_runtime.h>
#include <cuda_fp16.h>
#include <math.h>
#include <stdint.h>

// ---------------------------------------------------------------------------
// Shapes: b=2, L=4096, d=1024, h=16, n=p=64, chunk=64 -> tokens 8192, tiles 2048
// Output: y (8388608 f32) then final_state (131072 f32)
// ---------------------------------------------------------------------------
#define NTOK   8192
#define DMOD   1024
#define NHEADS 16
#define NTILE  2048
#define Y_ELEMS 8388608
#define PROJN  4224    // 2048 (xz) + 1024 (B) + 1024 (C) + 16 (dt) + 112 pad = 33*128

#define LO_SCALE     2048.0f
#define LO_INV_SCALE (1.0f / 2048.0f)

// fp32 scratch
__device__ float gProj[NTOK * PROJN];    // [tok][xz | B | C | dtraw | pad]
__device__ float gYdiag[NTILE * 4096];
__device__ float gStates[NTILE * 4096];
__device__ float gStateIn[NTILE * 4096];
__device__ float gAlast[NTILE];

// fp16 operand scratch (zero-initialized; pad rows of gWcat stay 0)
__device__ __half gXhi[NTOK * DMOD], gXlo[NTOK * DMOD];     // lo pre-scaled by 2048
__device__ __half gWcat[PROJN * DMOD];
__device__ __half gWo[DMOD * DMOD];
__device__ __half gYaHi[NTOK * DMOD], gYaLo[NTOK * DMOD];   // lo pre-scaled by 2048

// ---------------------------------------------------------------------------
// PTX helpers
// ---------------------------------------------------------------------------
__device__ __forceinline__ uint32_t smem_u32(const void* p) {
    uint32_t a;
    asm("{ .reg .u64 t; cvta.to.shared.u64 t, %1; cvt.u32.u64 %0, t; }" : "=r"(a) : "l"(p));
    return a;
}
#define SW128(o) ((o) ^ (((o) >> 3) & 0x70))

__device__ __forceinline__ void cp16(uint32_t dst, const void* src) {
    asm volatile("cp.async.cg.shared.global [%0], [%1], 16;\n" :: "r"(dst), "l"(src));
}
__device__ __forceinline__ void cp_commit() { asm volatile("cp.async.commit_group;\n" ::: "memory"); }
template <int N> __device__ __forceinline__ void cp_wait() {
    asm volatile("cp.async.wait_group %0;\n" :: "n"(N) : "memory");
}
__device__ __forceinline__ void ldsm4(uint32_t* r, uint32_t addr) {
    asm volatile("ldmatrix.sync.aligned.m8n8.x4.shared.b16 {%0,%1,%2,%3}, [%4];"
                 : "=r"(r[0]), "=r"(r[1]), "=r"(r[2]), "=r"(r[3]) : "r"(addr));
}
// f32-accumulator fp16 MMA (hi term)
__device__ __forceinline__ void mma_f32(float* d, const uint32_t* a, const uint32_t* b) {
    asm volatile("mma.sync.aligned.m16n8k16.row.col.f32.f16.f16.f32 "
                 "{%0,%1,%2,%3}, {%4,%5,%6,%7}, {%8,%9}, {%0,%1,%2,%3};"
                 : "+f"(d[0]), "+f"(d[1]), "+f"(d[2]), "+f"(d[3])
                 : "r"(a[0]), "r"(a[1]), "r"(a[2]), "r"(a[3]), "r"(b[0]), "r"(b[1]));
}
// f16-accumulator fp16 MMA (scaled lo term)
__device__ __forceinline__ void mma_f16(uint32_t* d, const uint32_t* a, const uint32_t* b) {
    asm volatile("mma.sync.aligned.m16n8k16.row.col.f16.f16.f16.f16 "
                 "{%0,%1}, {%2,%3,%4,%5}, {%6,%7}, {%0,%1};"
                 : "+r"(d[0]), "+r"(d[1])
                 : "r"(a[0]), "r"(a[1]), "r"(a[2]), "r"(a[3]), "r"(b[0]), "r"(b[1]));
}

// ---------------------------------------------------------------------------
// Tensor-core GEMM: C[M,N] = (Ahi + Alo/2048)[M,K] @ B[N,K]^T.
// CTA tile 128x128, 256 threads, 8 warps as 4m x 2n (warp tile 32x64),
// K chunk 64, double-buffered cp.async, SW128 swizzle.
// hi term -> f32 accum; scaled lo term -> f16 accum, folded in epilogue.
// ---------------------------------------------------------------------------
#define OF_AH 0
#define OF_AL 16384
#define OF_B  32768
#define STG   49152
#define GEMM_SMEM (2 * STG)   // 98304

__device__ __forceinline__ void load_rows(uint32_t smem_dst, const __half* g,
                                          int row0, int K, int k0, int t) {
#pragma unroll
    for (int it = 0; it < 4; it++) {
        int p = t + it * 256;
        int r = p >> 3, cc = p & 7;
        uint32_t off = (uint32_t)(r * 128 + cc * 16);
        cp16(smem_dst + SW128(off), g + (size_t)(row0 + r) * K + k0 + cc * 8);
    }
}

__global__ __launch_bounds__(256)
void gemm_mma(const __half* __restrict__ Ah, const __half* __restrict__ Al,
              const __half* __restrict__ B, float* __restrict__ C,
              int M, int N, int K) {
    extern __shared__ char smem[];
    const uint32_t sb = smem_u32(smem);
    const int t = threadIdx.x;
    const int wid = t >> 5, lane = t & 31;
    const int bm = blockIdx.y * 128;
    const int bn = blockIdx.x * 128;
    const int wm = (wid & 3) * 32;      // 4 m-groups of 32 rows
    const int wn = (wid >> 2) * 64;     // 2 n-groups of 64 cols
    const int nch = K >> 6;

    float    acc[2][8][4];
    uint32_t accl[2][8][2];
#pragma unroll
    for (int i = 0; i < 2; i++)
#pragma unroll
        for (int j = 0; j < 8; j++) {
#pragma unroll
            for (int k = 0; k < 4; k++) acc[i][j][k] = 0.f;
            accl[i][j][0] = 0u; accl[i][j][1] = 0u;
        }

    // prologue: chunk 0 -> stage 0
    load_rows(sb + OF_AH, Ah, bm, K, 0, t);
    load_rows(sb + OF_AL, Al, bm, K, 0, t);
    load_rows(sb + OF_B,  B,  bn, K, 0, t);
    cp_commit();

    const int ra = (lane & 15);
    const uint32_t ca = (uint32_t)((lane >> 4) << 4);
    const int rb = (lane & 7) + (((lane >> 4) & 1) << 3);
    const uint32_t cb = (uint32_t)(((lane >> 3) & 1) << 4);

    for (int i = 0; i < nch; i++) {
        if (i + 1 < nch) {
            uint32_t st2 = sb + ((i + 1) & 1) * STG;
            int k0 = (i + 1) * 64;
            load_rows(st2 + OF_AH, Ah, bm, K, k0, t);
            load_rows(st2 + OF_AL, Al, bm, K, k0, t);
            load_rows(st2 + OF_B,  B,  bn, K, k0, t);
            cp_commit();
            cp_wait<1>();
        } else {
            cp_wait<0>();
        }
        __syncthreads();
        const uint32_t st = sb + (i & 1) * STG;

#pragma unroll
        for (int kk = 0; kk < 4; kk++) {
            uint32_t ah[2][4], al[2][4], bf[4][4];
#pragma unroll
            for (int mi = 0; mi < 2; mi++) {
                int row = wm + mi * 16 + ra;
                uint32_t off = (uint32_t)(row * 128 + kk * 32) + ca;
                ldsm4(ah[mi], st + OF_AH + SW128(off));
                ldsm4(al[mi], st + OF_AL + SW128(off));
            }
#pragma unroll
            for (int nb = 0; nb < 4; nb++) {
                int rown = wn + nb * 16 + rb;
                uint32_t off = (uint32_t)(rown * 128 + kk * 32) + cb;
                ldsm4(bf[nb], st + OF_B + SW128(off));
            }
#pragma unroll
            for (int mi = 0; mi < 2; mi++)
#pragma unroll
                for (int ni = 0; ni < 8; ni++) {
                    const uint32_t* b2 = &bf[ni >> 1][(ni & 1) * 2];
                    mma_f32(acc[mi][ni], ah[mi], b2);
                    mma_f16(accl[mi][ni], al[mi], b2);
                }
        }
        __syncthreads();
    }

    // epilogue: C = acc_hi + acc_lo / 2048
#pragma unroll
    for (int mi = 0; mi < 2; mi++) {
        int r0 = bm + wm + mi * 16 + (lane >> 2);
#pragma unroll
        for (int ni = 0; ni < 8; ni++) {
            int c0 = bn + wn + ni * 8 + ((lane & 3) << 1);
            __half2 l01 = *(__half2*)&accl[mi][ni][0];
            __half2 l23 = *(__half2*)&accl[mi][ni][1];
            float2 v0 = make_float2(acc[mi][ni][0] + __half2float(l01.x) * LO_INV_SCALE,
                                    acc[mi][ni][1] + __half2float(l01.y) * LO_INV_SCALE);
            float2 v1 = make_float2(acc[mi][ni][2] + __half2float(l23.x) * LO_INV_SCALE,
                                    acc[mi][ni][3] + __half2float(l23.y) * LO_INV_SCALE);
            *(float2*)&C[(size_t)r0 * N + c0] = v0;
            *(float2*)&C[(size_t)(r0 + 8) * N + c0] = v1;
        }
    }
}

// ---------------------------------------------------------------------------
// One-shot conversions: x -> fp16 hi + scaled lo, weights -> fp16
// ---------------------------------------------------------------------------
__device__ __forceinline__ void cvt_hl(const float* __restrict__ src,
                                       __half* __restrict__ hi,
                                       __half* __restrict__ lo, int i) {
    float4 v = ((const float4*)src)[i];
    __half h0 = __float2half(v.x), h1 = __float2half(v.y);
    __half h2 = __float2half(v.z), h3 = __float2half(v.w);
    __half2* hp = (__half2*)hi;
    __half2* lp = (__half2*)lo;
    hp[2 * i]     = __half2(h0, h1);
    hp[2 * i + 1] = __half2(h2, h3);
    lp[2 * i]     = __half2(__float2half((v.x - __half2float(h0)) * LO_SCALE),
                            __float2half((v.y - __half2float(h1)) * LO_SCALE));
    lp[2 * i + 1] = __half2(__float2half((v.z - __half2float(h2)) * LO_SCALE),
                            __float2half((v.w - __half2float(h3)) * LO_SCALE));
}
__device__ __forceinline__ void cvt_s(const float* __restrict__ src,
                                      __half* __restrict__ dst, int i) {
    float4 v = ((const float4*)src)[i];
    __half2* dp = (__half2*)dst;
    dp[2 * i]     = __half2(__float2half(v.x), __float2half(v.y));
    dp[2 * i + 1] = __half2(__float2half(v.z), __float2half(v.w));
}

#define S_X   2097152   // 8192*1024/4
#define S_WIN 524288
#define S_WB  262144
#define S_WC  262144
#define S_WDT 4096
#define S_WO  262144
#define S_TOT (S_X + S_WIN + S_WB + S_WC + S_WDT + S_WO)

__global__ __launch_bounds__(256)
void cvt_all(const float* __restrict__ x, const float* __restrict__ Win,
             const float* __restrict__ WB, const float* __restrict__ WC,
             const float* __restrict__ Wdt, const float* __restrict__ Wout) {
    int i = blockIdx.x * 256 + threadIdx.x;
    if (i < S_X) { cvt_hl(x, gXhi, gXlo, i); return; }
    i -= S_X;
    if (i < S_WIN) { cvt_s(Win, gWcat, i); return; }
    i -= S_WIN;
    if (i < S_WB) { cvt_s(WB, gWcat + 2048 * DMOD, i); return; }
    i -= S_WB;
    if (i < S_WC) { cvt_s(WC, gWcat + 3072 * DMOD, i); return; }
    i -= S_WC;
    if (i < S_WDT) { cvt_s(Wdt, gWcat + 4096 * DMOD, i); return; }
    i -= S_WDT;
    if (i < S_WO) { cvt_s(Wout, gWo, i); return; }
}

// ---------------------------------------------------------------------------
// SSD pass 1
// ---------------------------------------------------------------------------
__global__ __launch_bounds__(256)
void ssd_pass1(const float* __restrict__ Alog, const float* __restrict__ bdt) {
    extern __shared__ float sm[];
    float* sB = sm;
    float* sC = sm + 64 * 65;
    float* sX = sm + 2 * 64 * 65;
    __shared__ float sdt[64];
    __shared__ float sacum[64];
    __shared__ float sdec[64];

    const int tile = blockIdx.x;
    const int h = tile & 15;
    const int c = (tile >> 4) & 63;
    const int b = tile >> 10;
    const int t = threadIdx.x;
    const int tokb = b * 4096 + c * 64;

    if (t < 64) {
        float v = gProj[(size_t)(tokb + t) * PROJN + 4096 + h] + bdt[h];
        sdt[t] = (v > 20.f) ? v : log1pf(expf(v));
    }
    __syncthreads();
    if (t == 0) {
        float expA = expf(Alog[h]);
        float run = 0.f;
        for (int l = 0; l < 64; l++) { run -= expA * sdt[l]; sacum[l] = run; }
    }
#pragma unroll
    for (int k = 0; k < 16; k++) {
        int idx = t + k * 256;
        int l = idx >> 6, n = idx & 63;
        size_t tok = (size_t)(tokb + l);
        sB[l * 65 + n] = gProj[tok * PROJN + 2048 + h * 64 + n];
        sC[l * 65 + n] = gProj[tok * PROJN + 3072 + h * 64 + n];
        sX[l * 65 + n] = gProj[tok * PROJN + h * 64 + n] * sdt[l];
    }
    __syncthreads();
    if (t < 64) sdec[t] = expf(sacum[63] - sacum[t]);

    const int ty = t >> 4, tx = t & 15;
    const int r0 = ty * 4, c0 = tx * 4;

    float g[4][4] = {};
#pragma unroll 4
    for (int n = 0; n < 64; n++) {
        float a[4], bb[4];
#pragma unroll
        for (int i = 0; i < 4; i++) a[i]  = sC[(r0 + i) * 65 + n];
#pragma unroll
        for (int j = 0; j < 4; j++) bb[j] = sB[(c0 + j) * 65 + n];
#pragma unroll
        for (int i = 0; i < 4; i++)
#pragma unroll
            for (int j = 0; j < 4; j++) g[i][j] += a[i] * bb[j];
    }
#pragma unroll
    for (int i = 0; i < 4; i++)
#pragma unroll
        for (int j = 0; j < 4; j++) {
            int l = r0 + i, s = c0 + j;
            g[i][j] = (s <= l) ? g[i][j] * expf(sacum[l] - sacum[s]) : 0.f;
        }
    __syncthreads();
#pragma unroll
    for (int i = 0; i < 4; i++)
#pragma unroll
        for (int j = 0; j < 4; j++) sC[(r0 + i) * 65 + c0 + j] = g[i][j];
    __syncthreads();

    float yd[4][4] = {};
#pragma unroll 4
    for (int s = 0; s < 64; s++) {
        float a[4], bb[4];
#pragma unroll
        for (int i = 0; i < 4; i++) a[i]  = sC[(r0 + i) * 65 + s];
#pragma unroll
        for (int j = 0; j < 4; j++) bb[j] = sX[s * 65 + c0 + j];
#pragma unroll
        for (int i = 0; i < 4; i++)
#pragma unroll
            for (int j = 0; j < 4; j++) yd[i][j] += a[i] * bb[j];
    }
    float st[4][4] = {};
#pragma unroll 4
    for (int l = 0; l < 64; l++) {
        float d = sdec[l];
        float a[4], bb[4];
#pragma unroll
        for (int i = 0; i < 4; i++) a[i]  = sX[l * 65 + r0 + i] * d;
#pragma unroll
        for (int j = 0; j < 4; j++) bb[j] = sB[l * 65 + c0 + j];
#pragma unroll
        for (int i = 0; i < 4; i++)
#pragma unroll
            for (int j = 0; j < 4; j++) st[i][j] += a[i] * bb[j];
    }
    size_t obase = (size_t)tile * 4096;
#pragma unroll
    for (int i = 0; i < 4; i++)
#pragma unroll
        for (int j = 0; j < 4; j++) {
            gYdiag[obase + (r0 + i) * 64 + c0 + j]  = yd[i][j];
            gStates[obase + (r0 + i) * 64 + c0 + j] = st[i][j];
        }
    if (t == 0) gAlast[tile] = sacum[63];
}

// ---------------------------------------------------------------------------
// Chunk-level scan
// ---------------------------------------------------------------------------
__global__ __launch_bounds__(256)
void scan_kernel(float* __restrict__ out_final) {
    const int bh = blockIdx.x >> 4;
    const int b = bh >> 4, h = bh & 15;
    const int e = ((blockIdx.x & 15) << 8) | threadIdx.x;
    float S = 0.f;
#pragma unroll 4
    for (int c = 0; c < 64; c++) {
        int tile = (b * 64 + c) * 16 + h;
        float d = expf(gAlast[tile]);
        size_t base = (size_t)tile * 4096 + e;
        gStateIn[base] = S;
        S = S * d + gStates[base];
    }
    out_final[(size_t)Y_ELEMS + (size_t)(b * 16 + h) * 4096 + e] = S;
}

// ---------------------------------------------------------------------------
// SSD pass 2: Y_off + silu gating; writes fp16 hi + scaled lo
// ---------------------------------------------------------------------------
__global__ __launch_bounds__(256)
void ssd_pass2(const float* __restrict__ Alog, const float* __restrict__ bdt) {
    __shared__ float sC[64 * 65];
    __shared__ float sS[64 * 65];
    __shared__ float sdt[64];
    __shared__ float sacum[64];

    const int tile = blockIdx.x;
    const int h = tile & 15;
    const int c = (tile >> 4) & 63;
    const int b = tile >> 10;
    const int t = threadIdx.x;
    const int tokb = b * 4096 + c * 64;

    if (t < 64) {
        float v = gProj[(size_t)(tokb + t) * PROJN + 4096 + h] + bdt[h];
        sdt[t] = (v > 20.f) ? v : log1pf(expf(v));
    }
    __syncthreads();
    if (t == 0) {
        float expA = expf(Alog[h]);
        float run = 0.f;
        for (int l = 0; l < 64; l++) { run -= expA * sdt[l]; sacum[l] = run; }
    }
    size_t sbase = (size_t)tile * 4096;
#pragma unroll
    for (int k = 0; k < 16; k++) {
        int idx = t + k * 256;
        int l = idx >> 6, n = idx & 63;
        sC[l * 65 + n] = gProj[(size_t)(tokb + l) * PROJN + 3072 + h * 64 + n];
        sS[l * 65 + n] = gStateIn[sbase + idx];
    }
    __syncthreads();

    const int ty = t >> 4, tx = t & 15;
    const int r0 = ty * 4, c0 = tx * 4;
    float o[4][4] = {};
#pragma unroll 4
    for (int n = 0; n < 64; n++) {
        float a[4], bb[4];
#pragma unroll
        for (int i = 0; i < 4; i++) a[i]  = sC[(r0 + i) * 65 + n];
#pragma unroll
        for (int j = 0; j < 4; j++) bb[j] = sS[(c0 + j) * 65 + n];
#pragma unroll
        for (int i = 0; i < 4; i++)
#pragma unroll
            for (int j = 0; j < 4; j++) o[i][j] += a[i] * bb[j];
    }
#pragma unroll
    for (int i = 0; i < 4; i++) {
        int l = r0 + i;
        size_t tok = (size_t)(tokb + l);
        float eA = expf(sacum[l]);
#pragma unroll
        for (int j = 0; j < 4; j++) {
            int p = c0 + j;
            int dcol = h * 64 + p;
            float yv = gYdiag[sbase + l * 64 + p] + o[i][j] * eA;
            float zv = gProj[tok * PROJN + 1024 + dcol];
            float sig = 1.f / (1.f + expf(-zv));
            float y = yv * (zv * sig);
            __half hh = __float2half(y);
            gYaHi[tok * DMOD + dcol] = hh;
            gYaLo[tok * DMOD + dcol] = __float2half((y - __half2float(hh)) * LO_SCALE);
        }
    }
}

// ---------------------------------------------------------------------------
extern "C" void kernel_launch(void* const* d_in, const int* in_sizes, int n_in,
                              void* d_out, int out_size) {
    const float* x     = (const float*)d_in[0];
    const float* W_in  = (const float*)d_in[1];
    const float* W_dt  = (const float*)d_in[2];
    const float* b_dt  = (const float*)d_in[3];
    const float* W_B   = (const float*)d_in[4];
    const float* W_C   = (const float*)d_in[5];
    const float* W_out = (const float*)d_in[6];
    const float* A_log = (const float*)d_in[7];
    float* out = (float*)d_out;

    void *pProj;
    cudaGetSymbolAddress(&pProj, gProj);
    void *pXhi, *pXlo, *pWc, *pWo, *pYaH, *pYaL;
    cudaGetSymbolAddress(&pXhi, gXhi); cudaGetSymbolAddress(&pXlo, gXlo);
    cudaGetSymbolAddress(&pWc, gWcat); cudaGetSymbolAddress(&pWo, gWo);
    cudaGetSymbolAddress(&pYaH, gYaHi); cudaGetSymbolAddress(&pYaL, gYaLo);

    cudaFuncSetAttribute(gemm_mma, cudaFuncAttributeMaxDynamicSharedMemorySize, GEMM_SMEM);
    const int P1_SHMEM = 3 * 64 * 65 * (int)sizeof(float);
    cudaFuncSetAttribute(ssd_pass1, cudaFuncAttributeMaxDynamicSharedMemorySize, P1_SHMEM);

    // #0: conversions
    cvt_all<<<S_TOT / 256, 256>>>(x, W_in, W_B, W_C, W_dt, W_out);

    // #1: combined projection GEMM [8192 x 4224 x 1024] -> gProj
    gemm_mma<<<dim3(PROJN / 128, NTOK / 128), 256, GEMM_SMEM>>>(
        (const __half*)pXhi, (const __half*)pXlo, (const __half*)pWc,
        (float*)pProj, NTOK, PROJN, DMOD);

    // #2-#4
    ssd_pass1<<<NTILE, 256, P1_SHMEM>>>(A_log, b_dt);
    scan_kernel<<<512, 256>>>(out);
    ssd_pass2<<<NTILE, 256>>>(A_log, b_dt);

    // #5: y = Yact @ W_out^T -> d_out
    gemm_mma<<<dim3(DMOD / 128, NTOK / 128), 256, GEMM_SMEM>>>(
        (const __half*)pYaH, (const __half*)pYaL, (const __half*)pWo,
        out, NTOK, DMOD, DMOD);
}

// round 8
// speedup vs baseline: 1.5484x; 1.0577x over previous
#include <cuda_runtime.h>
#include <cuda_fp16.h>
#include <math.h>
#include <stdint.h>

// ---------------------------------------------------------------------------
// Shapes: b=2, L=4096, d=1024, h=16, n=p=64, chunk=64 -> tokens 8192, tiles 2048
// Output: y (8388608 f32) then final_state (131072 f32)
// ---------------------------------------------------------------------------
#define NTOK   8192
#define DMOD   1024
#define NHEADS 16
#define NTILE  2048
#define Y_ELEMS 8388608
#define PROJN  4224    // 2048 (xz) + 1024 (B) + 1024 (C) + 16 (dt) + 112 pad

#define LO_SCALE     2048.0f
#define LO_INV_SCALE (1.0f / 2048.0f)

// fp32 scratch
__device__ float gProj[NTOK * PROJN];
__device__ float gStates[NTILE * 4096];
__device__ float gStateIn[NTILE * 4096];
__device__ float gAlast[NTILE];
__device__ float gAcum[NTILE * 64];

// fp16 operand scratch
__device__ __half gXhi[NTOK * DMOD], gXlo[NTOK * DMOD];     // lo pre-scaled
__device__ __half gWcat[PROJN * DMOD];
__device__ __half gWo[DMOD * DMOD];
__device__ __half gYaHi[NTOK * DMOD], gYaLo[NTOK * DMOD];

// ---------------------------------------------------------------------------
// PTX helpers
// ---------------------------------------------------------------------------
__device__ __forceinline__ uint32_t smem_u32(const void* p) {
    uint32_t a;
    asm("{ .reg .u64 t; cvta.to.shared.u64 t, %1; cvt.u32.u64 %0, t; }" : "=r"(a) : "l"(p));
    return a;
}
#define SW128(o) ((o) ^ (((o) >> 3) & 0x70))

__device__ __forceinline__ void cp16(uint32_t dst, const void* src) {
    asm volatile("cp.async.cg.shared.global [%0], [%1], 16;\n" :: "r"(dst), "l"(src));
}
__device__ __forceinline__ void cp_commit() { asm volatile("cp.async.commit_group;\n" ::: "memory"); }
template <int N> __device__ __forceinline__ void cp_wait() {
    asm volatile("cp.async.wait_group %0;\n" :: "n"(N) : "memory");
}
__device__ __forceinline__ void ldsm4(uint32_t* r, uint32_t addr) {
    asm volatile("ldmatrix.sync.aligned.m8n8.x4.shared.b16 {%0,%1,%2,%3}, [%4];"
                 : "=r"(r[0]), "=r"(r[1]), "=r"(r[2]), "=r"(r[3]) : "r"(addr));
}
__device__ __forceinline__ void mma_f32(float* d, const uint32_t* a, const uint32_t* b) {
    asm volatile("mma.sync.aligned.m16n8k16.row.col.f32.f16.f16.f32 "
                 "{%0,%1,%2,%3}, {%4,%5,%6,%7}, {%8,%9}, {%0,%1,%2,%3};"
                 : "+f"(d[0]), "+f"(d[1]), "+f"(d[2]), "+f"(d[3])
                 : "r"(a[0]), "r"(a[1]), "r"(a[2]), "r"(a[3]), "r"(b[0]), "r"(b[1]));
}
__device__ __forceinline__ void mma_f16(uint32_t* d, const uint32_t* a, const uint32_t* b) {
    asm volatile("mma.sync.aligned.m16n8k16.row.col.f16.f16.f16.f16 "
                 "{%0,%1}, {%2,%3,%4,%5}, {%6,%7}, {%0,%1};"
                 : "+r"(d[0]), "+r"(d[1])
                 : "r"(a[0]), "r"(a[1]), "r"(a[2]), "r"(a[3]), "r"(b[0]), "r"(b[1]));
}

// ---------------------------------------------------------------------------
// Big GEMM (unchanged from R7): C = (Ahi + Alo/2048) @ B^T
// ---------------------------------------------------------------------------
#define OF_AH 0
#define OF_AL 16384
#define OF_B  32768
#define STG   49152
#define GEMM_SMEM (2 * STG)

__device__ __forceinline__ void load_rows(uint32_t smem_dst, const __half* g,
                                          int row0, int K, int k0, int t) {
#pragma unroll
    for (int it = 0; it < 4; it++) {
        int p = t + it * 256;
        int r = p >> 3, cc = p & 7;
        uint32_t off = (uint32_t)(r * 128 + cc * 16);
        cp16(smem_dst + SW128(off), g + (size_t)(row0 + r) * K + k0 + cc * 8);
    }
}

__global__ __launch_bounds__(256)
void gemm_mma(const __half* __restrict__ Ah, const __half* __restrict__ Al,
              const __half* __restrict__ B, float* __restrict__ C,
              int M, int N, int K) {
    extern __shared__ char smem[];
    const uint32_t sb = smem_u32(smem);
    const int t = threadIdx.x;
    const int wid = t >> 5, lane = t & 31;
    const int bm = blockIdx.y * 128;
    const int bn = blockIdx.x * 128;
    const int wm = (wid & 3) * 32;
    const int wn = (wid >> 2) * 64;
    const int nch = K >> 6;

    float    acc[2][8][4];
    uint32_t accl[2][8][2];
#pragma unroll
    for (int i = 0; i < 2; i++)
#pragma unroll
        for (int j = 0; j < 8; j++) {
#pragma unroll
            for (int k = 0; k < 4; k++) acc[i][j][k] = 0.f;
            accl[i][j][0] = 0u; accl[i][j][1] = 0u;
        }

    load_rows(sb + OF_AH, Ah, bm, K, 0, t);
    load_rows(sb + OF_AL, Al, bm, K, 0, t);
    load_rows(sb + OF_B,  B,  bn, K, 0, t);
    cp_commit();

    const int ra = (lane & 15);
    const uint32_t ca = (uint32_t)((lane >> 4) << 4);
    const int rb = (lane & 7) + (((lane >> 4) & 1) << 3);
    const uint32_t cb = (uint32_t)(((lane >> 3) & 1) << 4);

    for (int i = 0; i < nch; i++) {
        if (i + 1 < nch) {
            uint32_t st2 = sb + ((i + 1) & 1) * STG;
            int k0 = (i + 1) * 64;
            load_rows(st2 + OF_AH, Ah, bm, K, k0, t);
            load_rows(st2 + OF_AL, Al, bm, K, k0, t);
            load_rows(st2 + OF_B,  B,  bn, K, k0, t);
            cp_commit();
            cp_wait<1>();
        } else {
            cp_wait<0>();
        }
        __syncthreads();
        const uint32_t st = sb + (i & 1) * STG;

#pragma unroll
        for (int kk = 0; kk < 4; kk++) {
            uint32_t ah[2][4], al[2][4], bf[4][4];
#pragma unroll
            for (int mi = 0; mi < 2; mi++) {
                int row = wm + mi * 16 + ra;
                uint32_t off = (uint32_t)(row * 128 + kk * 32) + ca;
                ldsm4(ah[mi], st + OF_AH + SW128(off));
                ldsm4(al[mi], st + OF_AL + SW128(off));
            }
#pragma unroll
            for (int nb = 0; nb < 4; nb++) {
                int rown = wn + nb * 16 + rb;
                uint32_t off = (uint32_t)(rown * 128 + kk * 32) + cb;
                ldsm4(bf[nb], st + OF_B + SW128(off));
            }
#pragma unroll
            for (int mi = 0; mi < 2; mi++)
#pragma unroll
                for (int ni = 0; ni < 8; ni++) {
                    const uint32_t* b2 = &bf[ni >> 1][(ni & 1) * 2];
                    mma_f32(acc[mi][ni], ah[mi], b2);
                    mma_f16(accl[mi][ni], al[mi], b2);
                }
        }
        __syncthreads();
    }

#pragma unroll
    for (int mi = 0; mi < 2; mi++) {
        int r0 = bm + wm + mi * 16 + (lane >> 2);
#pragma unroll
        for (int ni = 0; ni < 8; ni++) {
            int c0 = bn + wn + ni * 8 + ((lane & 3) << 1);
            __half2 l01 = *(__half2*)&accl[mi][ni][0];
            __half2 l23 = *(__half2*)&accl[mi][ni][1];
            float2 v0 = make_float2(acc[mi][ni][0] + __half2float(l01.x) * LO_INV_SCALE,
                                    acc[mi][ni][1] + __half2float(l01.y) * LO_INV_SCALE);
            float2 v1 = make_float2(acc[mi][ni][2] + __half2float(l23.x) * LO_INV_SCALE,
                                    acc[mi][ni][3] + __half2float(l23.y) * LO_INV_SCALE);
            *(float2*)&C[(size_t)r0 * N + c0] = v0;
            *(float2*)&C[(size_t)(r0 + 8) * N + c0] = v1;
        }
    }
}

// ---------------------------------------------------------------------------
// Conversions (unchanged)
// ---------------------------------------------------------------------------
__device__ __forceinline__ void cvt_hl(const float* __restrict__ src,
                                       __half* __restrict__ hi,
                                       __half* __restrict__ lo, int i) {
    float4 v = ((const float4*)src)[i];
    __half h0 = __float2half(v.x), h1 = __float2half(v.y);
    __half h2 = __float2half(v.z), h3 = __float2half(v.w);
    __half2* hp = (__half2*)hi;
    __half2* lp = (__half2*)lo;
    hp[2 * i]     = __half2(h0, h1);
    hp[2 * i + 1] = __half2(h2, h3);
    lp[2 * i]     = __half2(__float2half((v.x - __half2float(h0)) * LO_SCALE),
                            __float2half((v.y - __half2float(h1)) * LO_SCALE));
    lp[2 * i + 1] = __half2(__float2half((v.z - __half2float(h2)) * LO_SCALE),
                            __float2half((v.w - __half2float(h3)) * LO_SCALE));
}
__device__ __forceinline__ void cvt_s(const float* __restrict__ src,
                                      __half* __restrict__ dst, int i) {
    float4 v = ((const float4*)src)[i];
    __half2* dp = (__half2*)dst;
    dp[2 * i]     = __half2(__float2half(v.x), __float2half(v.y));
    dp[2 * i + 1] = __half2(__float2half(v.z), __float2half(v.w));
}

#define S_X   2097152
#define S_WIN 524288
#define S_WB  262144
#define S_WC  262144
#define S_WDT 4096
#define S_WO  262144
#define S_TOT (S_X + S_WIN + S_WB + S_WC + S_WDT + S_WO)

__global__ __launch_bounds__(256)
void cvt_all(const float* __restrict__ x, const float* __restrict__ Win,
             const float* __restrict__ WB, const float* __restrict__ WC,
             const float* __restrict__ Wdt, const float* __restrict__ Wout) {
    int i = blockIdx.x * 256 + threadIdx.x;
    if (i < S_X) { cvt_hl(x, gXhi, gXlo, i); return; }
    i -= S_X;
    if (i < S_WIN) { cvt_s(Win, gWcat, i); return; }
    i -= S_WIN;
    if (i < S_WB) { cvt_s(WB, gWcat + 2048 * DMOD, i); return; }
    i -= S_WB;
    if (i < S_WC) { cvt_s(WC, gWcat + 3072 * DMOD, i); return; }
    i -= S_WC;
    if (i < S_WDT) { cvt_s(Wdt, gWcat + 4096 * DMOD, i); return; }
    i -= S_WDT;
    if (i < S_WO) { cvt_s(Wout, gWo, i); return; }
}

// ---------------------------------------------------------------------------
// SSD helpers: stage fp32 rows into padded smem; transposed / direct fp16 tiles
// All fp16 tiles: 64 rows x 128 bytes, SW128-swizzled (same as big GEMM).
// ---------------------------------------------------------------------------
__device__ __forceinline__ void stage_rows(float* sStage, const float* __restrict__ src0,
                                           int stride, int t, const float* scale /*per-row or null*/) {
    int l = t >> 1, cbase = (t & 1) * 32;
    const float4* src = (const float4*)(src0 + (size_t)l * stride + cbase);
    float s = scale ? scale[l] : 1.f;
#pragma unroll
    for (int j = 0; j < 8; j++) {
        float4 v = src[j];
        float* d = &sStage[l * 65 + cbase + j * 4];
        d[0] = v.x * s; d[1] = v.y * s; d[2] = v.z * s; d[3] = v.w * s;
    }
}
// write fp16 tile row-major [row][64] from stage (direct, no transpose)
__device__ __forceinline__ void tile_direct(char* tile, const float* sStage, int t) {
    int l = t >> 1, cbase = (t & 1) * 32;
#pragma unroll
    for (int j = 0; j < 16; j++) {
        int c = cbase + 2 * j;
        __half2 hv = __floats2half2_rn(sStage[l * 65 + c], sStage[l * 65 + c + 1]);
        *(__half2*)(tile + SW128((uint32_t)(l * 128 + c * 2))) = hv;
    }
}
// write fp16 tile transposed: tile[o][k] = sStage[k][o] (* optional per-k scale)
__device__ __forceinline__ void tile_transpose(char* tile, const float* sStage, int t,
                                               const float* kscale /*per-k or null*/) {
    int o = t >> 1, kbase = (t & 1) * 32;
#pragma unroll
    for (int j = 0; j < 16; j++) {
        int k0 = kbase + 2 * j;
        float v0 = sStage[k0 * 65 + o];
        float v1 = sStage[(k0 + 1) * 65 + o];
        if (kscale) { v0 *= kscale[k0]; v1 *= kscale[k0 + 1]; }
        *(__half2*)(tile + SW128((uint32_t)(o * 128 + k0 * 2))) = __floats2half2_rn(v0, v1);
    }
}
// one 64x64x64 fp16 MMA: D[m][n] += A[m][k] * Bop[n][k]; 4 warps, warp w rows w*16..
__device__ __forceinline__ void tile_mma(float acc[8][4], uint32_t aBase, uint32_t bBase,
                                         int wm, int lane) {
    const int ra = (lane & 15);
    const uint32_t ca = (uint32_t)((lane >> 4) << 4);
    const int rb = (lane & 7) + (((lane >> 4) & 1) << 3);
    const uint32_t cb = (uint32_t)(((lane >> 3) & 1) << 4);
#pragma unroll
    for (int kk = 0; kk < 4; kk++) {
        uint32_t a[4], bf[4][4];
        ldsm4(a, aBase + SW128((uint32_t)((wm + ra) * 128 + kk * 32) + ca));
#pragma unroll
        for (int nb = 0; nb < 4; nb++)
            ldsm4(bf[nb], bBase + SW128((uint32_t)((nb * 16 + rb) * 128 + kk * 32) + cb));
#pragma unroll
        for (int ni = 0; ni < 8; ni++)
            mma_f32(acc[ni], a, &bf[ni >> 1][(ni & 1) * 2]);
    }
}

// ---------------------------------------------------------------------------
// SSD pass 1 (tensor): states[p][n] = sum_l X[l][p]*dt[l]*dec[l] * B[l][n]
// 128 threads per tile. Also writes gAcum + gAlast.
// dyn smem: [0,16640) stage fp32 | 16896 XTdec | 25088 BT | 33280 dt/acum/dec
// ---------------------------------------------------------------------------
#define P1_SMEM (33280 + 768)
__global__ __launch_bounds__(128)
void ssd_pass1(const float* __restrict__ Alog, const float* __restrict__ bdt) {
    extern __shared__ char sm[];
    float* sStage = (float*)sm;
    char*  sXT = sm + 16896;
    char*  sBT = sm + 25088;
    float* sdt   = (float*)(sm + 33280);
    float* sacum = (float*)(sm + 33280 + 256);
    float* sdec  = (float*)(sm + 33280 + 512);

    const int tile = blockIdx.x;
    const int h = tile & 15;
    const int c = (tile >> 4) & 63;
    const int b = tile >> 10;
    const int t = threadIdx.x;
    const int lane = t & 31, w = t >> 5;
    const int tokb = b * 4096 + c * 64;

    if (t < 64) {
        float v = gProj[(size_t)(tokb + t) * PROJN + 4096 + h] + bdt[h];
        sdt[t] = (v > 20.f) ? v : log1pf(expf(v));
    }
    __syncthreads();
    if (t == 0) {
        float expA = expf(Alog[h]);
        float run = 0.f;
        for (int l = 0; l < 64; l++) { run -= expA * sdt[l]; sacum[l] = run; }
        gAlast[tile] = run;
    }
    __syncthreads();
    if (t < 64) {
        sdec[t] = __expf(sacum[63] - sacum[t]);
        gAcum[tile * 64 + t] = sacum[t];
    }
    __syncthreads();

    // B -> BT[n][l]
    stage_rows(sStage, gProj + (size_t)tokb * PROJN + 2048 + h * 64, PROJN, t, nullptr);
    __syncthreads();
    tile_transpose(sBT, sStage, t, nullptr);
    __syncthreads();
    // X*dt -> stage; XTdec[p][l] = X[l][p]*dt[l]*dec[l]
    stage_rows(sStage, gProj + (size_t)tokb * PROJN + h * 64, PROJN, t, sdt);
    __syncthreads();
    tile_transpose(sXT, sStage, t, sdec);
    __syncthreads();

    float acc[8][4];
#pragma unroll
    for (int i = 0; i < 8; i++)
#pragma unroll
        for (int k = 0; k < 4; k++) acc[i][k] = 0.f;
    tile_mma(acc, smem_u32(sXT), smem_u32(sBT), w * 16, lane);

    size_t obase = (size_t)tile * 4096;
    int r = w * 16 + (lane >> 2);
#pragma unroll
    for (int ni = 0; ni < 8; ni++) {
        int cc = ni * 8 + ((lane & 3) << 1);
        *(float2*)&gStates[obase + r * 64 + cc]       = make_float2(acc[ni][0], acc[ni][1]);
        *(float2*)&gStates[obase + (r + 8) * 64 + cc] = make_float2(acc[ni][2], acc[ni][3]);
    }
}

// ---------------------------------------------------------------------------
// Chunk-level scan (unchanged)
// ---------------------------------------------------------------------------
__global__ __launch_bounds__(256)
void scan_kernel(float* __restrict__ out_final) {
    const int bh = blockIdx.x >> 4;
    const int b = bh >> 4, h = bh & 15;
    const int e = ((blockIdx.x & 15) << 8) | threadIdx.x;
    float S = 0.f;
#pragma unroll 4
    for (int c = 0; c < 64; c++) {
        int tile = (b * 64 + c) * 16 + h;
        float d = expf(gAlast[tile]);
        size_t base = (size_t)tile * 4096 + e;
        gStateIn[base] = S;
        S = S * d + gStates[base];
    }
    out_final[(size_t)Y_ELEMS + (size_t)(b * 16 + h) * 4096 + e] = S;
}

// ---------------------------------------------------------------------------
// SSD pass 2 (tensor): G = C.B^T (mask/exp) ; Y = G.X^T + eA*(C.S^T); gate; hi/lo out
// 128 threads per tile.
// dyn smem: 0 stage | 16896 C16 | 25088 B16 | 33280 XT | 41472 S16 | 49664 G16
//           | 57856 dt/acum/eA
// ---------------------------------------------------------------------------
#define P2_SMEM (57856 + 768)
__global__ __launch_bounds__(128)
void ssd_pass2(const float* __restrict__ bdt) {
    extern __shared__ char sm[];
    float* sStage = (float*)sm;
    char*  sC16 = sm + 16896;
    char*  sB16 = sm + 25088;
    char*  sXT  = sm + 33280;
    char*  sS16 = sm + 41472;
    char*  sG16 = sm + 49664;
    float* sdt   = (float*)(sm + 57856);
    float* sacum = (float*)(sm + 57856 + 256);
    float* seA   = (float*)(sm + 57856 + 512);

    const int tile = blockIdx.x;
    const int h = tile & 15;
    const int c = (tile >> 4) & 63;
    const int b = tile >> 10;
    const int t = threadIdx.x;
    const int lane = t & 31, w = t >> 5;
    const int tokb = b * 4096 + c * 64;

    if (t < 64) {
        float v = gProj[(size_t)(tokb + t) * PROJN + 4096 + h] + bdt[h];
        sdt[t] = (v > 20.f) ? v : log1pf(expf(v));
        float ac = gAcum[tile * 64 + t];
        sacum[t] = ac;
        seA[t] = __expf(ac);
    }
    __syncthreads();

    // C16 (direct), B16 (direct), S16 (direct), XT (transpose of X*dt)
    stage_rows(sStage, gProj + (size_t)tokb * PROJN + 3072 + h * 64, PROJN, t, nullptr);
    __syncthreads();
    tile_direct(sC16, sStage, t);
    __syncthreads();
    stage_rows(sStage, gProj + (size_t)tokb * PROJN + 2048 + h * 64, PROJN, t, nullptr);
    __syncthreads();
    tile_direct(sB16, sStage, t);
    __syncthreads();
    stage_rows(sStage, gStateIn + (size_t)tile * 4096, 64, t, nullptr);
    __syncthreads();
    tile_direct(sS16, sStage, t);
    __syncthreads();
    stage_rows(sStage, gProj + (size_t)tokb * PROJN + h * 64, PROJN, t, sdt);
    __syncthreads();
    tile_transpose(sXT, sStage, t, nullptr);
    __syncthreads();

    // GEMM1: G = C . B^T  (f32 acc)
    float g[8][4];
#pragma unroll
    for (int i = 0; i < 8; i++)
#pragma unroll
        for (int k = 0; k < 4; k++) g[i][k] = 0.f;
    tile_mma(g, smem_u32(sC16), smem_u32(sB16), w * 16, lane);

    // mask + exp scale, store G16
    {
        int r0 = w * 16 + (lane >> 2);
        int r1 = r0 + 8;
        float a0 = sacum[r0], a1 = sacum[r1];
#pragma unroll
        for (int ni = 0; ni < 8; ni++) {
            int s0 = ni * 8 + ((lane & 3) << 1);
            int s1 = s0 + 1;
            float v00 = (s0 <= r0) ? g[ni][0] * __expf(a0 - sacum[s0]) : 0.f;
            float v01 = (s1 <= r0) ? g[ni][1] * __expf(a0 - sacum[s1]) : 0.f;
            float v10 = (s0 <= r1) ? g[ni][2] * __expf(a1 - sacum[s0]) : 0.f;
            float v11 = (s1 <= r1) ? g[ni][3] * __expf(a1 - sacum[s1]) : 0.f;
            *(__half2*)(sG16 + SW128((uint32_t)(r0 * 128 + s0 * 2))) = __floats2half2_rn(v00, v01);
            *(__half2*)(sG16 + SW128((uint32_t)(r1 * 128 + s0 * 2))) = __floats2half2_rn(v10, v11);
        }
    }
    __syncthreads();

    // GEMM2: Ydiag = G . XT^T ; GEMM3: Yoff = C . S^T
    float accY[8][4], accO[8][4];
#pragma unroll
    for (int i = 0; i < 8; i++)
#pragma unroll
        for (int k = 0; k < 4; k++) { accY[i][k] = 0.f; accO[i][k] = 0.f; }
    tile_mma(accY, smem_u32(sG16), smem_u32(sXT), w * 16, lane);
    tile_mma(accO, smem_u32(sC16), smem_u32(sS16), w * 16, lane);

    // epilogue: y = (Ydiag + eA[l]*Yoff) * silu(z); write fp16 hi + scaled lo
    {
        int r0 = w * 16 + (lane >> 2);
#pragma unroll
        for (int rr = 0; rr < 2; rr++) {
            int l = r0 + rr * 8;
            float eA = seA[l];
            size_t tok = (size_t)(tokb + l);
            const float* zrow = gProj + tok * PROJN + 1024 + h * 64;
            __half2* hiRow = (__half2*)(gYaHi + tok * DMOD + h * 64);
            __half2* loRow = (__half2*)(gYaLo + tok * DMOD + h * 64);
#pragma unroll
            for (int ni = 0; ni < 8; ni++) {
                int p = ni * 8 + ((lane & 3) << 1);
                float y0 = accY[ni][rr * 2 + 0] + eA * accO[ni][rr * 2 + 0];
                float y1 = accY[ni][rr * 2 + 1] + eA * accO[ni][rr * 2 + 1];
                float2 z = *(const float2*)&zrow[p];
                float s0 = 1.f / (1.f + __expf(-z.x));
                float s1 = 1.f / (1.f + __expf(-z.y));
                y0 *= z.x * s0;
                y1 *= z.y * s1;
                __half h0 = __float2half(y0), h1 = __float2half(y1);
                hiRow[p >> 1] = __half2(h0, h1);
                loRow[p >> 1] = __half2(__float2half((y0 - __half2float(h0)) * LO_SCALE),
                                        __float2half((y1 - __half2float(h1)) * LO_SCALE));
            }
        }
    }
}

// ---------------------------------------------------------------------------
extern "C" void kernel_launch(void* const* d_in, const int* in_sizes, int n_in,
                              void* d_out, int out_size) {
    const float* x     = (const float*)d_in[0];
    const float* W_in  = (const float*)d_in[1];
    const float* W_dt  = (const float*)d_in[2];
    const float* b_dt  = (const float*)d_in[3];
    const float* W_B   = (const float*)d_in[4];
    const float* W_C   = (const float*)d_in[5];
    const float* W_out = (const float*)d_in[6];
    const float* A_log = (const float*)d_in[7];
    float* out = (float*)d_out;

    void *pProj;
    cudaGetSymbolAddress(&pProj, gProj);
    void *pXhi, *pXlo, *pWc, *pWo, *pYaH, *pYaL;
    cudaGetSymbolAddress(&pXhi, gXhi); cudaGetSymbolAddress(&pXlo, gXlo);
    cudaGetSymbolAddress(&pWc, gWcat); cudaGetSymbolAddress(&pWo, gWo);
    cudaGetSymbolAddress(&pYaH, gYaHi); cudaGetSymbolAddress(&pYaL, gYaLo);

    cudaFuncSetAttribute(gemm_mma, cudaFuncAttributeMaxDynamicSharedMemorySize, GEMM_SMEM);
    cudaFuncSetAttribute(ssd_pass2, cudaFuncAttributeMaxDynamicSharedMemorySize, P2_SMEM);

    // #0: conversions
    cvt_all<<<S_TOT / 256, 256>>>(x, W_in, W_B, W_C, W_dt, W_out);

    // #1: combined projection GEMM
    gemm_mma<<<dim3(PROJN / 128, NTOK / 128), 256, GEMM_SMEM>>>(
        (const __half*)pXhi, (const __half*)pXlo, (const __half*)pWc,
        (float*)pProj, NTOK, PROJN, DMOD);

    // #2-#4
    ssd_pass1<<<NTILE, 128, P1_SMEM>>>(A_log, b_dt);
    scan_kernel<<<512, 256>>>(out);
    ssd_pass2<<<NTILE, 128, P2_SMEM>>>(b_dt);

    // #5: output GEMM
    gemm_mma<<<dim3(DMOD / 128, NTOK / 128), 256, GEMM_SMEM>>>(
        (const __half*)pYaH, (const __half*)pYaL, (const __half*)pWo,
        out, NTOK, DMOD, DMOD);
}

// round 9
// speedup vs baseline: 1.9480x; 1.2581x over previous
#include <cuda_runtime.h>
#include <cuda_fp16.h>
#include <math.h>
#include <stdint.h>

#define NTOK   8192
#define DMOD   1024
#define NHEADS 16
#define NTILE  2048
#define Y_ELEMS 8388608
#define PROJN  4224

#define LO_SCALE     2048.0f
#define LO_INV_SCALE (1.0f / 2048.0f)

// fp32 scratch
__device__ float gProj[NTOK * PROJN];
__device__ float gStates[NTILE * 4096];
__device__ float gStateIn[NTILE * 4096];
__device__ float gAlast[NTILE];
__device__ float gAcum[NTILE * 64];

// fp16 operand scratch
__device__ __half gXh[NTOK * DMOD];
__device__ __half gWcat[PROJN * DMOD];
__device__ __half gWo[DMOD * DMOD];
__device__ __half gYa[NTOK * DMOD];

// ---------------------------------------------------------------------------
// PTX helpers
// ---------------------------------------------------------------------------
__device__ __forceinline__ uint32_t smem_u32(const void* p) {
    uint32_t a;
    asm("{ .reg .u64 t; cvta.to.shared.u64 t, %1; cvt.u32.u64 %0, t; }" : "=r"(a) : "l"(p));
    return a;
}
#define SW128(o) ((o) ^ (((o) >> 3) & 0x70))

__device__ __forceinline__ void cp16(uint32_t dst, const void* src) {
    asm volatile("cp.async.cg.shared.global [%0], [%1], 16;\n" :: "r"(dst), "l"(src));
}
__device__ __forceinline__ void cp_commit() { asm volatile("cp.async.commit_group;\n" ::: "memory"); }
template <int N> __device__ __forceinline__ void cp_wait() {
    asm volatile("cp.async.wait_group %0;\n" :: "n"(N) : "memory");
}
__device__ __forceinline__ void ldsm4(uint32_t* r, uint32_t addr) {
    asm volatile("ldmatrix.sync.aligned.m8n8.x4.shared.b16 {%0,%1,%2,%3}, [%4];"
                 : "=r"(r[0]), "=r"(r[1]), "=r"(r[2]), "=r"(r[3]) : "r"(addr));
}
__device__ __forceinline__ void mma_f32(float* d, const uint32_t* a, const uint32_t* b) {
    asm volatile("mma.sync.aligned.m16n8k16.row.col.f32.f16.f16.f32 "
                 "{%0,%1,%2,%3}, {%4,%5,%6,%7}, {%8,%9}, {%0,%1,%2,%3};"
                 : "+f"(d[0]), "+f"(d[1]), "+f"(d[2]), "+f"(d[3])
                 : "r"(a[0]), "r"(a[1]), "r"(a[2]), "r"(a[3]), "r"(b[0]), "r"(b[1]));
}

// ---------------------------------------------------------------------------
// Big GEMM, single-term fp16: C[M,N] = A @ B^T, f32 accum.
// CTA 128x128, 256 thr, 8 warps (4m x 2n, warp tile 32x64), k64 double buffer.
// ---------------------------------------------------------------------------
#define OF_A 0
#define OF_B 16384
#define STG  32768
#define GEMM_SMEM (2 * STG)   // 65536

__device__ __forceinline__ void load_rows(uint32_t smem_dst, const __half* g,
                                          int row0, int K, int k0, int t) {
#pragma unroll
    for (int it = 0; it < 4; it++) {
        int p = t + it * 256;
        int r = p >> 3, cc = p & 7;
        uint32_t off = (uint32_t)(r * 128 + cc * 16);
        cp16(smem_dst + SW128(off), g + (size_t)(row0 + r) * K + k0 + cc * 8);
    }
}

__global__ __launch_bounds__(256)
void gemm_mma(const __half* __restrict__ A, const __half* __restrict__ B,
              float* __restrict__ C, int M, int N, int K) {
    extern __shared__ char smem[];
    const uint32_t sb = smem_u32(smem);
    const int t = threadIdx.x;
    const int wid = t >> 5, lane = t & 31;
    const int bm = blockIdx.y * 128;
    const int bn = blockIdx.x * 128;
    const int wm = (wid & 3) * 32;
    const int wn = (wid >> 2) * 64;
    const int nch = K >> 6;

    float acc[2][8][4];
#pragma unroll
    for (int i = 0; i < 2; i++)
#pragma unroll
        for (int j = 0; j < 8; j++)
#pragma unroll
            for (int k = 0; k < 4; k++) acc[i][j][k] = 0.f;

    load_rows(sb + OF_A, A, bm, K, 0, t);
    load_rows(sb + OF_B, B, bn, K, 0, t);
    cp_commit();

    const int ra = (lane & 15);
    const uint32_t ca = (uint32_t)((lane >> 4) << 4);
    const int rb = (lane & 7) + (((lane >> 4) & 1) << 3);
    const uint32_t cb = (uint32_t)(((lane >> 3) & 1) << 4);

    for (int i = 0; i < nch; i++) {
        if (i + 1 < nch) {
            uint32_t st2 = sb + ((i + 1) & 1) * STG;
            int k0 = (i + 1) * 64;
            load_rows(st2 + OF_A, A, bm, K, k0, t);
            load_rows(st2 + OF_B, B, bn, K, k0, t);
            cp_commit();
            cp_wait<1>();
        } else {
            cp_wait<0>();
        }
        __syncthreads();
        const uint32_t st = sb + (i & 1) * STG;

#pragma unroll
        for (int kk = 0; kk < 4; kk++) {
            uint32_t af[2][4], bf[4][4];
#pragma unroll
            for (int mi = 0; mi < 2; mi++) {
                int row = wm + mi * 16 + ra;
                ldsm4(af[mi], st + OF_A + SW128((uint32_t)(row * 128 + kk * 32) + ca));
            }
#pragma unroll
            for (int nb = 0; nb < 4; nb++) {
                int rown = wn + nb * 16 + rb;
                ldsm4(bf[nb], st + OF_B + SW128((uint32_t)(rown * 128 + kk * 32) + cb));
            }
#pragma unroll
            for (int mi = 0; mi < 2; mi++)
#pragma unroll
                for (int ni = 0; ni < 8; ni++)
                    mma_f32(acc[mi][ni], af[mi], &bf[ni >> 1][(ni & 1) * 2]);
        }
        __syncthreads();
    }

#pragma unroll
    for (int mi = 0; mi < 2; mi++) {
        int r0 = bm + wm + mi * 16 + (lane >> 2);
#pragma unroll
        for (int ni = 0; ni < 8; ni++) {
            int c0 = bn + wn + ni * 8 + ((lane & 3) << 1);
            *(float2*)&C[(size_t)r0 * N + c0] = make_float2(acc[mi][ni][0], acc[mi][ni][1]);
            *(float2*)&C[(size_t)(r0 + 8) * N + c0] = make_float2(acc[mi][ni][2], acc[mi][ni][3]);
        }
    }
}

// ---------------------------------------------------------------------------
// Conversions: everything plain fp16 now (one launch)
// ---------------------------------------------------------------------------
__device__ __forceinline__ void cvt_s(const float* __restrict__ src,
                                      __half* __restrict__ dst, int i) {
    float4 v = ((const float4*)src)[i];
    __half2* dp = (__half2*)dst;
    dp[2 * i]     = __half2(__float2half(v.x), __float2half(v.y));
    dp[2 * i + 1] = __half2(__float2half(v.z), __float2half(v.w));
}

#define S_X   2097152
#define S_WIN 524288
#define S_WB  262144
#define S_WC  262144
#define S_WDT 4096
#define S_WO  262144
#define S_TOT (S_X + S_WIN + S_WB + S_WC + S_WDT + S_WO)

__global__ __launch_bounds__(256)
void cvt_all(const float* __restrict__ x, const float* __restrict__ Win,
             const float* __restrict__ WB, const float* __restrict__ WC,
             const float* __restrict__ Wdt, const float* __restrict__ Wout) {
    int i = blockIdx.x * 256 + threadIdx.x;
    if (i < S_X) { cvt_s(x, gXh, i); return; }
    i -= S_X;
    if (i < S_WIN) { cvt_s(Win, gWcat, i); return; }
    i -= S_WIN;
    if (i < S_WB) { cvt_s(WB, gWcat + 2048 * DMOD, i); return; }
    i -= S_WB;
    if (i < S_WC) { cvt_s(WC, gWcat + 3072 * DMOD, i); return; }
    i -= S_WC;
    if (i < S_WDT) { cvt_s(Wdt, gWcat + 4096 * DMOD, i); return; }
    i -= S_WDT;
    if (i < S_WO) { cvt_s(Wout, gWo, i); return; }
}

// ---------------------------------------------------------------------------
// SSD hi/lo tile helpers. Tiles: 64 rows x 128B, SW128-swizzled.
// lo tiles hold (v - hi) * 2048.
// ---------------------------------------------------------------------------
__device__ __forceinline__ void stage_rows(float* sStage, const float* __restrict__ src0,
                                           int stride, int t, const float* scale) {
    int l = t >> 1, cbase = (t & 1) * 32;
    const float4* src = (const float4*)(src0 + (size_t)l * stride + cbase);
    float s = scale ? scale[l] : 1.f;
#pragma unroll
    for (int j = 0; j < 8; j++) {
        float4 v = src[j];
        float* d = &sStage[l * 65 + cbase + j * 4];
        d[0] = v.x * s; d[1] = v.y * s; d[2] = v.z * s; d[3] = v.w * s;
    }
}
__device__ __forceinline__ void put_hl(char* tH, char* tL, uint32_t off, float v0, float v1) {
    __half h0 = __float2half(v0), h1 = __float2half(v1);
    *(__half2*)(tH + off) = __half2(h0, h1);
    *(__half2*)(tL + off) = __half2(__float2half((v0 - __half2float(h0)) * LO_SCALE),
                                    __float2half((v1 - __half2float(h1)) * LO_SCALE));
}
__device__ __forceinline__ void tile_direct_hl(char* tH, char* tL, const float* sStage, int t) {
    int l = t >> 1, cbase = (t & 1) * 32;
#pragma unroll
    for (int j = 0; j < 16; j++) {
        int c = cbase + 2 * j;
        put_hl(tH, tL, SW128((uint32_t)(l * 128 + c * 2)),
               sStage[l * 65 + c], sStage[l * 65 + c + 1]);
    }
}
__device__ __forceinline__ void tile_transpose_hl(char* tH, char* tL, const float* sStage,
                                                  int t, const float* kscale) {
    int o = t >> 1, kbase = (t & 1) * 32;
#pragma unroll
    for (int j = 0; j < 16; j++) {
        int k0 = kbase + 2 * j;
        float v0 = sStage[k0 * 65 + o];
        float v1 = sStage[(k0 + 1) * 65 + o];
        if (kscale) { v0 *= kscale[k0]; v1 *= kscale[k0 + 1]; }
        put_hl(tH, tL, SW128((uint32_t)(o * 128 + k0 * 2)), v0, v1);
    }
}
// 3-term 64x64x64 tile GEMM: res = Ah.Bh + (Ah.Bl + Al.Bh)/2048 (accumulated split)
__device__ __forceinline__ void tile_mma_hl(float accH[8][4], float accM[8][4],
                                            uint32_t aH, uint32_t aL,
                                            uint32_t bH, uint32_t bL,
                                            int wm, int lane) {
    const int ra = (lane & 15);
    const uint32_t ca = (uint32_t)((lane >> 4) << 4);
    const int rb = (lane & 7) + (((lane >> 4) & 1) << 3);
    const uint32_t cb = (uint32_t)(((lane >> 3) & 1) << 4);
#pragma unroll
    for (int kk = 0; kk < 4; kk++) {
        uint32_t ah[4], al[4], bh[4][4], bl[4][4];
        uint32_t aoff = SW128((uint32_t)((wm + ra) * 128 + kk * 32) + ca);
        ldsm4(ah, aH + aoff);
        ldsm4(al, aL + aoff);
#pragma unroll
        for (int nb = 0; nb < 4; nb++) {
            uint32_t boff = SW128((uint32_t)((nb * 16 + rb) * 128 + kk * 32) + cb);
            ldsm4(bh[nb], bH + boff);
            ldsm4(bl[nb], bL + boff);
        }
#pragma unroll
        for (int ni = 0; ni < 8; ni++) {
            const uint32_t* b2h = &bh[ni >> 1][(ni & 1) * 2];
            const uint32_t* b2l = &bl[ni >> 1][(ni & 1) * 2];
            mma_f32(accH[ni], ah, b2h);
            mma_f32(accM[ni], ah, b2l);
            mma_f32(accM[ni], al, b2h);
        }
    }
}

// ---------------------------------------------------------------------------
// SSD pass 1: states = (X*dt*dec)^T . B, 3-term. 128 threads.
// smem: stage 16640 | XTh 16640 | XTl 24832 | BTh 33024 | BTl 41216 | sc 49408
// ---------------------------------------------------------------------------
#define P1_SMEM (49408 + 768)
__global__ __launch_bounds__(128)
void ssd_pass1(const float* __restrict__ Alog, const float* __restrict__ bdt) {
    extern __shared__ char sm[];
    float* sStage = (float*)sm;
    char* sXTh = sm + 16640;
    char* sXTl = sm + 24832;
    char* sBTh = sm + 33024;
    char* sBTl = sm + 41216;
    float* sdt   = (float*)(sm + 49408);
    float* sacum = (float*)(sm + 49408 + 256);
    float* sdec  = (float*)(sm + 49408 + 512);

    const int tile = blockIdx.x;
    const int h = tile & 15;
    const int c = (tile >> 4) & 63;
    const int b = tile >> 10;
    const int t = threadIdx.x;
    const int lane = t & 31, w = t >> 5;
    const int tokb = b * 4096 + c * 64;

    if (t < 64) {
        float v = gProj[(size_t)(tokb + t) * PROJN + 4096 + h] + bdt[h];
        sdt[t] = (v > 20.f) ? v : log1pf(expf(v));
    }
    __syncthreads();
    if (t == 0) {
        float expA = expf(Alog[h]);
        float run = 0.f;
        for (int l = 0; l < 64; l++) { run -= expA * sdt[l]; sacum[l] = run; }
        gAlast[tile] = run;
    }
    __syncthreads();
    if (t < 64) {
        sdec[t] = __expf(sacum[63] - sacum[t]);
        gAcum[tile * 64 + t] = sacum[t];
    }
    __syncthreads();

    stage_rows(sStage, gProj + (size_t)tokb * PROJN + 2048 + h * 64, PROJN, t, nullptr);
    __syncthreads();
    tile_transpose_hl(sBTh, sBTl, sStage, t, nullptr);
    __syncthreads();
    stage_rows(sStage, gProj + (size_t)tokb * PROJN + h * 64, PROJN, t, sdt);
    __syncthreads();
    tile_transpose_hl(sXTh, sXTl, sStage, t, sdec);
    __syncthreads();

    float accH[8][4], accM[8][4];
#pragma unroll
    for (int i = 0; i < 8; i++)
#pragma unroll
        for (int k = 0; k < 4; k++) { accH[i][k] = 0.f; accM[i][k] = 0.f; }
    tile_mma_hl(accH, accM, smem_u32(sXTh), smem_u32(sXTl),
                smem_u32(sBTh), smem_u32(sBTl), w * 16, lane);

    size_t obase = (size_t)tile * 4096;
    int r = w * 16 + (lane >> 2);
#pragma unroll
    for (int ni = 0; ni < 8; ni++) {
        int cc = ni * 8 + ((lane & 3) << 1);
        *(float2*)&gStates[obase + r * 64 + cc] =
            make_float2(accH[ni][0] + accM[ni][0] * LO_INV_SCALE,
                        accH[ni][1] + accM[ni][1] * LO_INV_SCALE);
        *(float2*)&gStates[obase + (r + 8) * 64 + cc] =
            make_float2(accH[ni][2] + accM[ni][2] * LO_INV_SCALE,
                        accH[ni][3] + accM[ni][3] * LO_INV_SCALE);
    }
}

// ---------------------------------------------------------------------------
// Chunk-level scan (unchanged)
// ---------------------------------------------------------------------------
__global__ __launch_bounds__(256)
void scan_kernel(float* __restrict__ out_final) {
    const int bh = blockIdx.x >> 4;
    const int b = bh >> 4, h = bh & 15;
    const int e = ((blockIdx.x & 15) << 8) | threadIdx.x;
    float S = 0.f;
#pragma unroll 4
    for (int c = 0; c < 64; c++) {
        int tile = (b * 64 + c) * 16 + h;
        float d = expf(gAlast[tile]);
        size_t base = (size_t)tile * 4096 + e;
        gStateIn[base] = S;
        S = S * d + gStates[base];
    }
    out_final[(size_t)Y_ELEMS + (size_t)(b * 16 + h) * 4096 + e] = S;
}

// ---------------------------------------------------------------------------
// SSD pass 2, 3-term everywhere: G = C.B^T (mask/exp), Y = G.X^T + eA*(C.S^T),
// gate, write fp16 Ya. 128 threads.
// smem: stage 0 | Ch 16640 | Cl 24832 | Bh 33024 | Bl 41216 | Sh 49408
//       | Sl 57600 | Xh 65792 | Xl 73984 | Gh 82176 | Gl 90368 | sc 98560
// ---------------------------------------------------------------------------
#define P2_SMEM (98560 + 768)
__global__ __launch_bounds__(128)
void ssd_pass2(const float* __restrict__ bdt) {
    extern __shared__ char sm[];
    float* sStage = (float*)sm;
    char* sCh = sm + 16640;
    char* sCl = sm + 24832;
    char* sBh = sm + 33024;
    char* sBl = sm + 41216;
    char* sSh = sm + 49408;
    char* sSl = sm + 57600;
    char* sXh = sm + 65792;
    char* sXl = sm + 73984;
    char* sGh = sm + 82176;
    char* sGl = sm + 90368;
    float* sdt   = (float*)(sm + 98560);
    float* sacum = (float*)(sm + 98560 + 256);
    float* seA   = (float*)(sm + 98560 + 512);

    const int tile = blockIdx.x;
    const int h = tile & 15;
    const int c = (tile >> 4) & 63;
    const int b = tile >> 10;
    const int t = threadIdx.x;
    const int lane = t & 31, w = t >> 5;
    const int tokb = b * 4096 + c * 64;

    if (t < 64) {
        float v = gProj[(size_t)(tokb + t) * PROJN + 4096 + h] + bdt[h];
        sdt[t] = (v > 20.f) ? v : log1pf(expf(v));
        float ac = gAcum[tile * 64 + t];
        sacum[t] = ac;
        seA[t] = __expf(ac);
    }
    __syncthreads();

    stage_rows(sStage, gProj + (size_t)tokb * PROJN + 3072 + h * 64, PROJN, t, nullptr);
    __syncthreads();
    tile_direct_hl(sCh, sCl, sStage, t);
    __syncthreads();
    stage_rows(sStage, gProj + (size_t)tokb * PROJN + 2048 + h * 64, PROJN, t, nullptr);
    __syncthreads();
    tile_direct_hl(sBh, sBl, sStage, t);
    __syncthreads();
    stage_rows(sStage, gStateIn + (size_t)tile * 4096, 64, t, nullptr);
    __syncthreads();
    tile_direct_hl(sSh, sSl, sStage, t);
    __syncthreads();
    stage_rows(sStage, gProj + (size_t)tokb * PROJN + h * 64, PROJN, t, sdt);
    __syncthreads();
    tile_transpose_hl(sXh, sXl, sStage, t, nullptr);
    __syncthreads();

    // G = C.B^T (3-term), then mask + exp, write hi/lo G tiles
    {
        float gH[8][4], gM[8][4];
#pragma unroll
        for (int i = 0; i < 8; i++)
#pragma unroll
            for (int k = 0; k < 4; k++) { gH[i][k] = 0.f; gM[i][k] = 0.f; }
        tile_mma_hl(gH, gM, smem_u32(sCh), smem_u32(sCl),
                    smem_u32(sBh), smem_u32(sBl), w * 16, lane);

        int r0 = w * 16 + (lane >> 2);
        int r1 = r0 + 8;
        float a0 = sacum[r0], a1 = sacum[r1];
#pragma unroll
        for (int ni = 0; ni < 8; ni++) {
            int s0 = ni * 8 + ((lane & 3) << 1);
            int s1 = s0 + 1;
            float v00 = gH[ni][0] + gM[ni][0] * LO_INV_SCALE;
            float v01 = gH[ni][1] + gM[ni][1] * LO_INV_SCALE;
            float v10 = gH[ni][2] + gM[ni][2] * LO_INV_SCALE;
            float v11 = gH[ni][3] + gM[ni][3] * LO_INV_SCALE;
            v00 = (s0 <= r0) ? v00 * __expf(a0 - sacum[s0]) : 0.f;
            v01 = (s1 <= r0) ? v01 * __expf(a0 - sacum[s1]) : 0.f;
            v10 = (s0 <= r1) ? v10 * __expf(a1 - sacum[s0]) : 0.f;
            v11 = (s1 <= r1) ? v11 * __expf(a1 - sacum[s1]) : 0.f;
            put_hl(sGh, sGl, SW128((uint32_t)(r0 * 128 + s0 * 2)), v00, v01);
            put_hl(sGh, sGl, SW128((uint32_t)(r1 * 128 + s0 * 2)), v10, v11);
        }
    }
    __syncthreads();

    // Y = G.X^T (3-term)
    float yv[8][4];
    {
        float aH[8][4], aM[8][4];
#pragma unroll
        for (int i = 0; i < 8; i++)
#pragma unroll
            for (int k = 0; k < 4; k++) { aH[i][k] = 0.f; aM[i][k] = 0.f; }
        tile_mma_hl(aH, aM, smem_u32(sGh), smem_u32(sGl),
                    smem_u32(sXh), smem_u32(sXl), w * 16, lane);
#pragma unroll
        for (int i = 0; i < 8; i++)
#pragma unroll
            for (int k = 0; k < 4; k++) yv[i][k] = aH[i][k] + aM[i][k] * LO_INV_SCALE;
    }
    // O = C.S^T (3-term), fold, gate, write
    {
        float aH[8][4], aM[8][4];
#pragma unroll
        for (int i = 0; i < 8; i++)
#pragma unroll
            for (int k = 0; k < 4; k++) { aH[i][k] = 0.f; aM[i][k] = 0.f; }
        tile_mma_hl(aH, aM, smem_u32(sCh), smem_u32(sCl),
                    smem_u32(sSh), smem_u32(sSl), w * 16, lane);

        int r0 = w * 16 + (lane >> 2);
#pragma unroll
        for (int rr = 0; rr < 2; rr++) {
            int l = r0 + rr * 8;
            float eA = seA[l];
            size_t tok = (size_t)(tokb + l);
            const float* zrow = gProj + tok * PROJN + 1024 + h * 64;
            __half2* yaRow = (__half2*)(gYa + tok * DMOD + h * 64);
#pragma unroll
            for (int ni = 0; ni < 8; ni++) {
                int p = ni * 8 + ((lane & 3) << 1);
                float o0 = aH[ni][rr * 2 + 0] + aM[ni][rr * 2 + 0] * LO_INV_SCALE;
                float o1 = aH[ni][rr * 2 + 1] + aM[ni][rr * 2 + 1] * LO_INV_SCALE;
                float y0 = yv[ni][rr * 2 + 0] + eA * o0;
                float y1 = yv[ni][rr * 2 + 1] + eA * o1;
                float2 z = *(const float2*)&zrow[p];
                y0 *= z.x / (1.f + __expf(-z.x));
                y1 *= z.y / (1.f + __expf(-z.y));
                yaRow[p >> 1] = __half2(__float2half(y0), __float2half(y1));
            }
        }
    }
}

// ---------------------------------------------------------------------------
extern "C" void kernel_launch(void* const* d_in, const int* in_sizes, int n_in,
                              void* d_out, int out_size) {
    const float* x     = (const float*)d_in[0];
    const float* W_in  = (const float*)d_in[1];
    const float* W_dt  = (const float*)d_in[2];
    const float* b_dt  = (const float*)d_in[3];
    const float* W_B   = (const float*)d_in[4];
    const float* W_C   = (const float*)d_in[5];
    const float* W_out = (const float*)d_in[6];
    const float* A_log = (const float*)d_in[7];
    float* out = (float*)d_out;

    void *pProj, *pXh, *pWc, *pWo, *pYa;
    cudaGetSymbolAddress(&pProj, gProj);
    cudaGetSymbolAddress(&pXh, gXh);
    cudaGetSymbolAddress(&pWc, gWcat);
    cudaGetSymbolAddress(&pWo, gWo);
    cudaGetSymbolAddress(&pYa, gYa);

    cudaFuncSetAttribute(gemm_mma, cudaFuncAttributeMaxDynamicSharedMemorySize, GEMM_SMEM);
    cudaFuncSetAttribute(ssd_pass1, cudaFuncAttributeMaxDynamicSharedMemorySize, P1_SMEM);
    cudaFuncSetAttribute(ssd_pass2, cudaFuncAttributeMaxDynamicSharedMemorySize, P2_SMEM);

    // #0: conversions
    cvt_all<<<S_TOT / 256, 256>>>(x, W_in, W_B, W_C, W_dt, W_out);

    // #1: combined projection GEMM (single-term fp16)
    gemm_mma<<<dim3(PROJN / 128, NTOK / 128), 256, GEMM_SMEM>>>(
        (const __half*)pXh, (const __half*)pWc, (float*)pProj, NTOK, PROJN, DMOD);

    // #2-#4
    ssd_pass1<<<NTILE, 128, P1_SMEM>>>(A_log, b_dt);
    scan_kernel<<<512, 256>>>(out);
    ssd_pass2<<<NTILE, 128, P2_SMEM>>>(b_dt);

    // #5: output GEMM (single-term fp16)
    gemm_mma<<<dim3(DMOD / 128, NTOK / 128), 256, GEMM_SMEM>>>(
        (const __half*)pYa, (const __half*)pWo, out, NTOK, DMOD, DMOD);
}

// round 10
// speedup vs baseline: 2.1397x; 1.0984x over previous
#include <cuda_runtime.h>
#include <cuda_fp16.h>
#include <math.h>
#include <stdint.h>

#define NTOK   8192
#define DMOD   1024
#define NHEADS 16
#define NTILE  2048
#define Y_ELEMS 8388608
#define PROJN  4224

#define LO_SCALE     2048.0f
#define LO_INV_SCALE (1.0f / 2048.0f)

// fp32 scratch
__device__ float gProj[NTOK * PROJN];
__device__ float gStates[NTILE * 4096];
__device__ float gStateIn[NTILE * 4096];
__device__ float gAlast[NTILE];
__device__ float gAcum[NTILE * 64];

// fp16 operand scratch
__device__ __half gXh[NTOK * DMOD];
__device__ __half gWcat[PROJN * DMOD];
__device__ __half gWo[DMOD * DMOD];
__device__ __half gYa[NTOK * DMOD];

// ---------------------------------------------------------------------------
// PTX helpers
// ---------------------------------------------------------------------------
__device__ __forceinline__ uint32_t smem_u32(const void* p) {
    uint32_t a;
    asm("{ .reg .u64 t; cvta.to.shared.u64 t, %1; cvt.u32.u64 %0, t; }" : "=r"(a) : "l"(p));
    return a;
}
#define SW128(o) ((o) ^ (((o) >> 3) & 0x70))

__device__ __forceinline__ void cp16(uint32_t dst, const void* src) {
    asm volatile("cp.async.cg.shared.global [%0], [%1], 16;\n" :: "r"(dst), "l"(src));
}
__device__ __forceinline__ void cp_commit() { asm volatile("cp.async.commit_group;\n" ::: "memory"); }
template <int N> __device__ __forceinline__ void cp_wait() {
    asm volatile("cp.async.wait_group %0;\n" :: "n"(N) : "memory");
}
__device__ __forceinline__ void ldsm4(uint32_t* r, uint32_t addr) {
    asm volatile("ldmatrix.sync.aligned.m8n8.x4.shared.b16 {%0,%1,%2,%3}, [%4];"
                 : "=r"(r[0]), "=r"(r[1]), "=r"(r[2]), "=r"(r[3]) : "r"(addr));
}
__device__ __forceinline__ void mma_f32(float* d, const uint32_t* a, const uint32_t* b) {
    asm volatile("mma.sync.aligned.m16n8k16.row.col.f32.f16.f16.f32 "
                 "{%0,%1,%2,%3}, {%4,%5,%6,%7}, {%8,%9}, {%0,%1,%2,%3};"
                 : "+f"(d[0]), "+f"(d[1]), "+f"(d[2]), "+f"(d[3])
                 : "r"(a[0]), "r"(a[1]), "r"(a[2]), "r"(a[3]), "r"(b[0]), "r"(b[1]));
}

// ---------------------------------------------------------------------------
// Big GEMM, single-term fp16, 3-stage cp.async pipeline.
// CTA 128x128, 256 thr, 8 warps (4m x 2n, warp tile 32x64), k64 chunks.
// ---------------------------------------------------------------------------
#define OF_A 0
#define OF_B 16384
#define STG  32768
#define GEMM_SMEM (3 * STG)   // 98304

__device__ __forceinline__ void load_rows(uint32_t smem_dst, const __half* g,
                                          int row0, int K, int k0, int t) {
#pragma unroll
    for (int it = 0; it < 4; it++) {
        int p = t + it * 256;
        int r = p >> 3, cc = p & 7;
        uint32_t off = (uint32_t)(r * 128 + cc * 16);
        cp16(smem_dst + SW128(off), g + (size_t)(row0 + r) * K + k0 + cc * 8);
    }
}

__global__ __launch_bounds__(256)
void gemm_mma(const __half* __restrict__ A, const __half* __restrict__ B,
              float* __restrict__ C, int M, int N, int K) {
    extern __shared__ char smem[];
    const uint32_t sb = smem_u32(smem);
    const int t = threadIdx.x;
    const int wid = t >> 5, lane = t & 31;
    const int bm = blockIdx.y * 128;
    const int bn = blockIdx.x * 128;
    const int wm = (wid & 3) * 32;
    const int wn = (wid >> 2) * 64;
    const int nch = K >> 6;

    float acc[2][8][4];
#pragma unroll
    for (int i = 0; i < 2; i++)
#pragma unroll
        for (int j = 0; j < 8; j++)
#pragma unroll
            for (int k = 0; k < 4; k++) acc[i][j][k] = 0.f;

    // prologue: chunks 0,1 -> stages 0,1
#pragma unroll
    for (int pc = 0; pc < 2; pc++) {
        uint32_t st = sb + pc * STG;
        load_rows(st + OF_A, A, bm, K, pc * 64, t);
        load_rows(st + OF_B, B, bn, K, pc * 64, t);
        cp_commit();
    }

    const int ra = (lane & 15);
    const uint32_t ca = (uint32_t)((lane >> 4) << 4);
    const int rb = (lane & 7) + (((lane >> 4) & 1) << 3);
    const uint32_t cb = (uint32_t)(((lane >> 3) & 1) << 4);

    int s0 = 0;   // stage holding chunk i
    for (int i = 0; i < nch; i++) {
        if (i + 2 < nch) {
            int sl = s0 + 2; if (sl >= 3) sl -= 3;
            uint32_t st2 = sb + sl * STG;
            int k0 = (i + 2) * 64;
            load_rows(st2 + OF_A, A, bm, K, k0, t);
            load_rows(st2 + OF_B, B, bn, K, k0, t);
            cp_commit();
            cp_wait<2>();
        } else if (i + 1 < nch) cp_wait<1>();
        else cp_wait<0>();
        __syncthreads();
        const uint32_t st = sb + s0 * STG;

#pragma unroll
        for (int kk = 0; kk < 4; kk++) {
            uint32_t af[2][4], bf[4][4];
#pragma unroll
            for (int mi = 0; mi < 2; mi++) {
                int row = wm + mi * 16 + ra;
                ldsm4(af[mi], st + OF_A + SW128((uint32_t)(row * 128 + kk * 32) + ca));
            }
#pragma unroll
            for (int nb = 0; nb < 4; nb++) {
                int rown = wn + nb * 16 + rb;
                ldsm4(bf[nb], st + OF_B + SW128((uint32_t)(rown * 128 + kk * 32) + cb));
            }
#pragma unroll
            for (int mi = 0; mi < 2; mi++)
#pragma unroll
                for (int ni = 0; ni < 8; ni++)
                    mma_f32(acc[mi][ni], af[mi], &bf[ni >> 1][(ni & 1) * 2]);
        }
        __syncthreads();
        if (++s0 == 3) s0 = 0;
    }

#pragma unroll
    for (int mi = 0; mi < 2; mi++) {
        int r0 = bm + wm + mi * 16 + (lane >> 2);
#pragma unroll
        for (int ni = 0; ni < 8; ni++) {
            int c0 = bn + wn + ni * 8 + ((lane & 3) << 1);
            *(float2*)&C[(size_t)r0 * N + c0] = make_float2(acc[mi][ni][0], acc[mi][ni][1]);
            *(float2*)&C[(size_t)(r0 + 8) * N + c0] = make_float2(acc[mi][ni][2], acc[mi][ni][3]);
        }
    }
}

// ---------------------------------------------------------------------------
// Conversions (one launch)
// ---------------------------------------------------------------------------
__device__ __forceinline__ void cvt_s(const float* __restrict__ src,
                                      __half* __restrict__ dst, int i) {
    float4 v = ((const float4*)src)[i];
    __half2* dp = (__half2*)dst;
    dp[2 * i]     = __half2(__float2half(v.x), __float2half(v.y));
    dp[2 * i + 1] = __half2(__float2half(v.z), __float2half(v.w));
}

#define S_X   2097152
#define S_WIN 524288
#define S_WB  262144
#define S_WC  262144
#define S_WDT 4096
#define S_WO  262144
#define S_TOT (S_X + S_WIN + S_WB + S_WC + S_WDT + S_WO)

__global__ __launch_bounds__(256)
void cvt_all(const float* __restrict__ x, const float* __restrict__ Win,
             const float* __restrict__ WB, const float* __restrict__ WC,
             const float* __restrict__ Wdt, const float* __restrict__ Wout) {
    int i = blockIdx.x * 256 + threadIdx.x;
    if (i < S_X) { cvt_s(x, gXh, i); return; }
    i -= S_X;
    if (i < S_WIN) { cvt_s(Win, gWcat, i); return; }
    i -= S_WIN;
    if (i < S_WB) { cvt_s(WB, gWcat + 2048 * DMOD, i); return; }
    i -= S_WB;
    if (i < S_WC) { cvt_s(WC, gWcat + 3072 * DMOD, i); return; }
    i -= S_WC;
    if (i < S_WDT) { cvt_s(Wdt, gWcat + 4096 * DMOD, i); return; }
    i -= S_WDT;
    if (i < S_WO) { cvt_s(Wout, gWo, i); return; }
}

// ---------------------------------------------------------------------------
// SSD tile helpers (64x128B SW128 tiles; lo = (v-hi)*2048)
// ---------------------------------------------------------------------------
__device__ __forceinline__ void stage_rows(float* sStage, const float* __restrict__ src0,
                                           int stride, int t, const float* scale) {
    int l = t >> 1, cbase = (t & 1) * 32;
    const float4* src = (const float4*)(src0 + (size_t)l * stride + cbase);
    float s = scale ? scale[l] : 1.f;
#pragma unroll
    for (int j = 0; j < 8; j++) {
        float4 v = src[j];
        float* d = &sStage[l * 65 + cbase + j * 4];
        d[0] = v.x * s; d[1] = v.y * s; d[2] = v.z * s; d[3] = v.w * s;
    }
}
__device__ __forceinline__ void put_hl(char* tH, char* tL, uint32_t off, float v0, float v1) {
    __half h0 = __float2half(v0), h1 = __float2half(v1);
    *(__half2*)(tH + off) = __half2(h0, h1);
    *(__half2*)(tL + off) = __half2(__float2half((v0 - __half2float(h0)) * LO_SCALE),
                                    __float2half((v1 - __half2float(h1)) * LO_SCALE));
}
// convert fp32 global rows -> hi/lo fp16 swizzled tile, no staging (coalesced)
__device__ __forceinline__ void conv_direct_global(char* tH, char* tL,
                                                   const float* __restrict__ src0,
                                                   int stride, int t) {
    int l = t >> 1, cbase = (t & 1) * 32;
    const float4* src = (const float4*)(src0 + (size_t)l * stride + cbase);
#pragma unroll
    for (int j = 0; j < 8; j++) {
        float4 v = src[j];
        int c = cbase + j * 4;
        put_hl(tH, tL, SW128((uint32_t)(l * 128 + c * 2)), v.x, v.y);
        put_hl(tH, tL, SW128((uint32_t)(l * 128 + (c + 2) * 2)), v.z, v.w);
    }
}
__device__ __forceinline__ void tile_transpose_hl(char* tH, char* tL, const float* sStage,
                                                  int t, const float* kscale) {
    int o = t >> 1, kbase = (t & 1) * 32;
#pragma unroll
    for (int j = 0; j < 16; j++) {
        int k0 = kbase + 2 * j;
        float v0 = sStage[k0 * 65 + o];
        float v1 = sStage[(k0 + 1) * 65 + o];
        if (kscale) { v0 *= kscale[k0]; v1 *= kscale[k0 + 1]; }
        put_hl(tH, tL, SW128((uint32_t)(o * 128 + k0 * 2)), v0, v1);
    }
}
// 3-term 64x64x64 tile GEMM
__device__ __forceinline__ void tile_mma_hl(float accH[8][4], float accM[8][4],
                                            uint32_t aH, uint32_t aL,
                                            uint32_t bH, uint32_t bL,
                                            int wm, int lane) {
    const int ra = (lane & 15);
    const uint32_t ca = (uint32_t)((lane >> 4) << 4);
    const int rb = (lane & 7) + (((lane >> 4) & 1) << 3);
    const uint32_t cb = (uint32_t)(((lane >> 3) & 1) << 4);
#pragma unroll
    for (int kk = 0; kk < 4; kk++) {
        uint32_t ah[4], al[4], bh[4][4], bl[4][4];
        uint32_t aoff = SW128((uint32_t)((wm + ra) * 128 + kk * 32) + ca);
        ldsm4(ah, aH + aoff);
        ldsm4(al, aL + aoff);
#pragma unroll
        for (int nb = 0; nb < 4; nb++) {
            uint32_t boff = SW128((uint32_t)((nb * 16 + rb) * 128 + kk * 32) + cb);
            ldsm4(bh[nb], bH + boff);
            ldsm4(bl[nb], bL + boff);
        }
#pragma unroll
        for (int ni = 0; ni < 8; ni++) {
            const uint32_t* b2h = &bh[ni >> 1][(ni & 1) * 2];
            const uint32_t* b2l = &bl[ni >> 1][(ni & 1) * 2];
            mma_f32(accH[ni], ah, b2h);
            mma_f32(accM[ni], ah, b2l);
            mma_f32(accM[ni], al, b2h);
        }
    }
}

// ---------------------------------------------------------------------------
// SSD pass 1: states = (X*dt*dec)^T . B, 3-term, concurrent staging.
// smem: stageB 0 | stageX 16640 | XTh 33280 | XTl 41472 | BTh 49664
//       | BTl 57856 | sc 66048
// ---------------------------------------------------------------------------
#define P1_SMEM (66048 + 768)
__global__ __launch_bounds__(128)
void ssd_pass1(const float* __restrict__ Alog, const float* __restrict__ bdt) {
    extern __shared__ char sm[];
    float* sStageB = (float*)sm;
    float* sStageX = (float*)(sm + 16640);
    char* sXTh = sm + 33280;
    char* sXTl = sm + 41472;
    char* sBTh = sm + 49664;
    char* sBTl = sm + 57856;
    float* sdt   = (float*)(sm + 66048);
    float* sacum = (float*)(sm + 66048 + 256);
    float* sdec  = (float*)(sm + 66048 + 512);

    const int tile = blockIdx.x;
    const int h = tile & 15;
    const int c = (tile >> 4) & 63;
    const int b = tile >> 10;
    const int t = threadIdx.x;
    const int lane = t & 31, w = t >> 5;
    const int tokb = b * 4096 + c * 64;

    if (t < 64) {
        float v = gProj[(size_t)(tokb + t) * PROJN + 4096 + h] + bdt[h];
        sdt[t] = (v > 20.f) ? v : log1pf(expf(v));
    }
    __syncthreads();
    if (t == 0) {
        float expA = expf(Alog[h]);
        float run = 0.f;
        for (int l = 0; l < 64; l++) { run -= expA * sdt[l]; sacum[l] = run; }
        gAlast[tile] = run;
    }
    __syncthreads();
    if (t < 64) {
        sdec[t] = __expf(sacum[63] - sacum[t]);
        gAcum[tile * 64 + t] = sacum[t];
    }

    // stage B and X concurrently (loads overlap), one sync, transpose both
    stage_rows(sStageB, gProj + (size_t)tokb * PROJN + 2048 + h * 64, PROJN, t, nullptr);
    stage_rows(sStageX, gProj + (size_t)tokb * PROJN + h * 64, PROJN, t, sdt);
    __syncthreads();
    tile_transpose_hl(sBTh, sBTl, sStageB, t, nullptr);
    tile_transpose_hl(sXTh, sXTl, sStageX, t, sdec);
    __syncthreads();

    float accH[8][4], accM[8][4];
#pragma unroll
    for (int i = 0; i < 8; i++)
#pragma unroll
        for (int k = 0; k < 4; k++) { accH[i][k] = 0.f; accM[i][k] = 0.f; }
    tile_mma_hl(accH, accM, smem_u32(sXTh), smem_u32(sXTl),
                smem_u32(sBTh), smem_u32(sBTl), w * 16, lane);

    size_t obase = (size_t)tile * 4096;
    int r = w * 16 + (lane >> 2);
#pragma unroll
    for (int ni = 0; ni < 8; ni++) {
        int cc = ni * 8 + ((lane & 3) << 1);
        *(float2*)&gStates[obase + r * 64 + cc] =
            make_float2(accH[ni][0] + accM[ni][0] * LO_INV_SCALE,
                        accH[ni][1] + accM[ni][1] * LO_INV_SCALE);
        *(float2*)&gStates[obase + (r + 8) * 64 + cc] =
            make_float2(accH[ni][2] + accM[ni][2] * LO_INV_SCALE,
                        accH[ni][3] + accM[ni][3] * LO_INV_SCALE);
    }
}

// ---------------------------------------------------------------------------
// Chunk-level scan: 4 elements per thread (MLP=4 on the serial chain)
// grid 128, block 256: block covers bh = blk>>2, elems (blk&3)*1024 + tid + k*256
// ---------------------------------------------------------------------------
__global__ __launch_bounds__(256)
void scan_kernel(float* __restrict__ out_final) {
    const int blk = blockIdx.x;
    const int bh = blk >> 2;
    const int b = bh >> 4, h = bh & 15;
    const int e0 = (blk & 3) * 1024 + threadIdx.x;
    float S0 = 0.f, S1 = 0.f, S2 = 0.f, S3 = 0.f;
    for (int c = 0; c < 64; c++) {
        int tile = (b * 64 + c) * 16 + h;
        float d = expf(gAlast[tile]);
        size_t base = (size_t)tile * 4096 + e0;
        float v0 = gStates[base], v1 = gStates[base + 256];
        float v2 = gStates[base + 512], v3 = gStates[base + 768];
        gStateIn[base]       = S0;
        gStateIn[base + 256] = S1;
        gStateIn[base + 512] = S2;
        gStateIn[base + 768] = S3;
        S0 = S0 * d + v0; S1 = S1 * d + v1; S2 = S2 * d + v2; S3 = S3 * d + v3;
    }
    size_t ob = (size_t)Y_ELEMS + (size_t)(b * 16 + h) * 4096 + e0;
    out_final[ob]       = S0;
    out_final[ob + 256] = S1;
    out_final[ob + 512] = S2;
    out_final[ob + 768] = S3;
}

// ---------------------------------------------------------------------------
// SSD pass 2: direct global->tile conversion for C/B/S; staged transpose for X.
// smem: stageX 0 | Ch 16640 | Cl 24832 | Bh 33024 | Bl 41216 | Sh 49408
//       | Sl 57600 | Xh 65792 | Xl 73984 | Gh 82176 | Gl 90368 | sc 98560
// ---------------------------------------------------------------------------
#define P2_SMEM (98560 + 768)
__global__ __launch_bounds__(128)
void ssd_pass2(const float* __restrict__ bdt) {
    extern __shared__ char sm[];
    float* sStageX = (float*)sm;
    char* sCh = sm + 16640;
    char* sCl = sm + 24832;
    char* sBh = sm + 33024;
    char* sBl = sm + 41216;
    char* sSh = sm + 49408;
    char* sSl = sm + 57600;
    char* sXh = sm + 65792;
    char* sXl = sm + 73984;
    char* sGh = sm + 82176;
    char* sGl = sm + 90368;
    float* sdt   = (float*)(sm + 98560);
    float* sacum = (float*)(sm + 98560 + 256);
    float* seA   = (float*)(sm + 98560 + 512);

    const int tile = blockIdx.x;
    const int h = tile & 15;
    const int c = (tile >> 4) & 63;
    const int b = tile >> 10;
    const int t = threadIdx.x;
    const int lane = t & 31, w = t >> 5;
    const int tokb = b * 4096 + c * 64;

    if (t < 64) {
        float v = gProj[(size_t)(tokb + t) * PROJN + 4096 + h] + bdt[h];
        sdt[t] = (v > 20.f) ? v : log1pf(expf(v));
        float ac = gAcum[tile * 64 + t];
        sacum[t] = ac;
        seA[t] = __expf(ac);
    }
    __syncthreads();

    // all global reads issue up front; one sync; transpose X; one sync
    conv_direct_global(sCh, sCl, gProj + (size_t)tokb * PROJN + 3072 + h * 64, PROJN, t);
    conv_direct_global(sBh, sBl, gProj + (size_t)tokb * PROJN + 2048 + h * 64, PROJN, t);
    conv_direct_global(sSh, sSl, gStateIn + (size_t)tile * 4096, 64, t);
    stage_rows(sStageX, gProj + (size_t)tokb * PROJN + h * 64, PROJN, t, sdt);
    __syncthreads();
    tile_transpose_hl(sXh, sXl, sStageX, t, nullptr);
    __syncthreads();

    // G = C.B^T (3-term), mask + exp, write hi/lo G tiles
    {
        float gH[8][4], gM[8][4];
#pragma unroll
        for (int i = 0; i < 8; i++)
#pragma unroll
            for (int k = 0; k < 4; k++) { gH[i][k] = 0.f; gM[i][k] = 0.f; }
        tile_mma_hl(gH, gM, smem_u32(sCh), smem_u32(sCl),
                    smem_u32(sBh), smem_u32(sBl), w * 16, lane);

        int r0 = w * 16 + (lane >> 2);
        int r1 = r0 + 8;
        float a0 = sacum[r0], a1 = sacum[r1];
#pragma unroll
        for (int ni = 0; ni < 8; ni++) {
            int s0 = ni * 8 + ((lane & 3) << 1);
            int s1 = s0 + 1;
            float v00 = gH[ni][0] + gM[ni][0] * LO_INV_SCALE;
            float v01 = gH[ni][1] + gM[ni][1] * LO_INV_SCALE;
            float v10 = gH[ni][2] + gM[ni][2] * LO_INV_SCALE;
            float v11 = gH[ni][3] + gM[ni][3] * LO_INV_SCALE;
            v00 = (s0 <= r0) ? v00 * __expf(a0 - sacum[s0]) : 0.f;
            v01 = (s1 <= r0) ? v01 * __expf(a0 - sacum[s1]) : 0.f;
            v10 = (s0 <= r1) ? v10 * __expf(a1 - sacum[s0]) : 0.f;
            v11 = (s1 <= r1) ? v11 * __expf(a1 - sacum[s1]) : 0.f;
            put_hl(sGh, sGl, SW128((uint32_t)(r0 * 128 + s0 * 2)), v00, v01);
            put_hl(sGh, sGl, SW128((uint32_t)(r1 * 128 + s0 * 2)), v10, v11);
        }
    }
    __syncthreads();

    // Y = G.X^T (3-term)
    float yv[8][4];
    {
        float aH[8][4], aM[8][4];
#pragma unroll
        for (int i = 0; i < 8; i++)
#pragma unroll
            for (int k = 0; k < 4; k++) { aH[i][k] = 0.f; aM[i][k] = 0.f; }
        tile_mma_hl(aH, aM, smem_u32(sGh), smem_u32(sGl),
                    smem_u32(sXh), smem_u32(sXl), w * 16, lane);
#pragma unroll
        for (int i = 0; i < 8; i++)
#pragma unroll
            for (int k = 0; k < 4; k++) yv[i][k] = aH[i][k] + aM[i][k] * LO_INV_SCALE;
    }
    // O = C.S^T (3-term), fold, gate, write fp16 Ya
    {
        float aH[8][4], aM[8][4];
#pragma unroll
        for (int i = 0; i < 8; i++)
#pragma unroll
            for (int k = 0; k < 4; k++) { aH[i][k] = 0.f; aM[i][k] = 0.f; }
        tile_mma_hl(aH, aM, smem_u32(sCh), smem_u32(sCl),
                    smem_u32(sSh), smem_u32(sSl), w * 16, lane);

        int r0 = w * 16 + (lane >> 2);
#pragma unroll
        for (int rr = 0; rr < 2; rr++) {
            int l = r0 + rr * 8;
            float eA = seA[l];
            size_t tok = (size_t)(tokb + l);
            const float* zrow = gProj + tok * PROJN + 1024 + h * 64;
            __half2* yaRow = (__half2*)(gYa + tok * DMOD + h * 64);
#pragma unroll
            for (int ni = 0; ni < 8; ni++) {
                int p = ni * 8 + ((lane & 3) << 1);
                float o0 = aH[ni][rr * 2 + 0] + aM[ni][rr * 2 + 0] * LO_INV_SCALE;
                float o1 = aH[ni][rr * 2 + 1] + aM[ni][rr * 2 + 1] * LO_INV_SCALE;
                float y0 = yv[ni][rr * 2 + 0] + eA * o0;
                float y1 = yv[ni][rr * 2 + 1] + eA * o1;
                float2 z = *(const float2*)&zrow[p];
                y0 *= z.x / (1.f + __expf(-z.x));
                y1 *= z.y / (1.f + __expf(-z.y));
                yaRow[p >> 1] = __half2(__float2half(y0), __float2half(y1));
            }
        }
    }
}

// ---------------------------------------------------------------------------
extern "C" void kernel_launch(void* const* d_in, const int* in_sizes, int n_in,
                              void* d_out, int out_size) {
    const float* x     = (const float*)d_in[0];
    const float* W_in  = (const float*)d_in[1];
    const float* W_dt  = (const float*)d_in[2];
    const float* b_dt  = (const float*)d_in[3];
    const float* W_B   = (const float*)d_in[4];
    const float* W_C   = (const float*)d_in[5];
    const float* W_out = (const float*)d_in[6];
    const float* A_log = (const float*)d_in[7];
    float* out = (float*)d_out;

    void *pProj, *pXh, *pWc, *pWo, *pYa;
    cudaGetSymbolAddress(&pProj, gProj);
    cudaGetSymbolAddress(&pXh, gXh);
    cudaGetSymbolAddress(&pWc, gWcat);
    cudaGetSymbolAddress(&pWo, gWo);
    cudaGetSymbolAddress(&pYa, gYa);

    cudaFuncSetAttribute(gemm_mma, cudaFuncAttributeMaxDynamicSharedMemorySize, GEMM_SMEM);
    cudaFuncSetAttribute(ssd_pass1, cudaFuncAttributeMaxDynamicSharedMemorySize, P1_SMEM);
    cudaFuncSetAttribute(ssd_pass2, cudaFuncAttributeMaxDynamicSharedMemorySize, P2_SMEM);

    // #0: conversions
    cvt_all<<<S_TOT / 256, 256>>>(x, W_in, W_B, W_C, W_dt, W_out);

    // #1: combined projection GEMM (single-term fp16, 3-stage)
    gemm_mma<<<dim3(PROJN / 128, NTOK / 128), 256, GEMM_SMEM>>>(
        (const __half*)pXh, (const __half*)pWc, (float*)pProj, NTOK, PROJN, DMOD);

    // #2-#4
    ssd_pass1<<<NTILE, 128, P1_SMEM>>>(A_log, b_dt);
    scan_kernel<<<128, 256>>>(out);
    ssd_pass2<<<NTILE, 128, P2_SMEM>>>(b_dt);

    // #5: output GEMM (single-term fp16, 3-stage)
    gemm_mma<<<dim3(DMOD / 128, NTOK / 128), 256, GEMM_SMEM>>>(
        (const __half*)pYa, (const __half*)pWo, out, NTOK, DMOD, DMOD);
}

// round 11
// speedup vs baseline: 2.2193x; 1.0372x over previous
#include <cuda_runtime.h>
#include <cuda_fp16.h>
#include <math.h>
#include <stdint.h>

#define NTOK   8192
#define DMOD   1024
#define NHEADS 16
#define NTILE  2048
#define Y_ELEMS 8388608
#define PROJN  4224

#define LO_SCALE     2048.0f
#define LO_INV_SCALE (1.0f / 2048.0f)

// fp32 scratch
__device__ float gProj[NTOK * PROJN];
__device__ float gStates[NTILE * 4096];
__device__ float gStateIn[NTILE * 4096];
__device__ float gAlast[NTILE];
__device__ float gAcum[NTILE * 64];

// fp16 operand scratch
__device__ __half gXh[NTOK * DMOD];
__device__ __half gWcat[PROJN * DMOD];
__device__ __half gWo[DMOD * DMOD];
__device__ __half gYa[NTOK * DMOD];

// ---------------------------------------------------------------------------
// PTX helpers
// ---------------------------------------------------------------------------
__device__ __forceinline__ uint32_t smem_u32(const void* p) {
    uint32_t a;
    asm("{ .reg .u64 t; cvta.to.shared.u64 t, %1; cvt.u32.u64 %0, t; }" : "=r"(a) : "l"(p));
    return a;
}
#define SW128(o) ((o) ^ (((o) >> 3) & 0x70))

__device__ __forceinline__ void cp16(uint32_t dst, const void* src) {
    asm volatile("cp.async.cg.shared.global [%0], [%1], 16;\n" :: "r"(dst), "l"(src));
}
__device__ __forceinline__ void cp_commit() { asm volatile("cp.async.commit_group;\n" ::: "memory"); }
template <int N> __device__ __forceinline__ void cp_wait() {
    asm volatile("cp.async.wait_group %0;\n" :: "n"(N) : "memory");
}
__device__ __forceinline__ void ldsm4(uint32_t* r, uint32_t addr) {
    asm volatile("ldmatrix.sync.aligned.m8n8.x4.shared.b16 {%0,%1,%2,%3}, [%4];"
                 : "=r"(r[0]), "=r"(r[1]), "=r"(r[2]), "=r"(r[3]) : "r"(addr));
}
__device__ __forceinline__ void mma_f32(float* d, const uint32_t* a, const uint32_t* b) {
    asm volatile("mma.sync.aligned.m16n8k16.row.col.f32.f16.f16.f32 "
                 "{%0,%1,%2,%3}, {%4,%5,%6,%7}, {%8,%9}, {%0,%1,%2,%3};"
                 : "+f"(d[0]), "+f"(d[1]), "+f"(d[2]), "+f"(d[3])
                 : "r"(a[0]), "r"(a[1]), "r"(a[2]), "r"(a[3]), "r"(b[0]), "r"(b[1]));
}

// ---------------------------------------------------------------------------
// Big GEMM, single-term fp16, 3-stage cp.async, ONE sync per chunk.
// CTA 128x128, 256 thr, 8 warps (4m x 2n, warp tile 32x64), k64 chunks.
// ---------------------------------------------------------------------------
#define OF_A 0
#define OF_B 16384
#define STG  32768
#define GEMM_SMEM (3 * STG)   // 98304

__device__ __forceinline__ void load_rows(uint32_t smem_dst, const __half* g,
                                          int row0, int K, int k0, int t) {
#pragma unroll
    for (int it = 0; it < 4; it++) {
        int p = t + it * 256;
        int r = p >> 3, cc = p & 7;
        uint32_t off = (uint32_t)(r * 128 + cc * 16);
        cp16(smem_dst + SW128(off), g + (size_t)(row0 + r) * K + k0 + cc * 8);
    }
}

__global__ __launch_bounds__(256, 2)
void gemm_mma(const __half* __restrict__ A, const __half* __restrict__ B,
              float* __restrict__ C, int M, int N, int K) {
    extern __shared__ char smem[];
    const uint32_t sb = smem_u32(smem);
    const int t = threadIdx.x;
    const int wid = t >> 5, lane = t & 31;
    const int bm = blockIdx.y * 128;
    const int bn = blockIdx.x * 128;
    const int wm = (wid & 3) * 32;
    const int wn = (wid >> 2) * 64;
    const int nch = K >> 6;

    float acc[2][8][4];
#pragma unroll
    for (int i = 0; i < 2; i++)
#pragma unroll
        for (int j = 0; j < 8; j++)
#pragma unroll
            for (int k = 0; k < 4; k++) acc[i][j][k] = 0.f;

    // prologue: chunks 0,1 -> stages 0,1
#pragma unroll
    for (int pc = 0; pc < 2; pc++) {
        uint32_t st = sb + pc * STG;
        load_rows(st + OF_A, A, bm, K, pc * 64, t);
        load_rows(st + OF_B, B, bn, K, pc * 64, t);
        cp_commit();
    }

    const int ra = (lane & 15);
    const uint32_t ca = (uint32_t)((lane >> 4) << 4);
    const int rb = (lane & 7) + (((lane >> 4) & 1) << 3);
    const uint32_t cb = (uint32_t)(((lane >> 3) & 1) << 4);

    int s0 = 0;
    for (int i = 0; i < nch; i++) {
        // chunk i complete (chunk i+1's group may stay outstanding)
        if (i + 1 < nch) cp_wait<1>(); else cp_wait<0>();
        // one barrier: (a) chunk i visible to all, (b) all warps done with chunk i-1
        __syncthreads();
        // overwrite the stage that held chunk i-1 with chunk i+2
        if (i + 2 < nch) {
            int sl = s0 + 2; if (sl >= 3) sl -= 3;
            uint32_t st2 = sb + sl * STG;
            int k0 = (i + 2) * 64;
            load_rows(st2 + OF_A, A, bm, K, k0, t);
            load_rows(st2 + OF_B, B, bn, K, k0, t);
            cp_commit();
        }
        const uint32_t st = sb + s0 * STG;
#pragma unroll
        for (int kk = 0; kk < 4; kk++) {
            uint32_t af[2][4], bf[4][4];
#pragma unroll
            for (int mi = 0; mi < 2; mi++) {
                int row = wm + mi * 16 + ra;
                ldsm4(af[mi], st + OF_A + SW128((uint32_t)(row * 128 + kk * 32) + ca));
            }
#pragma unroll
            for (int nb = 0; nb < 4; nb++) {
                int rown = wn + nb * 16 + rb;
                ldsm4(bf[nb], st + OF_B + SW128((uint32_t)(rown * 128 + kk * 32) + cb));
            }
#pragma unroll
            for (int mi = 0; mi < 2; mi++)
#pragma unroll
                for (int ni = 0; ni < 8; ni++)
                    mma_f32(acc[mi][ni], af[mi], &bf[ni >> 1][(ni & 1) * 2]);
        }
        if (++s0 == 3) s0 = 0;
    }

#pragma unroll
    for (int mi = 0; mi < 2; mi++) {
        int r0 = bm + wm + mi * 16 + (lane >> 2);
#pragma unroll
        for (int ni = 0; ni < 8; ni++) {
            int c0 = bn + wn + ni * 8 + ((lane & 3) << 1);
            *(float2*)&C[(size_t)r0 * N + c0] = make_float2(acc[mi][ni][0], acc[mi][ni][1]);
            *(float2*)&C[(size_t)(r0 + 8) * N + c0] = make_float2(acc[mi][ni][2], acc[mi][ni][3]);
        }
    }
}

// ---------------------------------------------------------------------------
// Conversions (one launch)
// ---------------------------------------------------------------------------
__device__ __forceinline__ void cvt_s(const float* __restrict__ src,
                                      __half* __restrict__ dst, int i) {
    float4 v = ((const float4*)src)[i];
    __half2* dp = (__half2*)dst;
    dp[2 * i]     = __half2(__float2half(v.x), __float2half(v.y));
    dp[2 * i + 1] = __half2(__float2half(v.z), __float2half(v.w));
}

#define S_X   2097152
#define S_WIN 524288
#define S_WB  262144
#define S_WC  262144
#define S_WDT 4096
#define S_WO  262144
#define S_TOT (S_X + S_WIN + S_WB + S_WC + S_WDT + S_WO)

__global__ __launch_bounds__(256)
void cvt_all(const float* __restrict__ x, const float* __restrict__ Win,
             const float* __restrict__ WB, const float* __restrict__ WC,
             const float* __restrict__ Wdt, const float* __restrict__ Wout) {
    int i = blockIdx.x * 256 + threadIdx.x;
    if (i < S_X) { cvt_s(x, gXh, i); return; }
    i -= S_X;
    if (i < S_WIN) { cvt_s(Win, gWcat, i); return; }
    i -= S_WIN;
    if (i < S_WB) { cvt_s(WB, gWcat + 2048 * DMOD, i); return; }
    i -= S_WB;
    if (i < S_WC) { cvt_s(WC, gWcat + 3072 * DMOD, i); return; }
    i -= S_WC;
    if (i < S_WDT) { cvt_s(Wdt, gWcat + 4096 * DMOD, i); return; }
    i -= S_WDT;
    if (i < S_WO) { cvt_s(Wout, gWo, i); return; }
}

// ---------------------------------------------------------------------------
// SSD tile helpers (64x128B SW128 tiles; lo = (v-hi)*2048)
// ---------------------------------------------------------------------------
__device__ __forceinline__ void stage_rows(float* sStage, const float* __restrict__ src0,
                                           int stride, int t, const float* scale) {
    int l = t >> 1, cbase = (t & 1) * 32;
    const float4* src = (const float4*)(src0 + (size_t)l * stride + cbase);
    float s = scale ? scale[l] : 1.f;
#pragma unroll
    for (int j = 0; j < 8; j++) {
        float4 v = src[j];
        float* d = &sStage[l * 65 + cbase + j * 4];
        d[0] = v.x * s; d[1] = v.y * s; d[2] = v.z * s; d[3] = v.w * s;
    }
}
__device__ __forceinline__ void put_hl(char* tH, char* tL, uint32_t off, float v0, float v1) {
    __half h0 = __float2half(v0), h1 = __float2half(v1);
    *(__half2*)(tH + off) = __half2(h0, h1);
    *(__half2*)(tL + off) = __half2(__float2half((v0 - __half2float(h0)) * LO_SCALE),
                                    __float2half((v1 - __half2float(h1)) * LO_SCALE));
}
__device__ __forceinline__ void conv_direct_global(char* tH, char* tL,
                                                   const float* __restrict__ src0,
                                                   int stride, int t) {
    int l = t >> 1, cbase = (t & 1) * 32;
    const float4* src = (const float4*)(src0 + (size_t)l * stride + cbase);
#pragma unroll
    for (int j = 0; j < 8; j++) {
        float4 v = src[j];
        int c = cbase + j * 4;
        put_hl(tH, tL, SW128((uint32_t)(l * 128 + c * 2)), v.x, v.y);
        put_hl(tH, tL, SW128((uint32_t)(l * 128 + (c + 2) * 2)), v.z, v.w);
    }
}
__device__ __forceinline__ void tile_transpose_hl(char* tH, char* tL, const float* sStage,
                                                  int t, const float* kscale) {
    int o = t >> 1, kbase = (t & 1) * 32;
#pragma unroll
    for (int j = 0; j < 16; j++) {
        int k0 = kbase + 2 * j;
        float v0 = sStage[k0 * 65 + o];
        float v1 = sStage[(k0 + 1) * 65 + o];
        if (kscale) { v0 *= kscale[k0]; v1 *= kscale[k0 + 1]; }
        put_hl(tH, tL, SW128((uint32_t)(o * 128 + k0 * 2)), v0, v1);
    }
}
__device__ __forceinline__ void tile_mma_hl(float accH[8][4], float accM[8][4],
                                            uint32_t aH, uint32_t aL,
                                            uint32_t bH, uint32_t bL,
                                            int wm, int lane) {
    const int ra = (lane & 15);
    const uint32_t ca = (uint32_t)((lane >> 4) << 4);
    const int rb = (lane & 7) + (((lane >> 4) & 1) << 3);
    const uint32_t cb = (uint32_t)(((lane >> 3) & 1) << 4);
#pragma unroll
    for (int kk = 0; kk < 4; kk++) {
        uint32_t ah[4], al[4], bh[4][4], bl[4][4];
        uint32_t aoff = SW128((uint32_t)((wm + ra) * 128 + kk * 32) + ca);
        ldsm4(ah, aH + aoff);
        ldsm4(al, aL + aoff);
#pragma unroll
        for (int nb = 0; nb < 4; nb++) {
            uint32_t boff = SW128((uint32_t)((nb * 16 + rb) * 128 + kk * 32) + cb);
            ldsm4(bh[nb], bH + boff);
            ldsm4(bl[nb], bL + boff);
        }
#pragma unroll
        for (int ni = 0; ni < 8; ni++) {
            const uint32_t* b2h = &bh[ni >> 1][(ni & 1) * 2];
            const uint32_t* b2l = &bl[ni >> 1][(ni & 1) * 2];
            mma_f32(accH[ni], ah, b2h);
            mma_f32(accM[ni], ah, b2l);
            mma_f32(accM[ni], al, b2h);
        }
    }
}

// ---------------------------------------------------------------------------
// SSD pass 1 (unchanged from R10)
// ---------------------------------------------------------------------------
#define P1_SMEM (66048 + 768)
__global__ __launch_bounds__(128)
void ssd_pass1(const float* __restrict__ Alog, const float* __restrict__ bdt) {
    extern __shared__ char sm[];
    float* sStageB = (float*)sm;
    float* sStageX = (float*)(sm + 16640);
    char* sXTh = sm + 33280;
    char* sXTl = sm + 41472;
    char* sBTh = sm + 49664;
    char* sBTl = sm + 57856;
    float* sdt   = (float*)(sm + 66048);
    float* sacum = (float*)(sm + 66048 + 256);
    float* sdec  = (float*)(sm + 66048 + 512);

    const int tile = blockIdx.x;
    const int h = tile & 15;
    const int c = (tile >> 4) & 63;
    const int b = tile >> 10;
    const int t = threadIdx.x;
    const int lane = t & 31, w = t >> 5;
    const int tokb = b * 4096 + c * 64;

    if (t < 64) {
        float v = gProj[(size_t)(tokb + t) * PROJN + 4096 + h] + bdt[h];
        sdt[t] = (v > 20.f) ? v : log1pf(expf(v));
    }
    __syncthreads();
    if (t == 0) {
        float expA = expf(Alog[h]);
        float run = 0.f;
        for (int l = 0; l < 64; l++) { run -= expA * sdt[l]; sacum[l] = run; }
        gAlast[tile] = run;
    }
    __syncthreads();
    if (t < 64) {
        sdec[t] = __expf(sacum[63] - sacum[t]);
        gAcum[tile * 64 + t] = sacum[t];
    }

    stage_rows(sStageB, gProj + (size_t)tokb * PROJN + 2048 + h * 64, PROJN, t, nullptr);
    stage_rows(sStageX, gProj + (size_t)tokb * PROJN + h * 64, PROJN, t, sdt);
    __syncthreads();
    tile_transpose_hl(sBTh, sBTl, sStageB, t, nullptr);
    tile_transpose_hl(sXTh, sXTl, sStageX, t, sdec);
    __syncthreads();

    float accH[8][4], accM[8][4];
#pragma unroll
    for (int i = 0; i < 8; i++)
#pragma unroll
        for (int k = 0; k < 4; k++) { accH[i][k] = 0.f; accM[i][k] = 0.f; }
    tile_mma_hl(accH, accM, smem_u32(sXTh), smem_u32(sXTl),
                smem_u32(sBTh), smem_u32(sBTl), w * 16, lane);

    size_t obase = (size_t)tile * 4096;
    int r = w * 16 + (lane >> 2);
#pragma unroll
    for (int ni = 0; ni < 8; ni++) {
        int cc = ni * 8 + ((lane & 3) << 1);
        *(float2*)&gStates[obase + r * 64 + cc] =
            make_float2(accH[ni][0] + accM[ni][0] * LO_INV_SCALE,
                        accH[ni][1] + accM[ni][1] * LO_INV_SCALE);
        *(float2*)&gStates[obase + (r + 8) * 64 + cc] =
            make_float2(accH[ni][2] + accM[ni][2] * LO_INV_SCALE,
                        accH[ni][3] + accM[ni][3] * LO_INV_SCALE);
    }
}

// ---------------------------------------------------------------------------
// Chunk-level scan: 256 CTAs x 256 thr, 2 elems/thread, prefetched loads,
// decay table in smem.
// ---------------------------------------------------------------------------
__global__ __launch_bounds__(256)
void scan_kernel(float* __restrict__ out_final) {
    __shared__ float sD[64];
    const int blk = blockIdx.x;
    const int bh = blk >> 3;               // 32 (b,h) pairs
    const int b = bh >> 4, h = bh & 15;
    const int e0 = (blk & 7) * 512 + threadIdx.x;   // elems e0, e0+256

    if (threadIdx.x < 64) {
        int tile = (b * 64 + threadIdx.x) * 16 + h;
        sD[threadIdx.x] = expf(gAlast[tile]);
    }
    __syncthreads();

    size_t base = ((size_t)(b * 64 * 16 + h)) * 4096 + e0;
    const size_t step = (size_t)16 * 4096;
    float S0 = 0.f, S1 = 0.f;
    float v0 = gStates[base], v1 = gStates[base + 256];
#pragma unroll 4
    for (int c = 0; c < 64; c++) {
        size_t nbase = base + step;
        float nv0 = 0.f, nv1 = 0.f;
        if (c < 63) { nv0 = gStates[nbase]; nv1 = gStates[nbase + 256]; }
        gStateIn[base]       = S0;
        gStateIn[base + 256] = S1;
        float d = sD[c];
        S0 = S0 * d + v0;
        S1 = S1 * d + v1;
        v0 = nv0; v1 = nv1;
        base = nbase;
    }
    size_t ob = (size_t)Y_ELEMS + (size_t)(b * 16 + h) * 4096 + e0;
    out_final[ob]       = S0;
    out_final[ob + 256] = S1;
}

// ---------------------------------------------------------------------------
// SSD pass 2 (unchanged from R10)
// ---------------------------------------------------------------------------
#define P2_SMEM (98560 + 768)
__global__ __launch_bounds__(128)
void ssd_pass2(const float* __restrict__ bdt) {
    extern __shared__ char sm[];
    float* sStageX = (float*)sm;
    char* sCh = sm + 16640;
    char* sCl = sm + 24832;
    char* sBh = sm + 33024;
    char* sBl = sm + 41216;
    char* sSh = sm + 49408;
    char* sSl = sm + 57600;
    char* sXh = sm + 65792;
    char* sXl = sm + 73984;
    char* sGh = sm + 82176;
    char* sGl = sm + 90368;
    float* sdt   = (float*)(sm + 98560);
    float* sacum = (float*)(sm + 98560 + 256);
    float* seA   = (float*)(sm + 98560 + 512);

    const int tile = blockIdx.x;
    const int h = tile & 15;
    const int c = (tile >> 4) & 63;
    const int b = tile >> 10;
    const int t = threadIdx.x;
    const int lane = t & 31, w = t >> 5;
    const int tokb = b * 4096 + c * 64;

    if (t < 64) {
        float v = gProj[(size_t)(tokb + t) * PROJN + 4096 + h] + bdt[h];
        sdt[t] = (v > 20.f) ? v : log1pf(expf(v));
        float ac = gAcum[tile * 64 + t];
        sacum[t] = ac;
        seA[t] = __expf(ac);
    }
    __syncthreads();

    conv_direct_global(sCh, sCl, gProj + (size_t)tokb * PROJN + 3072 + h * 64, PROJN, t);
    conv_direct_global(sBh, sBl, gProj + (size_t)tokb * PROJN + 2048 + h * 64, PROJN, t);
    conv_direct_global(sSh, sSl, gStateIn + (size_t)tile * 4096, 64, t);
    stage_rows(sStageX, gProj + (size_t)tokb * PROJN + h * 64, PROJN, t, sdt);
    __syncthreads();
    tile_transpose_hl(sXh, sXl, sStageX, t, nullptr);
    __syncthreads();

    {
        float gH[8][4], gM[8][4];
#pragma unroll
        for (int i = 0; i < 8; i++)
#pragma unroll
            for (int k = 0; k < 4; k++) { gH[i][k] = 0.f; gM[i][k] = 0.f; }
        tile_mma_hl(gH, gM, smem_u32(sCh), smem_u32(sCl),
                    smem_u32(sBh), smem_u32(sBl), w * 16, lane);

        int r0 = w * 16 + (lane >> 2);
        int r1 = r0 + 8;
        float a0 = sacum[r0], a1 = sacum[r1];
#pragma unroll
        for (int ni = 0; ni < 8; ni++) {
            int s0 = ni * 8 + ((lane & 3) << 1);
            int s1 = s0 + 1;
            float v00 = gH[ni][0] + gM[ni][0] * LO_INV_SCALE;
            float v01 = gH[ni][1] + gM[ni][1] * LO_INV_SCALE;
            float v10 = gH[ni][2] + gM[ni][2] * LO_INV_SCALE;
            float v11 = gH[ni][3] + gM[ni][3] * LO_INV_SCALE;
            v00 = (s0 <= r0) ? v00 * __expf(a0 - sacum[s0]) : 0.f;
            v01 = (s1 <= r0) ? v01 * __expf(a0 - sacum[s1]) : 0.f;
            v10 = (s0 <= r1) ? v10 * __expf(a1 - sacum[s0]) : 0.f;
            v11 = (s1 <= r1) ? v11 * __expf(a1 - sacum[s1]) : 0.f;
            put_hl(sGh, sGl, SW128((uint32_t)(r0 * 128 + s0 * 2)), v00, v01);
            put_hl(sGh, sGl, SW128((uint32_t)(r1 * 128 + s0 * 2)), v10, v11);
        }
    }
    __syncthreads();

    float yv[8][4];
    {
        float aH[8][4], aM[8][4];
#pragma unroll
        for (int i = 0; i < 8; i++)
#pragma unroll
            for (int k = 0; k < 4; k++) { aH[i][k] = 0.f; aM[i][k] = 0.f; }
        tile_mma_hl(aH, aM, smem_u32(sGh), smem_u32(sGl),
                    smem_u32(sXh), smem_u32(sXl), w * 16, lane);
#pragma unroll
        for (int i = 0; i < 8; i++)
#pragma unroll
            for (int k = 0; k < 4; k++) yv[i][k] = aH[i][k] + aM[i][k] * LO_INV_SCALE;
    }
    {
        float aH[8][4], aM[8][4];
#pragma unroll
        for (int i = 0; i < 8; i++)
#pragma unroll
            for (int k = 0; k < 4; k++) { aH[i][k] = 0.f; aM[i][k] = 0.f; }
        tile_mma_hl(aH, aM, smem_u32(sCh), smem_u32(sCl),
                    smem_u32(sSh), smem_u32(sSl), w * 16, lane);

        int r0 = w * 16 + (lane >> 2);
#pragma unroll
        for (int rr = 0; rr < 2; rr++) {
            int l = r0 + rr * 8;
            float eA = seA[l];
            size_t tok = (size_t)(tokb + l);
            const float* zrow = gProj + tok * PROJN + 1024 + h * 64;
            __half2* yaRow = (__half2*)(gYa + tok * DMOD + h * 64);
#pragma unroll
            for (int ni = 0; ni < 8; ni++) {
                int p = ni * 8 + ((lane & 3) << 1);
                float o0 = aH[ni][rr * 2 + 0] + aM[ni][rr * 2 + 0] * LO_INV_SCALE;
                float o1 = aH[ni][rr * 2 + 1] + aM[ni][rr * 2 + 1] * LO_INV_SCALE;
                float y0 = yv[ni][rr * 2 + 0] + eA * o0;
                float y1 = yv[ni][rr * 2 + 1] + eA * o1;
                float2 z = *(const float2*)&zrow[p];
                y0 *= z.x / (1.f + __expf(-z.x));
                y1 *= z.y / (1.f + __expf(-z.y));
                yaRow[p >> 1] = __half2(__float2half(y0), __float2half(y1));
            }
        }
    }
}

// ---------------------------------------------------------------------------
extern "C" void kernel_launch(void* const* d_in, const int* in_sizes, int n_in,
                              void* d_out, int out_size) {
    const float* x     = (const float*)d_in[0];
    const float* W_in  = (const float*)d_in[1];
    const float* W_dt  = (const float*)d_in[2];
    const float* b_dt  = (const float*)d_in[3];
    const float* W_B   = (const float*)d_in[4];
    const float* W_C   = (const float*)d_in[5];
    const float* W_out = (const float*)d_in[6];
    const float* A_log = (const float*)d_in[7];
    float* out = (float*)d_out;

    void *pProj, *pXh, *pWc, *pWo, *pYa;
    cudaGetSymbolAddress(&pProj, gProj);
    cudaGetSymbolAddress(&pXh, gXh);
    cudaGetSymbolAddress(&pWc, gWcat);
    cudaGetSymbolAddress(&pWo, gWo);
    cudaGetSymbolAddress(&pYa, gYa);

    cudaFuncSetAttribute(gemm_mma, cudaFuncAttributeMaxDynamicSharedMemorySize, GEMM_SMEM);
    cudaFuncSetAttribute(ssd_pass1, cudaFuncAttributeMaxDynamicSharedMemorySize, P1_SMEM);
    cudaFuncSetAttribute(ssd_pass2, cudaFuncAttributeMaxDynamicSharedMemorySize, P2_SMEM);

    // #0: conversions
    cvt_all<<<S_TOT / 256, 256>>>(x, W_in, W_B, W_C, W_dt, W_out);

    // #1: combined projection GEMM
    gemm_mma<<<dim3(PROJN / 128, NTOK / 128), 256, GEMM_SMEM>>>(
        (const __half*)pXh, (const __half*)pWc, (float*)pProj, NTOK, PROJN, DMOD);

    // #2-#4
    ssd_pass1<<<NTILE, 128, P1_SMEM>>>(A_log, b_dt);
    scan_kernel<<<256, 256>>>(out);
    ssd_pass2<<<NTILE, 128, P2_SMEM>>>(b_dt);

    // #5: output GEMM
    gemm_mma<<<dim3(DMOD / 128, NTOK / 128), 256, GEMM_SMEM>>>(
        (const __half*)pYa, (const __half*)pWo, out, NTOK, DMOD, DMOD);
}

// round 12
// speedup vs baseline: 2.5223x; 1.1366x over previous
#include <cuda_runtime.h>
#include <cuda_fp16.h>
#include <math.h>
#include <stdint.h>

#define NTOK   8192
#define DMOD   1024
#define NHEADS 16
#define NTILE  2048
#define Y_ELEMS 8388608
#define PROJN  4224

#define LO_SCALE     2048.0f
#define LO_INV_SCALE (1.0f / 2048.0f)

// fp32 scratch
__device__ float gProj[NTOK * PROJN];
__device__ float gStates[NTILE * 4096];
__device__ float gStateIn[NTILE * 4096];
__device__ float gAlast[NTILE];
__device__ float gAcum[NTILE * 64];

// fp16 operand scratch
__device__ __half gXh[NTOK * DMOD];
__device__ __half gWcat[PROJN * DMOD];
__device__ __half gWo[DMOD * DMOD];
__device__ __half gYa[NTOK * DMOD];

// ---------------------------------------------------------------------------
// PTX helpers
// ---------------------------------------------------------------------------
__device__ __forceinline__ uint32_t smem_u32(const void* p) {
    uint32_t a;
    asm("{ .reg .u64 t; cvta.to.shared.u64 t, %1; cvt.u32.u64 %0, t; }" : "=r"(a) : "l"(p));
    return a;
}
#define SW128(o) ((o) ^ (((o) >> 3) & 0x70))

__device__ __forceinline__ void cp16(uint32_t dst, const void* src) {
    asm volatile("cp.async.cg.shared.global [%0], [%1], 16;\n" :: "r"(dst), "l"(src));
}
__device__ __forceinline__ void cp_commit() { asm volatile("cp.async.commit_group;\n" ::: "memory"); }
template <int N> __device__ __forceinline__ void cp_wait() {
    asm volatile("cp.async.wait_group %0;\n" :: "n"(N) : "memory");
}
__device__ __forceinline__ void ldsm4(uint32_t* r, uint32_t addr) {
    asm volatile("ldmatrix.sync.aligned.m8n8.x4.shared.b16 {%0,%1,%2,%3}, [%4];"
                 : "=r"(r[0]), "=r"(r[1]), "=r"(r[2]), "=r"(r[3]) : "r"(addr));
}
__device__ __forceinline__ void mma_f32(float* d, const uint32_t* a, const uint32_t* b) {
    asm volatile("mma.sync.aligned.m16n8k16.row.col.f32.f16.f16.f32 "
                 "{%0,%1,%2,%3}, {%4,%5,%6,%7}, {%8,%9}, {%0,%1,%2,%3};"
                 : "+f"(d[0]), "+f"(d[1]), "+f"(d[2]), "+f"(d[3])
                 : "r"(a[0]), "r"(a[1]), "r"(a[2]), "r"(a[3]), "r"(b[0]), "r"(b[1]));
}

// ---------------------------------------------------------------------------
// Big GEMM (unchanged from R11 — at HMMA issue cap)
// ---------------------------------------------------------------------------
#define OF_A 0
#define OF_B 16384
#define STG  32768
#define GEMM_SMEM (3 * STG)

__device__ __forceinline__ void load_rows(uint32_t smem_dst, const __half* g,
                                          int row0, int K, int k0, int t) {
#pragma unroll
    for (int it = 0; it < 4; it++) {
        int p = t + it * 256;
        int r = p >> 3, cc = p & 7;
        uint32_t off = (uint32_t)(r * 128 + cc * 16);
        cp16(smem_dst + SW128(off), g + (size_t)(row0 + r) * K + k0 + cc * 8);
    }
}

__global__ __launch_bounds__(256, 2)
void gemm_mma(const __half* __restrict__ A, const __half* __restrict__ B,
              float* __restrict__ C, int M, int N, int K) {
    extern __shared__ char smem[];
    const uint32_t sb = smem_u32(smem);
    const int t = threadIdx.x;
    const int wid = t >> 5, lane = t & 31;
    const int bm = blockIdx.y * 128;
    const int bn = blockIdx.x * 128;
    const int wm = (wid & 3) * 32;
    const int wn = (wid >> 2) * 64;
    const int nch = K >> 6;

    float acc[2][8][4];
#pragma unroll
    for (int i = 0; i < 2; i++)
#pragma unroll
        for (int j = 0; j < 8; j++)
#pragma unroll
            for (int k = 0; k < 4; k++) acc[i][j][k] = 0.f;

#pragma unroll
    for (int pc = 0; pc < 2; pc++) {
        uint32_t st = sb + pc * STG;
        load_rows(st + OF_A, A, bm, K, pc * 64, t);
        load_rows(st + OF_B, B, bn, K, pc * 64, t);
        cp_commit();
    }

    const int ra = (lane & 15);
    const uint32_t ca = (uint32_t)((lane >> 4) << 4);
    const int rb = (lane & 7) + (((lane >> 4) & 1) << 3);
    const uint32_t cb = (uint32_t)(((lane >> 3) & 1) << 4);

    int s0 = 0;
    for (int i = 0; i < nch; i++) {
        if (i + 1 < nch) cp_wait<1>(); else cp_wait<0>();
        __syncthreads();
        if (i + 2 < nch) {
            int sl = s0 + 2; if (sl >= 3) sl -= 3;
            uint32_t st2 = sb + sl * STG;
            int k0 = (i + 2) * 64;
            load_rows(st2 + OF_A, A, bm, K, k0, t);
            load_rows(st2 + OF_B, B, bn, K, k0, t);
            cp_commit();
        }
        const uint32_t st = sb + s0 * STG;
#pragma unroll
        for (int kk = 0; kk < 4; kk++) {
            uint32_t af[2][4], bf[4][4];
#pragma unroll
            for (int mi = 0; mi < 2; mi++) {
                int row = wm + mi * 16 + ra;
                ldsm4(af[mi], st + OF_A + SW128((uint32_t)(row * 128 + kk * 32) + ca));
            }
#pragma unroll
            for (int nb = 0; nb < 4; nb++) {
                int rown = wn + nb * 16 + rb;
                ldsm4(bf[nb], st + OF_B + SW128((uint32_t)(rown * 128 + kk * 32) + cb));
            }
#pragma unroll
            for (int mi = 0; mi < 2; mi++)
#pragma unroll
                for (int ni = 0; ni < 8; ni++)
                    mma_f32(acc[mi][ni], af[mi], &bf[ni >> 1][(ni & 1) * 2]);
        }
        if (++s0 == 3) s0 = 0;
    }

#pragma unroll
    for (int mi = 0; mi < 2; mi++) {
        int r0 = bm + wm + mi * 16 + (lane >> 2);
#pragma unroll
        for (int ni = 0; ni < 8; ni++) {
            int c0 = bn + wn + ni * 8 + ((lane & 3) << 1);
            *(float2*)&C[(size_t)r0 * N + c0] = make_float2(acc[mi][ni][0], acc[mi][ni][1]);
            *(float2*)&C[(size_t)(r0 + 8) * N + c0] = make_float2(acc[mi][ni][2], acc[mi][ni][3]);
        }
    }
}

// ---------------------------------------------------------------------------
// Conversions (one launch)
// ---------------------------------------------------------------------------
__device__ __forceinline__ void cvt_s(const float* __restrict__ src,
                                      __half* __restrict__ dst, int i) {
    float4 v = ((const float4*)src)[i];
    __half2* dp = (__half2*)dst;
    dp[2 * i]     = __half2(__float2half(v.x), __float2half(v.y));
    dp[2 * i + 1] = __half2(__float2half(v.z), __float2half(v.w));
}

#define S_X   2097152
#define S_WIN 524288
#define S_WB  262144
#define S_WC  262144
#define S_WDT 4096
#define S_WO  262144
#define S_TOT (S_X + S_WIN + S_WB + S_WC + S_WDT + S_WO)

__global__ __launch_bounds__(256)
void cvt_all(const float* __restrict__ x, const float* __restrict__ Win,
             const float* __restrict__ WB, const float* __restrict__ WC,
             const float* __restrict__ Wdt, const float* __restrict__ Wout) {
    int i = blockIdx.x * 256 + threadIdx.x;
    if (i < S_X) { cvt_s(x, gXh, i); return; }
    i -= S_X;
    if (i < S_WIN) { cvt_s(Win, gWcat, i); return; }
    i -= S_WIN;
    if (i < S_WB) { cvt_s(WB, gWcat + 2048 * DMOD, i); return; }
    i -= S_WB;
    if (i < S_WC) { cvt_s(WC, gWcat + 3072 * DMOD, i); return; }
    i -= S_WC;
    if (i < S_WDT) { cvt_s(Wdt, gWcat + 4096 * DMOD, i); return; }
    i -= S_WDT;
    if (i < S_WO) { cvt_s(Wout, gWo, i); return; }
}

// ---------------------------------------------------------------------------
// SSD helpers, 256-thread variants. Tiles: 64 rows x 128B SW128; lo = (v-hi)*2048.
// ---------------------------------------------------------------------------
__device__ __forceinline__ void put_hl(char* tH, char* tL, uint32_t off, float v0, float v1) {
    __half h0 = __float2half(v0), h1 = __float2half(v1);
    *(__half2*)(tH + off) = __half2(h0, h1);
    *(__half2*)(tL + off) = __half2(__float2half((v0 - __half2float(h0)) * LO_SCALE),
                                    __float2half((v1 - __half2float(h1)) * LO_SCALE));
}
// 256 threads: thread handles row t>>2, 16 cols starting (t&3)*16
__device__ __forceinline__ void stage_rows256(float* sStage, const float* __restrict__ src0,
                                              int stride, int t, const float* scale) {
    int l = t >> 2, cbase = (t & 3) * 16;
    const float4* src = (const float4*)(src0 + (size_t)l * stride + cbase);
    float s = scale ? scale[l] : 1.f;
#pragma unroll
    for (int j = 0; j < 4; j++) {
        float4 v = src[j];
        float* d = &sStage[l * 65 + cbase + j * 4];
        d[0] = v.x * s; d[1] = v.y * s; d[2] = v.z * s; d[3] = v.w * s;
    }
}
__device__ __forceinline__ void conv_direct_global256(char* tH, char* tL,
                                                      const float* __restrict__ src0,
                                                      int stride, int t) {
    int l = t >> 2, cbase = (t & 3) * 16;
    const float4* src = (const float4*)(src0 + (size_t)l * stride + cbase);
#pragma unroll
    for (int j = 0; j < 4; j++) {
        float4 v = src[j];
        int c = cbase + j * 4;
        put_hl(tH, tL, SW128((uint32_t)(l * 128 + c * 2)), v.x, v.y);
        put_hl(tH, tL, SW128((uint32_t)(l * 128 + (c + 2) * 2)), v.z, v.w);
    }
}
__device__ __forceinline__ void tile_transpose_hl256(char* tH, char* tL, const float* sStage,
                                                     int t, const float* kscale) {
    int o = t >> 2, kbase = (t & 3) * 16;
#pragma unroll
    for (int j = 0; j < 8; j++) {
        int k0 = kbase + 2 * j;
        float v0 = sStage[k0 * 65 + o];
        float v1 = sStage[(k0 + 1) * 65 + o];
        if (kscale) { v0 *= kscale[k0]; v1 *= kscale[k0 + 1]; }
        put_hl(tH, tL, SW128((uint32_t)(o * 128 + k0 * 2)), v0, v1);
    }
}
// 8-warp quadrant MMA: warp computes rows [wm,wm+16) x cols [wn2,wn2+32), 3-term
__device__ __forceinline__ void tile_mma8(float accH[4][4], float accM[4][4],
                                          uint32_t aH, uint32_t aL,
                                          uint32_t bH, uint32_t bL,
                                          int wm, int wn2, int lane) {
    const int ra = (lane & 15);
    const uint32_t ca = (uint32_t)((lane >> 4) << 4);
    const int rb = (lane & 7) + (((lane >> 4) & 1) << 3);
    const uint32_t cb = (uint32_t)(((lane >> 3) & 1) << 4);
    const int nb0 = wn2 >> 4;   // first 16-col group index (0 or 2)
#pragma unroll
    for (int kk = 0; kk < 4; kk++) {
        uint32_t ah[4], al[4], bh[2][4], bl[2][4];
        uint32_t aoff = SW128((uint32_t)((wm + ra) * 128 + kk * 32) + ca);
        ldsm4(ah, aH + aoff);
        ldsm4(al, aL + aoff);
#pragma unroll
        for (int nb = 0; nb < 2; nb++) {
            uint32_t boff = SW128((uint32_t)(((nb0 + nb) * 16 + rb) * 128 + kk * 32) + cb);
            ldsm4(bh[nb], bH + boff);
            ldsm4(bl[nb], bL + boff);
        }
#pragma unroll
        for (int ni = 0; ni < 4; ni++) {
            const uint32_t* b2h = &bh[ni >> 1][(ni & 1) * 2];
            const uint32_t* b2l = &bl[ni >> 1][(ni & 1) * 2];
            mma_f32(accH[ni], ah, b2h);
            mma_f32(accM[ni], ah, b2l);
            mma_f32(accM[ni], al, b2h);
        }
    }
}

// ---------------------------------------------------------------------------
// SSD pass 1 (256 threads): states = (X*dt*dec)^T . B, 3-term.
// smem: stageB 0 | stageX 16640 | XTh 33280 | XTl 41472 | BTh 49664
//       | BTl 57856 | sc 66048
// ---------------------------------------------------------------------------
#define P1_SMEM (66048 + 768)
__global__ __launch_bounds__(256)
void ssd_pass1(const float* __restrict__ Alog, const float* __restrict__ bdt) {
    extern __shared__ char sm[];
    float* sStageB = (float*)sm;
    float* sStageX = (float*)(sm + 16640);
    char* sXTh = sm + 33280;
    char* sXTl = sm + 41472;
    char* sBTh = sm + 49664;
    char* sBTl = sm + 57856;
    float* sdt   = (float*)(sm + 66048);
    float* sacum = (float*)(sm + 66048 + 256);
    float* sdec  = (float*)(sm + 66048 + 512);

    const int tile = blockIdx.x;
    const int h = tile & 15;
    const int c = (tile >> 4) & 63;
    const int b = tile >> 10;
    const int t = threadIdx.x;
    const int lane = t & 31, w = t >> 5;
    const int tokb = b * 4096 + c * 64;
    const int wm = (w & 3) * 16, wn2 = (w >> 2) * 32;

    if (t < 64) {
        float v = gProj[(size_t)(tokb + t) * PROJN + 4096 + h] + bdt[h];
        sdt[t] = (v > 20.f) ? v : log1pf(expf(v));
    }
    __syncthreads();
    if (t == 0) {
        float expA = expf(Alog[h]);
        float run = 0.f;
        for (int l = 0; l < 64; l++) { run -= expA * sdt[l]; sacum[l] = run; }
        gAlast[tile] = run;
    }
    __syncthreads();
    if (t < 64) {
        sdec[t] = __expf(sacum[63] - sacum[t]);
        gAcum[tile * 64 + t] = sacum[t];
    }

    stage_rows256(sStageB, gProj + (size_t)tokb * PROJN + 2048 + h * 64, PROJN, t, nullptr);
    stage_rows256(sStageX, gProj + (size_t)tokb * PROJN + h * 64, PROJN, t, sdt);
    __syncthreads();
    tile_transpose_hl256(sBTh, sBTl, sStageB, t, nullptr);
    tile_transpose_hl256(sXTh, sXTl, sStageX, t, sdec);
    __syncthreads();

    float accH[4][4], accM[4][4];
#pragma unroll
    for (int i = 0; i < 4; i++)
#pragma unroll
        for (int k = 0; k < 4; k++) { accH[i][k] = 0.f; accM[i][k] = 0.f; }
    tile_mma8(accH, accM, smem_u32(sXTh), smem_u32(sXTl),
              smem_u32(sBTh), smem_u32(sBTl), wm, wn2, lane);

    size_t obase = (size_t)tile * 4096;
    int r = wm + (lane >> 2);
#pragma unroll
    for (int ni = 0; ni < 4; ni++) {
        int cc = wn2 + ni * 8 + ((lane & 3) << 1);
        *(float2*)&gStates[obase + r * 64 + cc] =
            make_float2(accH[ni][0] + accM[ni][0] * LO_INV_SCALE,
                        accH[ni][1] + accM[ni][1] * LO_INV_SCALE);
        *(float2*)&gStates[obase + (r + 8) * 64 + cc] =
            make_float2(accH[ni][2] + accM[ni][2] * LO_INV_SCALE,
                        accH[ni][3] + accM[ni][3] * LO_INV_SCALE);
    }
}

// ---------------------------------------------------------------------------
// Chunk-level scan: 512 CTAs x 256 thr, 1 elem/thread, prefetch + decay table
// ---------------------------------------------------------------------------
__global__ __launch_bounds__(256)
void scan_kernel(float* __restrict__ out_final) {
    __shared__ float sD[64];
    const int blk = blockIdx.x;
    const int bh = blk >> 4;               // 32 (b,h) pairs
    const int b = bh >> 4, h = bh & 15;
    const int e0 = ((blk & 15) << 8) | threadIdx.x;

    if (threadIdx.x < 64) {
        int tile = (b * 64 + threadIdx.x) * 16 + h;
        sD[threadIdx.x] = expf(gAlast[tile]);
    }
    __syncthreads();

    size_t base = ((size_t)(b * 64 * 16 + h)) * 4096 + e0;
    const size_t step = (size_t)16 * 4096;
    float S = 0.f;
    float v = gStates[base];
#pragma unroll 4
    for (int c = 0; c < 64; c++) {
        float nv = 0.f;
        if (c < 63) nv = gStates[base + step];
        gStateIn[base] = S;
        S = S * sD[c] + v;
        v = nv;
        base += step;
    }
    out_final[(size_t)Y_ELEMS + (size_t)(b * 16 + h) * 4096 + e0] = S;
}

// ---------------------------------------------------------------------------
// SSD pass 2 (256 threads): G = C.B^T (mask/exp); Y = G.X^T; O = C.S^T;
// y = (Y + eA*O)*silu(z) -> fp16 Ya. Each warp owns a 16x32 quadrant.
// smem: stageX 0 | Ch 16640 | Cl 24832 | Bh 33024 | Bl 41216 | Sh 49408
//       | Sl 57600 | Xh 65792 | Xl 73984 | Gh 82176 | Gl 90368 | sc 98560
// ---------------------------------------------------------------------------
#define P2_SMEM (98560 + 768)
__global__ __launch_bounds__(256)
void ssd_pass2(const float* __restrict__ bdt) {
    extern __shared__ char sm[];
    float* sStageX = (float*)sm;
    char* sCh = sm + 16640;
    char* sCl = sm + 24832;
    char* sBh = sm + 33024;
    char* sBl = sm + 41216;
    char* sSh = sm + 49408;
    char* sSl = sm + 57600;
    char* sXh = sm + 65792;
    char* sXl = sm + 73984;
    char* sGh = sm + 82176;
    char* sGl = sm + 90368;
    float* sdt   = (float*)(sm + 98560);
    float* sacum = (float*)(sm + 98560 + 256);
    float* seA   = (float*)(sm + 98560 + 512);

    const int tile = blockIdx.x;
    const int h = tile & 15;
    const int c = (tile >> 4) & 63;
    const int b = tile >> 10;
    const int t = threadIdx.x;
    const int lane = t & 31, w = t >> 5;
    const int tokb = b * 4096 + c * 64;
    const int wm = (w & 3) * 16, wn2 = (w >> 2) * 32;

    if (t < 64) {
        float v = gProj[(size_t)(tokb + t) * PROJN + 4096 + h] + bdt[h];
        sdt[t] = (v > 20.f) ? v : log1pf(expf(v));
        float ac = gAcum[tile * 64 + t];
        sacum[t] = ac;
        seA[t] = __expf(ac);
    }
    __syncthreads();

    conv_direct_global256(sCh, sCl, gProj + (size_t)tokb * PROJN + 3072 + h * 64, PROJN, t);
    conv_direct_global256(sBh, sBl, gProj + (size_t)tokb * PROJN + 2048 + h * 64, PROJN, t);
    conv_direct_global256(sSh, sSl, gStateIn + (size_t)tile * 4096, 64, t);
    stage_rows256(sStageX, gProj + (size_t)tokb * PROJN + h * 64, PROJN, t, sdt);
    __syncthreads();
    tile_transpose_hl256(sXh, sXl, sStageX, t, nullptr);
    __syncthreads();

    // G = C.B^T (3-term), mask + exp, write hi/lo G tiles (warp-local quadrant)
    {
        float gH[4][4], gM[4][4];
#pragma unroll
        for (int i = 0; i < 4; i++)
#pragma unroll
            for (int k = 0; k < 4; k++) { gH[i][k] = 0.f; gM[i][k] = 0.f; }
        tile_mma8(gH, gM, smem_u32(sCh), smem_u32(sCl),
                  smem_u32(sBh), smem_u32(sBl), wm, wn2, lane);

        int r0 = wm + (lane >> 2);
        int r1 = r0 + 8;
        float a0 = sacum[r0], a1 = sacum[r1];
#pragma unroll
        for (int ni = 0; ni < 4; ni++) {
            int s0 = wn2 + ni * 8 + ((lane & 3) << 1);
            int s1 = s0 + 1;
            float v00 = gH[ni][0] + gM[ni][0] * LO_INV_SCALE;
            float v01 = gH[ni][1] + gM[ni][1] * LO_INV_SCALE;
            float v10 = gH[ni][2] + gM[ni][2] * LO_INV_SCALE;
            float v11 = gH[ni][3] + gM[ni][3] * LO_INV_SCALE;
            v00 = (s0 <= r0) ? v00 * __expf(a0 - sacum[s0]) : 0.f;
            v01 = (s1 <= r0) ? v01 * __expf(a0 - sacum[s1]) : 0.f;
            v10 = (s0 <= r1) ? v10 * __expf(a1 - sacum[s0]) : 0.f;
            v11 = (s1 <= r1) ? v11 * __expf(a1 - sacum[s1]) : 0.f;
            put_hl(sGh, sGl, SW128((uint32_t)(r0 * 128 + s0 * 2)), v00, v01);
            put_hl(sGh, sGl, SW128((uint32_t)(r1 * 128 + s0 * 2)), v10, v11);
        }
    }
    __syncthreads();

    // Y = G.X^T and O = C.S^T (each warp its quadrant), combine, gate, write
    {
        float yH[4][4], yM[4][4], oH[4][4], oM[4][4];
#pragma unroll
        for (int i = 0; i < 4; i++)
#pragma unroll
            for (int k = 0; k < 4; k++) { yH[i][k] = 0.f; yM[i][k] = 0.f; oH[i][k] = 0.f; oM[i][k] = 0.f; }
        tile_mma8(yH, yM, smem_u32(sGh), smem_u32(sGl),
                  smem_u32(sXh), smem_u32(sXl), wm, wn2, lane);
        tile_mma8(oH, oM, smem_u32(sCh), smem_u32(sCl),
                  smem_u32(sSh), smem_u32(sSl), wm, wn2, lane);

        int r0 = wm + (lane >> 2);
#pragma unroll
        for (int rr = 0; rr < 2; rr++) {
            int l = r0 + rr * 8;
            float eA = seA[l];
            size_t tok = (size_t)(tokb + l);
            const float* zrow = gProj + tok * PROJN + 1024 + h * 64;
            __half2* yaRow = (__half2*)(gYa + tok * DMOD + h * 64);
#pragma unroll
            for (int ni = 0; ni < 4; ni++) {
                int p = wn2 + ni * 8 + ((lane & 3) << 1);
                float o0 = oH[ni][rr * 2 + 0] + oM[ni][rr * 2 + 0] * LO_INV_SCALE;
                float o1 = oH[ni][rr * 2 + 1] + oM[ni][rr * 2 + 1] * LO_INV_SCALE;
                float y0 = yH[ni][rr * 2 + 0] + yM[ni][rr * 2 + 0] * LO_INV_SCALE + eA * o0;
                float y1 = yH[ni][rr * 2 + 1] + yM[ni][rr * 2 + 1] * LO_INV_SCALE + eA * o1;
                float2 z = *(const float2*)&zrow[p];
                y0 *= z.x / (1.f + __expf(-z.x));
                y1 *= z.y / (1.f + __expf(-z.y));
                yaRow[p >> 1] = __half2(__float2half(y0), __float2half(y1));
            }
        }
    }
}

// ---------------------------------------------------------------------------
extern "C" void kernel_launch(void* const* d_in, const int* in_sizes, int n_in,
                              void* d_out, int out_size) {
    const float* x     = (const float*)d_in[0];
    const float* W_in  = (const float*)d_in[1];
    const float* W_dt  = (const float*)d_in[2];
    const float* b_dt  = (const float*)d_in[3];
    const float* W_B   = (const float*)d_in[4];
    const float* W_C   = (const float*)d_in[5];
    const float* W_out = (const float*)d_in[6];
    const float* A_log = (const float*)d_in[7];
    float* out = (float*)d_out;

    void *pProj, *pXh, *pWc, *pWo, *pYa;
    cudaGetSymbolAddress(&pProj, gProj);
    cudaGetSymbolAddress(&pXh, gXh);
    cudaGetSymbolAddress(&pWc, gWcat);
    cudaGetSymbolAddress(&pWo, gWo);
    cudaGetSymbolAddress(&pYa, gYa);

    cudaFuncSetAttribute(gemm_mma, cudaFuncAttributeMaxDynamicSharedMemorySize, GEMM_SMEM);
    cudaFuncSetAttribute(ssd_pass1, cudaFuncAttributeMaxDynamicSharedMemorySize, P1_SMEM);
    cudaFuncSetAttribute(ssd_pass2, cudaFuncAttributeMaxDynamicSharedMemorySize, P2_SMEM);

    // #0: conversions
    cvt_all<<<S_TOT / 256, 256>>>(x, W_in, W_B, W_C, W_dt, W_out);

    // #1: combined projection GEMM
    gemm_mma<<<dim3(PROJN / 128, NTOK / 128), 256, GEMM_SMEM>>>(
        (const __half*)pXh, (const __half*)pWc, (float*)pProj, NTOK, PROJN, DMOD);

    // #2-#4
    ssd_pass1<<<NTILE, 256, P1_SMEM>>>(A_log, b_dt);
    scan_kernel<<<512, 256>>>(out);
    ssd_pass2<<<NTILE, 256, P2_SMEM>>>(b_dt);

    // #5: output GEMM
    gemm_mma<<<dim3(DMOD / 128, NTOK / 128), 256, GEMM_SMEM>>>(
        (const __half*)pYa, (const __half*)pWo, out, NTOK, DMOD, DMOD);
}

// round 13
// speedup vs baseline: 2.8035x; 1.1115x over previous
#include <cuda_runtime.h>
#include <cuda_fp16.h>
#include <math.h>
#include <stdint.h>

#define NTOK   8192
#define DMOD   1024
#define NHEADS 16
#define NTILE  2048
#define Y_ELEMS 8388608
#define PROJN  4224

// fp32 scratch
__device__ float gProj[NTOK * PROJN];
__device__ float gAlast[NTILE];
__device__ float gAcum[NTILE * 64];

// fp16 scratch
__device__ __half gStates[NTILE * 4096];
__device__ __half gStateIn[NTILE * 4096];
__device__ __half gXh[NTOK * DMOD];
__device__ __half gWcat[PROJN * DMOD];
__device__ __half gWo[DMOD * DMOD];
__device__ __half gYa[NTOK * DMOD];

// ---------------------------------------------------------------------------
// PTX helpers
// ---------------------------------------------------------------------------
__device__ __forceinline__ uint32_t smem_u32(const void* p) {
    uint32_t a;
    asm("{ .reg .u64 t; cvta.to.shared.u64 t, %1; cvt.u32.u64 %0, t; }" : "=r"(a) : "l"(p));
    return a;
}
#define SW128(o) ((o) ^ (((o) >> 3) & 0x70))

__device__ __forceinline__ void cp16(uint32_t dst, const void* src) {
    asm volatile("cp.async.cg.shared.global [%0], [%1], 16;\n" :: "r"(dst), "l"(src));
}
__device__ __forceinline__ void cp_commit() { asm volatile("cp.async.commit_group;\n" ::: "memory"); }
template <int N> __device__ __forceinline__ void cp_wait() {
    asm volatile("cp.async.wait_group %0;\n" :: "n"(N) : "memory");
}
__device__ __forceinline__ void ldsm4(uint32_t* r, uint32_t addr) {
    asm volatile("ldmatrix.sync.aligned.m8n8.x4.shared.b16 {%0,%1,%2,%3}, [%4];"
                 : "=r"(r[0]), "=r"(r[1]), "=r"(r[2]), "=r"(r[3]) : "r"(addr));
}
__device__ __forceinline__ void mma_f32(float* d, const uint32_t* a, const uint32_t* b) {
    asm volatile("mma.sync.aligned.m16n8k16.row.col.f32.f16.f16.f32 "
                 "{%0,%1,%2,%3}, {%4,%5,%6,%7}, {%8,%9}, {%0,%1,%2,%3};"
                 : "+f"(d[0]), "+f"(d[1]), "+f"(d[2]), "+f"(d[3])
                 : "r"(a[0]), "r"(a[1]), "r"(a[2]), "r"(a[3]), "r"(b[0]), "r"(b[1]));
}

// ---------------------------------------------------------------------------
// Big GEMM (unchanged — at HMMA issue cap)
// ---------------------------------------------------------------------------
#define OF_A 0
#define OF_B 16384
#define STG  32768
#define GEMM_SMEM (3 * STG)

__device__ __forceinline__ void load_rows(uint32_t smem_dst, const __half* g,
                                          int row0, int K, int k0, int t) {
#pragma unroll
    for (int it = 0; it < 4; it++) {
        int p = t + it * 256;
        int r = p >> 3, cc = p & 7;
        uint32_t off = (uint32_t)(r * 128 + cc * 16);
        cp16(smem_dst + SW128(off), g + (size_t)(row0 + r) * K + k0 + cc * 8);
    }
}

__global__ __launch_bounds__(256, 2)
void gemm_mma(const __half* __restrict__ A, const __half* __restrict__ B,
              float* __restrict__ C, int M, int N, int K) {
    extern __shared__ char smem[];
    const uint32_t sb = smem_u32(smem);
    const int t = threadIdx.x;
    const int wid = t >> 5, lane = t & 31;
    const int bm = blockIdx.y * 128;
    const int bn = blockIdx.x * 128;
    const int wm = (wid & 3) * 32;
    const int wn = (wid >> 2) * 64;
    const int nch = K >> 6;

    float acc[2][8][4];
#pragma unroll
    for (int i = 0; i < 2; i++)
#pragma unroll
        for (int j = 0; j < 8; j++)
#pragma unroll
            for (int k = 0; k < 4; k++) acc[i][j][k] = 0.f;

#pragma unroll
    for (int pc = 0; pc < 2; pc++) {
        uint32_t st = sb + pc * STG;
        load_rows(st + OF_A, A, bm, K, pc * 64, t);
        load_rows(st + OF_B, B, bn, K, pc * 64, t);
        cp_commit();
    }

    const int ra = (lane & 15);
    const uint32_t ca = (uint32_t)((lane >> 4) << 4);
    const int rb = (lane & 7) + (((lane >> 4) & 1) << 3);
    const uint32_t cb = (uint32_t)(((lane >> 3) & 1) << 4);

    int s0 = 0;
    for (int i = 0; i < nch; i++) {
        if (i + 1 < nch) cp_wait<1>(); else cp_wait<0>();
        __syncthreads();
        if (i + 2 < nch) {
            int sl = s0 + 2; if (sl >= 3) sl -= 3;
            uint32_t st2 = sb + sl * STG;
            int k0 = (i + 2) * 64;
            load_rows(st2 + OF_A, A, bm, K, k0, t);
            load_rows(st2 + OF_B, B, bn, K, k0, t);
            cp_commit();
        }
        const uint32_t st = sb + s0 * STG;
#pragma unroll
        for (int kk = 0; kk < 4; kk++) {
            uint32_t af[2][4], bf[4][4];
#pragma unroll
            for (int mi = 0; mi < 2; mi++) {
                int row = wm + mi * 16 + ra;
                ldsm4(af[mi], st + OF_A + SW128((uint32_t)(row * 128 + kk * 32) + ca));
            }
#pragma unroll
            for (int nb = 0; nb < 4; nb++) {
                int rown = wn + nb * 16 + rb;
                ldsm4(bf[nb], st + OF_B + SW128((uint32_t)(rown * 128 + kk * 32) + cb));
            }
#pragma unroll
            for (int mi = 0; mi < 2; mi++)
#pragma unroll
                for (int ni = 0; ni < 8; ni++)
                    mma_f32(acc[mi][ni], af[mi], &bf[ni >> 1][(ni & 1) * 2]);
        }
        if (++s0 == 3) s0 = 0;
    }

#pragma unroll
    for (int mi = 0; mi < 2; mi++) {
        int r0 = bm + wm + mi * 16 + (lane >> 2);
#pragma unroll
        for (int ni = 0; ni < 8; ni++) {
            int c0 = bn + wn + ni * 8 + ((lane & 3) << 1);
            *(float2*)&C[(size_t)r0 * N + c0] = make_float2(acc[mi][ni][0], acc[mi][ni][1]);
            *(float2*)&C[(size_t)(r0 + 8) * N + c0] = make_float2(acc[mi][ni][2], acc[mi][ni][3]);
        }
    }
}

// ---------------------------------------------------------------------------
// Conversions (one launch)
// ---------------------------------------------------------------------------
__device__ __forceinline__ void cvt_s(const float* __restrict__ src,
                                      __half* __restrict__ dst, int i) {
    float4 v = ((const float4*)src)[i];
    __half2* dp = (__half2*)dst;
    dp[2 * i]     = __half2(__float2half(v.x), __float2half(v.y));
    dp[2 * i + 1] = __half2(__float2half(v.z), __float2half(v.w));
}

#define S_X   2097152
#define S_WIN 524288
#define S_WB  262144
#define S_WC  262144
#define S_WDT 4096
#define S_WO  262144
#define S_TOT (S_X + S_WIN + S_WB + S_WC + S_WDT + S_WO)

__global__ __launch_bounds__(256)
void cvt_all(const float* __restrict__ x, const float* __restrict__ Win,
             const float* __restrict__ WB, const float* __restrict__ WC,
             const float* __restrict__ Wdt, const float* __restrict__ Wout) {
    int i = blockIdx.x * 256 + threadIdx.x;
    if (i < S_X) { cvt_s(x, gXh, i); return; }
    i -= S_X;
    if (i < S_WIN) { cvt_s(Win, gWcat, i); return; }
    i -= S_WIN;
    if (i < S_WB) { cvt_s(WB, gWcat + 2048 * DMOD, i); return; }
    i -= S_WB;
    if (i < S_WC) { cvt_s(WC, gWcat + 3072 * DMOD, i); return; }
    i -= S_WC;
    if (i < S_WDT) { cvt_s(Wdt, gWcat + 4096 * DMOD, i); return; }
    i -= S_WDT;
    if (i < S_WO) { cvt_s(Wout, gWo, i); return; }
}

// ---------------------------------------------------------------------------
// SSD helpers (256 threads, hi-only fp16 tiles: 64 rows x 128B, SW128)
// ---------------------------------------------------------------------------
__device__ __forceinline__ void stage_rows256(float* sStage, const float* __restrict__ src0,
                                              int stride, int t, const float* scale) {
    int l = t >> 2, cbase = (t & 3) * 16;
    const float4* src = (const float4*)(src0 + (size_t)l * stride + cbase);
    float s = scale ? scale[l] : 1.f;
#pragma unroll
    for (int j = 0; j < 4; j++) {
        float4 v = src[j];
        float* d = &sStage[l * 65 + cbase + j * 4];
        d[0] = v.x * s; d[1] = v.y * s; d[2] = v.z * s; d[3] = v.w * s;
    }
}
// fp32 global rows -> hi fp16 swizzled tile
__device__ __forceinline__ void conv_direct_h256(char* tH, const float* __restrict__ src0,
                                                 int stride, int t) {
    int l = t >> 2, cbase = (t & 3) * 16;
    const float4* src = (const float4*)(src0 + (size_t)l * stride + cbase);
#pragma unroll
    for (int j = 0; j < 4; j++) {
        float4 v = src[j];
        int c = cbase + j * 4;
        *(__half2*)(tH + SW128((uint32_t)(l * 128 + c * 2)))       = __floats2half2_rn(v.x, v.y);
        *(__half2*)(tH + SW128((uint32_t)(l * 128 + (c + 2) * 2))) = __floats2half2_rn(v.z, v.w);
    }
}
// fp16 global tile (row-major 64x64) -> swizzled smem tile (raw copy)
__device__ __forceinline__ void copy_tile_h256(char* tH, const __half* __restrict__ g, int t) {
    int l = t >> 2, c2 = (t & 3) * 2;
#pragma unroll
    for (int j = 0; j < 2; j++) {
        int cc = c2 + j;
        uint4 v = *(const uint4*)(g + l * 64 + cc * 8);
        *(uint4*)(tH + SW128((uint32_t)(l * 128 + cc * 16))) = v;
    }
}
// staged fp32 -> transposed hi tile
__device__ __forceinline__ void tile_transpose_h256(char* tH, const float* sStage,
                                                    int t, const float* kscale) {
    int o = t >> 2, kbase = (t & 3) * 16;
#pragma unroll
    for (int j = 0; j < 8; j++) {
        int k0 = kbase + 2 * j;
        float v0 = sStage[k0 * 65 + o];
        float v1 = sStage[(k0 + 1) * 65 + o];
        if (kscale) { v0 *= kscale[k0]; v1 *= kscale[k0 + 1]; }
        *(__half2*)(tH + SW128((uint32_t)(o * 128 + k0 * 2))) = __floats2half2_rn(v0, v1);
    }
}
// 8-warp quadrant MMA, 1-term: rows [wm,wm+16) x cols [wn2,wn2+32)
__device__ __forceinline__ void tile_mma8_1t(float accH[4][4], uint32_t aH, uint32_t bH,
                                             int wm, int wn2, int lane) {
    const int ra = (lane & 15);
    const uint32_t ca = (uint32_t)((lane >> 4) << 4);
    const int rb = (lane & 7) + (((lane >> 4) & 1) << 3);
    const uint32_t cb = (uint32_t)(((lane >> 3) & 1) << 4);
    const int nb0 = wn2 >> 4;
#pragma unroll
    for (int kk = 0; kk < 4; kk++) {
        uint32_t ah[4], bh[2][4];
        ldsm4(ah, aH + SW128((uint32_t)((wm + ra) * 128 + kk * 32) + ca));
#pragma unroll
        for (int nb = 0; nb < 2; nb++)
            ldsm4(bh[nb], bH + SW128((uint32_t)(((nb0 + nb) * 16 + rb) * 128 + kk * 32) + cb));
#pragma unroll
        for (int ni = 0; ni < 4; ni++)
            mma_f32(accH[ni], ah, &bh[ni >> 1][(ni & 1) * 2]);
    }
}

// ---------------------------------------------------------------------------
// SSD pass 1 (256 thr, 1-term): states = (X*dt*dec)^T . B -> fp16 gStates
// smem: stageB 0 | stageX 16640 | XTh 33280 | BTh 41472 | sc 49664
// ---------------------------------------------------------------------------
#define P1_SMEM (49664 + 768)
__global__ __launch_bounds__(256)
void ssd_pass1(const float* __restrict__ Alog, const float* __restrict__ bdt) {
    extern __shared__ char sm[];
    float* sStageB = (float*)sm;
    float* sStageX = (float*)(sm + 16640);
    char* sXTh = sm + 33280;
    char* sBTh = sm + 41472;
    float* sdt   = (float*)(sm + 49664);
    float* sacum = (float*)(sm + 49664 + 256);
    float* sdec  = (float*)(sm + 49664 + 512);

    const int tile = blockIdx.x;
    const int h = tile & 15;
    const int c = (tile >> 4) & 63;
    const int b = tile >> 10;
    const int t = threadIdx.x;
    const int lane = t & 31, w = t >> 5;
    const int tokb = b * 4096 + c * 64;
    const int wm = (w & 3) * 16, wn2 = (w >> 2) * 32;

    if (t < 64) {
        float v = gProj[(size_t)(tokb + t) * PROJN + 4096 + h] + bdt[h];
        sdt[t] = (v > 20.f) ? v : log1pf(expf(v));
    }
    __syncthreads();
    if (t == 0) {
        float expA = expf(Alog[h]);
        float run = 0.f;
        for (int l = 0; l < 64; l++) { run -= expA * sdt[l]; sacum[l] = run; }
        gAlast[tile] = run;
    }
    __syncthreads();
    if (t < 64) {
        sdec[t] = __expf(sacum[63] - sacum[t]);
        gAcum[tile * 64 + t] = sacum[t];
    }

    stage_rows256(sStageB, gProj + (size_t)tokb * PROJN + 2048 + h * 64, PROJN, t, nullptr);
    stage_rows256(sStageX, gProj + (size_t)tokb * PROJN + h * 64, PROJN, t, sdt);
    __syncthreads();
    tile_transpose_h256(sBTh, sStageB, t, nullptr);
    tile_transpose_h256(sXTh, sStageX, t, sdec);
    __syncthreads();

    float accH[4][4];
#pragma unroll
    for (int i = 0; i < 4; i++)
#pragma unroll
        for (int k = 0; k < 4; k++) accH[i][k] = 0.f;
    tile_mma8_1t(accH, smem_u32(sXTh), smem_u32(sBTh), wm, wn2, lane);

    size_t obase = (size_t)tile * 4096;
    int r = wm + (lane >> 2);
#pragma unroll
    for (int ni = 0; ni < 4; ni++) {
        int cc = wn2 + ni * 8 + ((lane & 3) << 1);
        *(__half2*)&gStates[obase + r * 64 + cc] = __floats2half2_rn(accH[ni][0], accH[ni][1]);
        *(__half2*)&gStates[obase + (r + 8) * 64 + cc] = __floats2half2_rn(accH[ni][2], accH[ni][3]);
    }
}

// ---------------------------------------------------------------------------
// Chunk-level scan (fp16 states): 512 CTAs x 256 thr, prefetch + decay table
// ---------------------------------------------------------------------------
__global__ __launch_bounds__(256)
void scan_kernel(float* __restrict__ out_final) {
    __shared__ float sD[64];
    const int blk = blockIdx.x;
    const int bh = blk >> 4;
    const int b = bh >> 4, h = bh & 15;
    const int e0 = ((blk & 15) << 8) | threadIdx.x;

    if (threadIdx.x < 64) {
        int tile = (b * 64 + threadIdx.x) * 16 + h;
        sD[threadIdx.x] = expf(gAlast[tile]);
    }
    __syncthreads();

    size_t base = ((size_t)(b * 64 * 16 + h)) * 4096 + e0;
    const size_t step = (size_t)16 * 4096;
    float S = 0.f;
    float v = __half2float(gStates[base]);
#pragma unroll 4
    for (int c = 0; c < 64; c++) {
        float nv = 0.f;
        if (c < 63) nv = __half2float(gStates[base + step]);
        gStateIn[base] = __float2half(S);
        S = S * sD[c] + v;
        v = nv;
        base += step;
    }
    out_final[(size_t)Y_ELEMS + (size_t)(b * 16 + h) * 4096 + e0] = S;
}

// ---------------------------------------------------------------------------
// SSD pass 2 (256 thr, 1-term): G = C.B^T (mask/exp); Y = G.X^T; O = C.S^T;
// y = (Y + eA*O)*silu(z) -> fp16 Ya.
// smem: stageX 0 | Ch 16640 | Bh 24832 | Sh 33024 | Xh 41216 | Gh 49408 | sc 57600
// ---------------------------------------------------------------------------
#define P2_SMEM (57600 + 768)
__global__ __launch_bounds__(256)
void ssd_pass2(const float* __restrict__ bdt) {
    extern __shared__ char sm[];
    float* sStageX = (float*)sm;
    char* sCh = sm + 16640;
    char* sBh = sm + 24832;
    char* sSh = sm + 33024;
    char* sXh = sm + 41216;
    char* sGh = sm + 49408;
    float* sdt   = (float*)(sm + 57600);
    float* sacum = (float*)(sm + 57600 + 256);
    float* seA   = (float*)(sm + 57600 + 512);

    const int tile = blockIdx.x;
    const int h = tile & 15;
    const int c = (tile >> 4) & 63;
    const int b = tile >> 10;
    const int t = threadIdx.x;
    const int lane = t & 31, w = t >> 5;
    const int tokb = b * 4096 + c * 64;
    const int wm = (w & 3) * 16, wn2 = (w >> 2) * 32;

    if (t < 64) {
        float v = gProj[(size_t)(tokb + t) * PROJN + 4096 + h] + bdt[h];
        sdt[t] = (v > 20.f) ? v : log1pf(expf(v));
        float ac = gAcum[tile * 64 + t];
        sacum[t] = ac;
        seA[t] = __expf(ac);
    }
    __syncthreads();

    conv_direct_h256(sCh, gProj + (size_t)tokb * PROJN + 3072 + h * 64, PROJN, t);
    conv_direct_h256(sBh, gProj + (size_t)tokb * PROJN + 2048 + h * 64, PROJN, t);
    copy_tile_h256(sSh, gStateIn + (size_t)tile * 4096, t);
    stage_rows256(sStageX, gProj + (size_t)tokb * PROJN + h * 64, PROJN, t, sdt);
    __syncthreads();
    tile_transpose_h256(sXh, sStageX, t, nullptr);
    __syncthreads();

    // G = C.B^T, mask + exp, write hi G tile (warp-local quadrant)
    {
        float gH[4][4];
#pragma unroll
        for (int i = 0; i < 4; i++)
#pragma unroll
            for (int k = 0; k < 4; k++) gH[i][k] = 0.f;
        tile_mma8_1t(gH, smem_u32(sCh), smem_u32(sBh), wm, wn2, lane);

        int r0 = wm + (lane >> 2);
        int r1 = r0 + 8;
        float a0 = sacum[r0], a1 = sacum[r1];
#pragma unroll
        for (int ni = 0; ni < 4; ni++) {
            int s0 = wn2 + ni * 8 + ((lane & 3) << 1);
            int s1 = s0 + 1;
            float v00 = (s0 <= r0) ? gH[ni][0] * __expf(a0 - sacum[s0]) : 0.f;
            float v01 = (s1 <= r0) ? gH[ni][1] * __expf(a0 - sacum[s1]) : 0.f;
            float v10 = (s0 <= r1) ? gH[ni][2] * __expf(a1 - sacum[s0]) : 0.f;
            float v11 = (s1 <= r1) ? gH[ni][3] * __expf(a1 - sacum[s1]) : 0.f;
            *(__half2*)(sGh + SW128((uint32_t)(r0 * 128 + s0 * 2))) = __floats2half2_rn(v00, v01);
            *(__half2*)(sGh + SW128((uint32_t)(r1 * 128 + s0 * 2))) = __floats2half2_rn(v10, v11);
        }
    }
    __syncthreads();

    // Y = G.X^T ; O = C.S^T ; combine, gate, write fp16 Ya
    {
        float yH[4][4], oH[4][4];
#pragma unroll
        for (int i = 0; i < 4; i++)
#pragma unroll
            for (int k = 0; k < 4; k++) { yH[i][k] = 0.f; oH[i][k] = 0.f; }
        tile_mma8_1t(yH, smem_u32(sGh), smem_u32(sXh), wm, wn2, lane);
        tile_mma8_1t(oH, smem_u32(sCh), smem_u32(sSh), wm, wn2, lane);

        int r0 = wm + (lane >> 2);
#pragma unroll
        for (int rr = 0; rr < 2; rr++) {
            int l = r0 + rr * 8;
            float eA = seA[l];
            size_t tok = (size_t)(tokb + l);
            const float* zrow = gProj + tok * PROJN + 1024 + h * 64;
            __half2* yaRow = (__half2*)(gYa + tok * DMOD + h * 64);
#pragma unroll
            for (int ni = 0; ni < 4; ni++) {
                int p = wn2 + ni * 8 + ((lane & 3) << 1);
                float y0 = yH[ni][rr * 2 + 0] + eA * oH[ni][rr * 2 + 0];
                float y1 = yH[ni][rr * 2 + 1] + eA * oH[ni][rr * 2 + 1];
                float2 z = *(const float2*)&zrow[p];
                y0 *= z.x / (1.f + __expf(-z.x));
                y1 *= z.y / (1.f + __expf(-z.y));
                yaRow[p >> 1] = __half2(__float2half(y0), __float2half(y1));
            }
        }
    }
}

// ---------------------------------------------------------------------------
extern "C" void kernel_launch(void* const* d_in, const int* in_sizes, int n_in,
                              void* d_out, int out_size) {
    const float* x     = (const float*)d_in[0];
    const float* W_in  = (const float*)d_in[1];
    const float* W_dt  = (const float*)d_in[2];
    const float* b_dt  = (const float*)d_in[3];
    const float* W_B   = (const float*)d_in[4];
    const float* W_C   = (const float*)d_in[5];
    const float* W_out = (const float*)d_in[6];
    const float* A_log = (const float*)d_in[7];
    float* out = (float*)d_out;

    void *pProj, *pXh, *pWc, *pWo, *pYa;
    cudaGetSymbolAddress(&pProj, gProj);
    cudaGetSymbolAddress(&pXh, gXh);
    cudaGetSymbolAddress(&pWc, gWcat);
    cudaGetSymbolAddress(&pWo, gWo);
    cudaGetSymbolAddress(&pYa, gYa);

    cudaFuncSetAttribute(gemm_mma, cudaFuncAttributeMaxDynamicSharedMemorySize, GEMM_SMEM);
    cudaFuncSetAttribute(ssd_pass1, cudaFuncAttributeMaxDynamicSharedMemorySize, P1_SMEM);
    cudaFuncSetAttribute(ssd_pass2, cudaFuncAttributeMaxDynamicSharedMemorySize, P2_SMEM);

    // #0: conversions
    cvt_all<<<S_TOT / 256, 256>>>(x, W_in, W_B, W_C, W_dt, W_out);

    // #1: combined projection GEMM
    gemm_mma<<<dim3(PROJN / 128, NTOK / 128), 256, GEMM_SMEM>>>(
        (const __half*)pXh, (const __half*)pWc, (float*)pProj, NTOK, PROJN, DMOD);

    // #2-#4
    ssd_pass1<<<NTILE, 256, P1_SMEM>>>(A_log, b_dt);
    scan_kernel<<<512, 256>>>(out);
    ssd_pass2<<<NTILE, 256, P2_SMEM>>>(b_dt);

    // #5: output GEMM
    gemm_mma<<<dim3(DMOD / 128, NTOK / 128), 256, GEMM_SMEM>>>(
        (const __half*)pYa, (const __half*)pWo, out, NTOK, DMOD, DMOD);
}

// round 14
// speedup vs baseline: 2.9975x; 1.0692x over previous
#include <cuda_runtime.h>
#include <cuda_fp16.h>
#include <math.h>
#include <stdint.h>

#define NTOK   8192
#define DMOD   1024
#define NHEADS 16
#define NTILE  2048
#define Y_ELEMS 8388608
#define PROJN  4224     // GEMM N extent: x|z (2048) + B|C (2048) + dt tile (128)
#define PF_W   2176     // gProjF width: x(1024) + z(1024) + dt(16) + pad

// fp32 scratch
__device__ float gProjF[NTOK * PF_W];     // [tok][ x | z | dtraw pad128 ]
__device__ float gAlast[NTILE];
__device__ float gAcum[NTILE * 64];

// fp16 scratch
__device__ __half gBCh[NTOK * 2048];      // [tok][ B(1024) | C(1024) ]
__device__ __half gStates[NTILE * 4096];
__device__ __half gStateIn[NTILE * 4096];
__device__ __half gXh[NTOK * DMOD];
__device__ __half gWcat[PROJN * DMOD];
__device__ __half gWo[DMOD * DMOD];
__device__ __half gYa[NTOK * DMOD];

// ---------------------------------------------------------------------------
// PTX helpers
// ---------------------------------------------------------------------------
__device__ __forceinline__ uint32_t smem_u32(const void* p) {
    uint32_t a;
    asm("{ .reg .u64 t; cvta.to.shared.u64 t, %1; cvt.u32.u64 %0, t; }" : "=r"(a) : "l"(p));
    return a;
}
#define SW128(o) ((o) ^ (((o) >> 3) & 0x70))

__device__ __forceinline__ void cp16(uint32_t dst, const void* src) {
    asm volatile("cp.async.cg.shared.global [%0], [%1], 16;\n" :: "r"(dst), "l"(src));
}
__device__ __forceinline__ void cp_commit() { asm volatile("cp.async.commit_group;\n" ::: "memory"); }
template <int N> __device__ __forceinline__ void cp_wait() {
    asm volatile("cp.async.wait_group %0;\n" :: "n"(N) : "memory");
}
__device__ __forceinline__ void ldsm4(uint32_t* r, uint32_t addr) {
    asm volatile("ldmatrix.sync.aligned.m8n8.x4.shared.b16 {%0,%1,%2,%3}, [%4];"
                 : "=r"(r[0]), "=r"(r[1]), "=r"(r[2]), "=r"(r[3]) : "r"(addr));
}
__device__ __forceinline__ void mma_f32(float* d, const uint32_t* a, const uint32_t* b) {
    asm volatile("mma.sync.aligned.m16n8k16.row.col.f32.f16.f16.f32 "
                 "{%0,%1,%2,%3}, {%4,%5,%6,%7}, {%8,%9}, {%0,%1,%2,%3};"
                 : "+f"(d[0]), "+f"(d[1]), "+f"(d[2]), "+f"(d[3])
                 : "r"(a[0]), "r"(a[1]), "r"(a[2]), "r"(a[3]), "r"(b[0]), "r"(b[1]));
}

// ---------------------------------------------------------------------------
// Big GEMM. proj_mode=1: split epilogue (fp32 x/z/dt into gProjF, fp16 B/C
// into gBCh). proj_mode=0: plain fp32 C.
// ---------------------------------------------------------------------------
#define OF_A 0
#define OF_B 16384
#define STG  32768
#define GEMM_SMEM (3 * STG)

__device__ __forceinline__ void load_rows(uint32_t smem_dst, const __half* g,
                                          int row0, int K, int k0, int t) {
#pragma unroll
    for (int it = 0; it < 4; it++) {
        int p = t + it * 256;
        int r = p >> 3, cc = p & 7;
        uint32_t off = (uint32_t)(r * 128 + cc * 16);
        cp16(smem_dst + SW128(off), g + (size_t)(row0 + r) * K + k0 + cc * 8);
    }
}

__global__ __launch_bounds__(256, 2)
void gemm_mma(const __half* __restrict__ A, const __half* __restrict__ B,
              float* __restrict__ C, int M, int N, int K, int proj_mode) {
    extern __shared__ char smem[];
    const uint32_t sb = smem_u32(smem);
    const int t = threadIdx.x;
    const int wid = t >> 5, lane = t & 31;
    const int bm = blockIdx.y * 128;
    const int bn = blockIdx.x * 128;
    const int wm = (wid & 3) * 32;
    const int wn = (wid >> 2) * 64;
    const int nch = K >> 6;

    float acc[2][8][4];
#pragma unroll
    for (int i = 0; i < 2; i++)
#pragma unroll
        for (int j = 0; j < 8; j++)
#pragma unroll
            for (int k = 0; k < 4; k++) acc[i][j][k] = 0.f;

#pragma unroll
    for (int pc = 0; pc < 2; pc++) {
        uint32_t st = sb + pc * STG;
        load_rows(st + OF_A, A, bm, K, pc * 64, t);
        load_rows(st + OF_B, B, bn, K, pc * 64, t);
        cp_commit();
    }

    const int ra = (lane & 15);
    const uint32_t ca = (uint32_t)((lane >> 4) << 4);
    const int rb = (lane & 7) + (((lane >> 4) & 1) << 3);
    const uint32_t cb = (uint32_t)(((lane >> 3) & 1) << 4);

    int s0 = 0;
    for (int i = 0; i < nch; i++) {
        if (i + 1 < nch) cp_wait<1>(); else cp_wait<0>();
        __syncthreads();
        if (i + 2 < nch) {
            int sl = s0 + 2; if (sl >= 3) sl -= 3;
            uint32_t st2 = sb + sl * STG;
            int k0 = (i + 2) * 64;
            load_rows(st2 + OF_A, A, bm, K, k0, t);
            load_rows(st2 + OF_B, B, bn, K, k0, t);
            cp_commit();
        }
        const uint32_t st = sb + s0 * STG;
#pragma unroll
        for (int kk = 0; kk < 4; kk++) {
            uint32_t af[2][4], bf[4][4];
#pragma unroll
            for (int mi = 0; mi < 2; mi++) {
                int row = wm + mi * 16 + ra;
                ldsm4(af[mi], st + OF_A + SW128((uint32_t)(row * 128 + kk * 32) + ca));
            }
#pragma unroll
            for (int nb = 0; nb < 4; nb++) {
                int rown = wn + nb * 16 + rb;
                ldsm4(bf[nb], st + OF_B + SW128((uint32_t)(rown * 128 + kk * 32) + cb));
            }
#pragma unroll
            for (int mi = 0; mi < 2; mi++)
#pragma unroll
                for (int ni = 0; ni < 8; ni++)
                    mma_f32(acc[mi][ni], af[mi], &bf[ni >> 1][(ni & 1) * 2]);
        }
        if (++s0 == 3) s0 = 0;
    }

    if (!proj_mode) {
#pragma unroll
        for (int mi = 0; mi < 2; mi++) {
            int r0 = bm + wm + mi * 16 + (lane >> 2);
#pragma unroll
            for (int ni = 0; ni < 8; ni++) {
                int c0 = bn + wn + ni * 8 + ((lane & 3) << 1);
                *(float2*)&C[(size_t)r0 * N + c0] = make_float2(acc[mi][ni][0], acc[mi][ni][1]);
                *(float2*)&C[(size_t)(r0 + 8) * N + c0] = make_float2(acc[mi][ni][2], acc[mi][ni][3]);
            }
        }
    } else if (bn < 2048 || bn >= 4096) {
        // fp32 region: x|z at col bn; dt tile at col 2048+(bn-4096)
        int colbase = (bn < 2048) ? bn : (2048 + (bn - 4096));
#pragma unroll
        for (int mi = 0; mi < 2; mi++) {
            size_t r0 = (size_t)(bm + wm + mi * 16 + (lane >> 2));
#pragma unroll
            for (int ni = 0; ni < 8; ni++) {
                int c0 = colbase + wn + ni * 8 + ((lane & 3) << 1);
                *(float2*)&gProjF[r0 * PF_W + c0] = make_float2(acc[mi][ni][0], acc[mi][ni][1]);
                *(float2*)&gProjF[(r0 + 8) * PF_W + c0] = make_float2(acc[mi][ni][2], acc[mi][ni][3]);
            }
        }
    } else {
        // fp16 region: B|C at col bn-2048
        int colbase = bn - 2048;
#pragma unroll
        for (int mi = 0; mi < 2; mi++) {
            size_t r0 = (size_t)(bm + wm + mi * 16 + (lane >> 2));
#pragma unroll
            for (int ni = 0; ni < 8; ni++) {
                int c0 = colbase + wn + ni * 8 + ((lane & 3) << 1);
                *(__half2*)&gBCh[r0 * 2048 + c0] = __floats2half2_rn(acc[mi][ni][0], acc[mi][ni][1]);
                *(__half2*)&gBCh[(r0 + 8) * 2048 + c0] = __floats2half2_rn(acc[mi][ni][2], acc[mi][ni][3]);
            }
        }
    }
}

// ---------------------------------------------------------------------------
// Conversions (one launch)
// ---------------------------------------------------------------------------
__device__ __forceinline__ void cvt_s(const float* __restrict__ src,
                                      __half* __restrict__ dst, int i) {
    float4 v = ((const float4*)src)[i];
    __half2* dp = (__half2*)dst;
    dp[2 * i]     = __half2(__float2half(v.x), __float2half(v.y));
    dp[2 * i + 1] = __half2(__float2half(v.z), __float2half(v.w));
}

#define S_X   2097152
#define S_WIN 524288
#define S_WB  262144
#define S_WC  262144
#define S_WDT 4096
#define S_WO  262144
#define S_TOT (S_X + S_WIN + S_WB + S_WC + S_WDT + S_WO)

__global__ __launch_bounds__(256)
void cvt_all(const float* __restrict__ x, const float* __restrict__ Win,
             const float* __restrict__ WB, const float* __restrict__ WC,
             const float* __restrict__ Wdt, const float* __restrict__ Wout) {
    int i = blockIdx.x * 256 + threadIdx.x;
    if (i < S_X) { cvt_s(x, gXh, i); return; }
    i -= S_X;
    if (i < S_WIN) { cvt_s(Win, gWcat, i); return; }
    i -= S_WIN;
    if (i < S_WB) { cvt_s(WB, gWcat + 2048 * DMOD, i); return; }
    i -= S_WB;
    if (i < S_WC) { cvt_s(WC, gWcat + 3072 * DMOD, i); return; }
    i -= S_WC;
    if (i < S_WDT) { cvt_s(Wdt, gWcat + 4096 * DMOD, i); return; }
    i -= S_WDT;
    if (i < S_WO) { cvt_s(Wout, gWo, i); return; }
}

// ---------------------------------------------------------------------------
// SSD helpers (256 threads, hi-only fp16 tiles: 64 rows x 128B, SW128)
// ---------------------------------------------------------------------------
// fp32 rows -> fp32 staging (optionally scaled per-row)
__device__ __forceinline__ void stage_rows256(float* sStage, const float* __restrict__ src0,
                                              int stride, int t, const float* scale) {
    int l = t >> 2, cbase = (t & 3) * 16;
    const float4* src = (const float4*)(src0 + (size_t)l * stride + cbase);
    float s = scale ? scale[l] : 1.f;
#pragma unroll
    for (int j = 0; j < 4; j++) {
        float4 v = src[j];
        float* d = &sStage[l * 65 + cbase + j * 4];
        d[0] = v.x * s; d[1] = v.y * s; d[2] = v.z * s; d[3] = v.w * s;
    }
}
// fp16 rows -> fp32 staging
__device__ __forceinline__ void stage_rows256_h(float* sStage, const __half* __restrict__ src0,
                                                int strideH, int t) {
    int l = t >> 2, cbase = (t & 3) * 16;
    const __half2* src = (const __half2*)(src0 + (size_t)l * strideH + cbase);
#pragma unroll
    for (int j = 0; j < 8; j++) {
        float2 v = __half22float2(src[j]);
        float* d = &sStage[l * 65 + cbase + j * 2];
        d[0] = v.x; d[1] = v.y;
    }
}
// fp16 global rows -> raw swizzled copy (stride in halves)
__device__ __forceinline__ void copy_tile_h256(char* tH, const __half* __restrict__ g,
                                               int strideH, int t) {
    int l = t >> 2, c2 = (t & 3) * 2;
#pragma unroll
    for (int j = 0; j < 2; j++) {
        int cc = c2 + j;
        uint4 v = *(const uint4*)(g + (size_t)l * strideH + cc * 8);
        *(uint4*)(tH + SW128((uint32_t)(l * 128 + cc * 16))) = v;
    }
}
// staged fp32 -> transposed hi tile
__device__ __forceinline__ void tile_transpose_h256(char* tH, const float* sStage,
                                                    int t, const float* kscale) {
    int o = t >> 2, kbase = (t & 3) * 16;
#pragma unroll
    for (int j = 0; j < 8; j++) {
        int k0 = kbase + 2 * j;
        float v0 = sStage[k0 * 65 + o];
        float v1 = sStage[(k0 + 1) * 65 + o];
        if (kscale) { v0 *= kscale[k0]; v1 *= kscale[k0 + 1]; }
        *(__half2*)(tH + SW128((uint32_t)(o * 128 + k0 * 2))) = __floats2half2_rn(v0, v1);
    }
}
// 8-warp quadrant MMA, 1-term
__device__ __forceinline__ void tile_mma8_1t(float accH[4][4], uint32_t aH, uint32_t bH,
                                             int wm, int wn2, int lane) {
    const int ra = (lane & 15);
    const uint32_t ca = (uint32_t)((lane >> 4) << 4);
    const int rb = (lane & 7) + (((lane >> 4) & 1) << 3);
    const uint32_t cb = (uint32_t)(((lane >> 3) & 1) << 4);
    const int nb0 = wn2 >> 4;
#pragma unroll
    for (int kk = 0; kk < 4; kk++) {
        uint32_t ah[4], bh[2][4];
        ldsm4(ah, aH + SW128((uint32_t)((wm + ra) * 128 + kk * 32) + ca));
#pragma unroll
        for (int nb = 0; nb < 2; nb++)
            ldsm4(bh[nb], bH + SW128((uint32_t)(((nb0 + nb) * 16 + rb) * 128 + kk * 32) + cb));
#pragma unroll
        for (int ni = 0; ni < 4; ni++)
            mma_f32(accH[ni], ah, &bh[ni >> 1][(ni & 1) * 2]);
    }
}

// ---------------------------------------------------------------------------
// SSD pass 1 (256 thr): states = (X*dt*dec)^T . B -> fp16 gStates
// smem: stageB 0 | stageX 16640 | XTh 33280 | BTh 41472 | sc 49664
// ---------------------------------------------------------------------------
#define P1_SMEM (49664 + 768)
__global__ __launch_bounds__(256)
void ssd_pass1(const float* __restrict__ Alog, const float* __restrict__ bdt) {
    extern __shared__ char sm[];
    float* sStageB = (float*)sm;
    float* sStageX = (float*)(sm + 16640);
    char* sXTh = sm + 33280;
    char* sBTh = sm + 41472;
    float* sdt   = (float*)(sm + 49664);
    float* sacum = (float*)(sm + 49664 + 256);
    float* sdec  = (float*)(sm + 49664 + 512);

    const int tile = blockIdx.x;
    const int h = tile & 15;
    const int c = (tile >> 4) & 63;
    const int b = tile >> 10;
    const int t = threadIdx.x;
    const int lane = t & 31, w = t >> 5;
    const int tokb = b * 4096 + c * 64;
    const int wm = (w & 3) * 16, wn2 = (w >> 2) * 32;

    if (t < 64) {
        float v = gProjF[(size_t)(tokb + t) * PF_W + 2048 + h] + bdt[h];
        sdt[t] = (v > 20.f) ? v : log1pf(expf(v));
    }
    __syncthreads();
    if (t == 0) {
        float expA = expf(Alog[h]);
        float run = 0.f;
        for (int l = 0; l < 64; l++) { run -= expA * sdt[l]; sacum[l] = run; }
        gAlast[tile] = run;
    }
    __syncthreads();
    if (t < 64) {
        sdec[t] = __expf(sacum[63] - sacum[t]);
        gAcum[tile * 64 + t] = sacum[t];
    }

    stage_rows256_h(sStageB, gBCh + (size_t)tokb * 2048 + h * 64, 2048, t);
    stage_rows256(sStageX, gProjF + (size_t)tokb * PF_W + h * 64, PF_W, t, sdt);
    __syncthreads();
    tile_transpose_h256(sBTh, sStageB, t, nullptr);
    tile_transpose_h256(sXTh, sStageX, t, sdec);
    __syncthreads();

    float accH[4][4];
#pragma unroll
    for (int i = 0; i < 4; i++)
#pragma unroll
        for (int k = 0; k < 4; k++) accH[i][k] = 0.f;
    tile_mma8_1t(accH, smem_u32(sXTh), smem_u32(sBTh), wm, wn2, lane);

    size_t obase = (size_t)tile * 4096;
    int r = wm + (lane >> 2);
#pragma unroll
    for (int ni = 0; ni < 4; ni++) {
        int cc = wn2 + ni * 8 + ((lane & 3) << 1);
        *(__half2*)&gStates[obase + r * 64 + cc] = __floats2half2_rn(accH[ni][0], accH[ni][1]);
        *(__half2*)&gStates[obase + (r + 8) * 64 + cc] = __floats2half2_rn(accH[ni][2], accH[ni][3]);
    }
}

// ---------------------------------------------------------------------------
// Chunk-level scan (fp16 states): 512 CTAs x 256 thr, prefetch depth 2
// ---------------------------------------------------------------------------
__global__ __launch_bounds__(256)
void scan_kernel(float* __restrict__ out_final) {
    __shared__ float sD[64];
    const int blk = blockIdx.x;
    const int bh = blk >> 4;
    const int b = bh >> 4, h = bh & 15;
    const int e0 = ((blk & 15) << 8) | threadIdx.x;

    if (threadIdx.x < 64) {
        int tile = (b * 64 + threadIdx.x) * 16 + h;
        sD[threadIdx.x] = expf(gAlast[tile]);
    }
    __syncthreads();

    size_t base = ((size_t)(b * 64 * 16 + h)) * 4096 + e0;
    const size_t step = (size_t)16 * 4096;
    float S = 0.f;
    float v0 = __half2float(gStates[base]);
    float v1 = __half2float(gStates[base + step]);
#pragma unroll 4
    for (int c = 0; c < 64; c++) {
        float v2 = 0.f;
        if (c < 62) v2 = __half2float(gStates[base + 2 * step]);
        gStateIn[base] = __float2half(S);
        S = S * sD[c] + v0;
        v0 = v1; v1 = v2;
        base += step;
    }
    out_final[(size_t)Y_ELEMS + (size_t)(b * 16 + h) * 4096 + e0] = S;
}

// ---------------------------------------------------------------------------
// SSD pass 2 (256 thr): G = C.B^T (mask/exp); Y = G.X^T; O = C.S^T;
// y = (Y + eA*O)*silu(z) -> fp16 Ya. C/B/S tiles are raw fp16 copies.
// smem: stageX 0 | Ch 16640 | Bh 24832 | Sh 33024 | Xh 41216 | Gh 49408 | sc 57600
// ---------------------------------------------------------------------------
#define P2_SMEM (57600 + 768)
__global__ __launch_bounds__(256)
void ssd_pass2(const float* __restrict__ bdt) {
    extern __shared__ char sm[];
    float* sStageX = (float*)sm;
    char* sCh = sm + 16640;
    char* sBh = sm + 24832;
    char* sSh = sm + 33024;
    char* sXh = sm + 41216;
    char* sGh = sm + 49408;
    float* sdt   = (float*)(sm + 57600);
    float* sacum = (float*)(sm + 57600 + 256);
    float* seA   = (float*)(sm + 57600 + 512);

    const int tile = blockIdx.x;
    const int h = tile & 15;
    const int c = (tile >> 4) & 63;
    const int b = tile >> 10;
    const int t = threadIdx.x;
    const int lane = t & 31, w = t >> 5;
    const int tokb = b * 4096 + c * 64;
    const int wm = (w & 3) * 16, wn2 = (w >> 2) * 32;

    if (t < 64) {
        float v = gProjF[(size_t)(tokb + t) * PF_W + 2048 + h] + bdt[h];
        sdt[t] = (v > 20.f) ? v : log1pf(expf(v));
        float ac = gAcum[tile * 64 + t];
        sacum[t] = ac;
        seA[t] = __expf(ac);
    }
    __syncthreads();

    copy_tile_h256(sCh, gBCh + (size_t)tokb * 2048 + 1024 + h * 64, 2048, t);
    copy_tile_h256(sBh, gBCh + (size_t)tokb * 2048 + h * 64, 2048, t);
    copy_tile_h256(sSh, gStateIn + (size_t)tile * 4096, 64, t);
    stage_rows256(sStageX, gProjF + (size_t)tokb * PF_W + h * 64, PF_W, t, sdt);
    __syncthreads();
    tile_transpose_h256(sXh, sStageX, t, nullptr);
    __syncthreads();

    // G = C.B^T, mask + exp, write hi G tile (warp-local quadrant)
    {
        float gH[4][4];
#pragma unroll
        for (int i = 0; i < 4; i++)
#pragma unroll
            for (int k = 0; k < 4; k++) gH[i][k] = 0.f;
        tile_mma8_1t(gH, smem_u32(sCh), smem_u32(sBh), wm, wn2, lane);

        int r0 = wm + (lane >> 2);
        int r1 = r0 + 8;
        float a0 = sacum[r0], a1 = sacum[r1];
#pragma unroll
        for (int ni = 0; ni < 4; ni++) {
            int s0 = wn2 + ni * 8 + ((lane & 3) << 1);
            int s1 = s0 + 1;
            float v00 = (s0 <= r0) ? gH[ni][0] * __expf(a0 - sacum[s0]) : 0.f;
            float v01 = (s1 <= r0) ? gH[ni][1] * __expf(a0 - sacum[s1]) : 0.f;
            float v10 = (s0 <= r1) ? gH[ni][2] * __expf(a1 - sacum[s0]) : 0.f;
            float v11 = (s1 <= r1) ? gH[ni][3] * __expf(a1 - sacum[s1]) : 0.f;
            *(__half2*)(sGh + SW128((uint32_t)(r0 * 128 + s0 * 2))) = __floats2half2_rn(v00, v01);
            *(__half2*)(sGh + SW128((uint32_t)(r1 * 128 + s0 * 2))) = __floats2half2_rn(v10, v11);
        }
    }
    __syncthreads();

    // Y = G.X^T ; O = C.S^T ; combine, gate, write fp16 Ya
    {
        float yH[4][4], oH[4][4];
#pragma unroll
        for (int i = 0; i < 4; i++)
#pragma unroll
            for (int k = 0; k < 4; k++) { yH[i][k] = 0.f; oH[i][k] = 0.f; }
        tile_mma8_1t(yH, smem_u32(sGh), smem_u32(sXh), wm, wn2, lane);
        tile_mma8_1t(oH, smem_u32(sCh), smem_u32(sSh), wm, wn2, lane);

        int r0 = wm + (lane >> 2);
#pragma unroll
        for (int rr = 0; rr < 2; rr++) {
            int l = r0 + rr * 8;
            float eA = seA[l];
            size_t tok = (size_t)(tokb + l);
            const float* zrow = gProjF + tok * PF_W + 1024 + h * 64;
            __half2* yaRow = (__half2*)(gYa + tok * DMOD + h * 64);
#pragma unroll
            for (int ni = 0; ni < 4; ni++) {
                int p = wn2 + ni * 8 + ((lane & 3) << 1);
                float y0 = yH[ni][rr * 2 + 0] + eA * oH[ni][rr * 2 + 0];
                float y1 = yH[ni][rr * 2 + 1] + eA * oH[ni][rr * 2 + 1];
                float2 z = *(const float2*)&zrow[p];
                y0 *= z.x / (1.f + __expf(-z.x));
                y1 *= z.y / (1.f + __expf(-z.y));
                yaRow[p >> 1] = __half2(__float2half(y0), __float2half(y1));
            }
        }
    }
}

// ---------------------------------------------------------------------------
extern "C" void kernel_launch(void* const* d_in, const int* in_sizes, int n_in,
                              void* d_out, int out_size) {
    const float* x     = (const float*)d_in[0];
    const float* W_in  = (const float*)d_in[1];
    const float* W_dt  = (const float*)d_in[2];
    const float* b_dt  = (const float*)d_in[3];
    const float* W_B   = (const float*)d_in[4];
    const float* W_C   = (const float*)d_in[5];
    const float* W_out = (const float*)d_in[6];
    const float* A_log = (const float*)d_in[7];
    float* out = (float*)d_out;

    void *pXh, *pWc, *pWo, *pYa;
    cudaGetSymbolAddress(&pXh, gXh);
    cudaGetSymbolAddress(&pWc, gWcat);
    cudaGetSymbolAddress(&pWo, gWo);
    cudaGetSymbolAddress(&pYa, gYa);

    cudaFuncSetAttribute(gemm_mma, cudaFuncAttributeMaxDynamicSharedMemorySize, GEMM_SMEM);
    cudaFuncSetAttribute(ssd_pass1, cudaFuncAttributeMaxDynamicSharedMemorySize, P1_SMEM);
    cudaFuncSetAttribute(ssd_pass2, cudaFuncAttributeMaxDynamicSharedMemorySize, P2_SMEM);

    // #0: conversions
    cvt_all<<<S_TOT / 256, 256>>>(x, W_in, W_B, W_C, W_dt, W_out);

    // #1: combined projection GEMM (split-dtype epilogue)
    gemm_mma<<<dim3(PROJN / 128, NTOK / 128), 256, GEMM_SMEM>>>(
        (const __half*)pXh, (const __half*)pWc, nullptr, NTOK, PROJN, DMOD, 1);

    // #2-#4
    ssd_pass1<<<NTILE, 256, P1_SMEM>>>(A_log, b_dt);
    scan_kernel<<<512, 256>>>(out);
    ssd_pass2<<<NTILE, 256, P2_SMEM>>>(b_dt);

    // #5: output GEMM
    gemm_mma<<<dim3(DMOD / 128, NTOK / 128), 256, GEMM_SMEM>>>(
        (const __half*)pYa, (const __half*)pWo, out, NTOK, DMOD, DMOD, 0);
}